// round 1
// baseline (speedup 1.0000x reference)
#include <cuda_runtime.h>
#include <math.h>

#define NB 16
#define NT 512
#define ND 1024
#define NH 16
#define NDK 64

#define OUT_ELEMS  ((size_t)NB*NT*ND)            // 8,388,608
#define ATTN_ELEMS ((size_t)NB*NH*NT*NT)          // 67,108,864

// Scratch (device globals: allocation-free per harness rules)
__device__ float g_q[NB*NH*NT*NDK];
__device__ float g_k[NB*NH*NT*NDK];
__device__ float g_v[NB*NH*NT*NDK];
__device__ float g_ctx[NB*NT*ND];
__device__ float g_attn_fallback[NB*NH*NT*NT];    // used only if d_out lacks attn region

// ---------------------------------------------------------------------------
// GEMM 1: QKV projection. C[m,n] = sum_k x[m,k]*Wqkv[k,n] + bqkv[n]
// Scatter into g_q / g_k / g_v with [B,H,T,DK] layout.
// Tiles: BM=64, BN=64, BK=16; 256 threads; 4x4 microtile.
// ---------------------------------------------------------------------------
__global__ __launch_bounds__(256) void qkv_gemm_kernel(
    const float* __restrict__ A, const float* __restrict__ Bw,
    const float* __restrict__ bias)
{
    __shared__ float As[16][68];   // [k][m], stride 68 keeps float4 alignment
    __shared__ float Bs[16][64];   // [k][n]
    const int tid = threadIdx.x;
    const int tx = tid & 15, ty = tid >> 4;
    const int m0 = blockIdx.y * 64, n0 = blockIdx.x * 64;
    float acc[4][4] = {};

    for (int k0 = 0; k0 < ND; k0 += 16) {
        {
            int r = tid >> 4, c = tid & 15;
            #pragma unroll
            for (int i = 0; i < 4; i++)
                As[c][r + 16*i] = A[(size_t)(m0 + r + 16*i)*ND + k0 + c];
        }
        #pragma unroll
        for (int i = 0; i < 4; i++) {
            int idx = tid + 256*i;
            int r = idx >> 6, c = idx & 63;
            Bs[r][c] = Bw[(size_t)(k0 + r)*3072 + n0 + c];
        }
        __syncthreads();
        #pragma unroll
        for (int kk = 0; kk < 16; kk++) {
            float4 a4 = *(const float4*)&As[kk][ty*4];
            float4 b4 = *(const float4*)&Bs[kk][tx*4];
            float av[4] = {a4.x, a4.y, a4.z, a4.w};
            float bv[4] = {b4.x, b4.y, b4.z, b4.w};
            #pragma unroll
            for (int i = 0; i < 4; i++)
                #pragma unroll
                for (int j = 0; j < 4; j++)
                    acc[i][j] += av[i] * bv[j];
        }
        __syncthreads();
    }

    // Epilogue: n0 is 64-aligned => whole tile maps to one (part, head)
    const int chunk = n0 >> 6;        // 0..47
    const int part  = chunk >> 4;     // 0=q, 1=k, 2=v
    const int h     = chunk & 15;
    float* gp = (part == 0) ? g_q : (part == 1) ? g_k : g_v;
    #pragma unroll
    for (int i = 0; i < 4; i++) {
        int m = m0 + ty*4 + i;
        int b = m >> 9, t = m & 511;
        float* dst = gp + ((size_t)(b*NH + h)*NT + t)*NDK;
        #pragma unroll
        for (int j = 0; j < 4; j++) {
            int dk = tx*4 + j;
            dst[dk] = acc[i][j] + bias[n0 + dk];
        }
    }
}

// ---------------------------------------------------------------------------
// Pass A: scores + bias + mask + softmax; write full attn rows (zeros outside
// the per-row window). One block per (bh, 16-query tile).
// ---------------------------------------------------------------------------
__global__ __launch_bounds__(256) void attn_scores_kernel(
    const float* __restrict__ rel_table, float* __restrict__ attn)
{
    __shared__ float Qs[64][17];    // [d][q]
    __shared__ float Ks[64][68];    // [d][j]
    __shared__ float S[16][276];    // [q][j - ws], nk <= 272
    const int tid = threadIdx.x;
    const int tx = tid & 15, ty = tid >> 4;   // ty = q row, tx = j group of 4
    const int bh = blockIdx.y;
    const int h  = bh & 15;
    const int q0 = blockIdx.x * 16;
    const int ws = max(0, q0 - 128);
    const int we = min(NT, q0 + 16 + 128);

    const float* qptr = g_q + ((size_t)bh*NT + q0)*NDK;
    #pragma unroll
    for (int i = 0; i < 4; i++) {
        int idx = tid + 256*i;
        int r = idx >> 6, c = idx & 63;
        Qs[c][r] = qptr[(size_t)r*NDK + c];
    }
    const float* kbase = g_k + (size_t)bh*NT*NDK;

    for (int c0 = ws; c0 < we; c0 += 64) {
        __syncthreads();
        #pragma unroll
        for (int i = 0; i < 16; i++) {
            int idx = tid + 256*i;
            int r = idx >> 6, c = idx & 63;   // r = local j, c = d
            int jg = c0 + r;
            Ks[c][r] = (jg < we) ? kbase[(size_t)jg*NDK + c] : 0.f;
        }
        __syncthreads();
        float a0 = 0.f, a1 = 0.f, a2 = 0.f, a3 = 0.f;
        #pragma unroll
        for (int d = 0; d < 64; d++) {
            float qv = Qs[d][ty];
            float4 kv = *(const float4*)&Ks[d][tx*4];
            a0 += qv*kv.x; a1 += qv*kv.y; a2 += qv*kv.z; a3 += qv*kv.w;
        }
        const int qi = q0 + ty;
        float sc[4] = {a0, a1, a2, a3};
        #pragma unroll
        for (int j = 0; j < 4; j++) {
            int jg = c0 + tx*4 + j;
            if (jg < we)
                S[ty][jg - ws] = sc[j]*0.125f
                               + rel_table[(size_t)(jg - qi + 511)*NH + h];
        }
    }
    __syncthreads();

    // Softmax per row: 8 warps x 2 rows
    const int warp = tid >> 5, lane = tid & 31;
    #pragma unroll
    for (int rr = 0; rr < 2; rr++) {
        int r  = warp*2 + rr;
        int qi = q0 + r;
        int jlo = max(0, qi - 128), jhi = min(NT - 1, qi + 128);
        int lo = jlo - ws, hi = jhi - ws;
        float mx = -1e30f;
        for (int idx = lo + lane; idx <= hi; idx += 32)
            mx = fmaxf(mx, S[r][idx]);
        #pragma unroll
        for (int o = 16; o > 0; o >>= 1)
            mx = fmaxf(mx, __shfl_xor_sync(0xffffffffu, mx, o));
        float sum = 0.f;
        for (int idx = lo + lane; idx <= hi; idx += 32) {
            float e = expf(S[r][idx] - mx);
            S[r][idx] = e;
            sum += e;
        }
        #pragma unroll
        for (int o = 16; o > 0; o >>= 1)
            sum += __shfl_xor_sync(0xffffffffu, sum, o);
        float inv = 1.f / sum;
        float* arow = attn + ((size_t)bh*NT + qi)*NT;
        for (int j = lane; j < NT; j += 32) {
            float v = (j >= jlo && j <= jhi) ? S[r][j - ws]*inv : 0.f;
            arow[j] = v;
        }
    }
}

// ---------------------------------------------------------------------------
// Pass B: ctx = attn @ V over the live window; write into [B,T,D] layout.
// ---------------------------------------------------------------------------
__global__ __launch_bounds__(256) void attn_ctx_kernel(const float* __restrict__ attn)
{
    __shared__ float Ps[64][17];   // [j][q]
    __shared__ float Vs[64][68];   // [j][d]
    const int tid = threadIdx.x;
    const int tx = tid & 15, ty = tid >> 4;
    const int bh = blockIdx.y;
    const int b = bh >> 4, h = bh & 15;
    const int q0 = blockIdx.x * 16;
    const int ws = max(0, q0 - 128);
    const int we = min(NT, q0 + 16 + 128);
    const float* vbase = g_v + (size_t)bh*NT*NDK;
    const float* abase = attn + ((size_t)bh*NT + q0)*NT;

    float cx = 0.f, cy = 0.f, cz = 0.f, cw = 0.f;
    for (int c0 = ws; c0 < we; c0 += 64) {
        __syncthreads();
        #pragma unroll
        for (int i = 0; i < 4; i++) {
            int idx = tid + 256*i;
            int r = idx >> 6, c = idx & 63;   // r = q, c = local j
            int jg = c0 + c;
            Ps[c][r] = (jg < we) ? abase[(size_t)r*NT + jg] : 0.f;
        }
        #pragma unroll
        for (int i = 0; i < 16; i++) {
            int idx = tid + 256*i;
            int r = idx >> 6, c = idx & 63;   // r = local j, c = d
            int jg = c0 + r;
            Vs[r][c] = (jg < we) ? vbase[(size_t)jg*NDK + c] : 0.f;
        }
        __syncthreads();
        #pragma unroll
        for (int j = 0; j < 64; j++) {
            float p = Ps[j][ty];
            float4 v = *(const float4*)&Vs[j][tx*4];
            cx += p*v.x; cy += p*v.y; cz += p*v.z; cw += p*v.w;
        }
    }
    int qi = q0 + ty;
    float* dst = g_ctx + ((size_t)(b*NT + qi))*ND + h*NDK + tx*4;
    dst[0] = cx; dst[1] = cy; dst[2] = cz; dst[3] = cw;
}

// ---------------------------------------------------------------------------
// GEMM 2: out = g_ctx @ Wo + bo
// ---------------------------------------------------------------------------
__global__ __launch_bounds__(256) void out_gemm_kernel(
    const float* __restrict__ Bw, const float* __restrict__ bias,
    float* __restrict__ C)
{
    __shared__ float As[16][68];
    __shared__ float Bs[16][64];
    const int tid = threadIdx.x;
    const int tx = tid & 15, ty = tid >> 4;
    const int m0 = blockIdx.y * 64, n0 = blockIdx.x * 64;
    float acc[4][4] = {};

    for (int k0 = 0; k0 < ND; k0 += 16) {
        {
            int r = tid >> 4, c = tid & 15;
            #pragma unroll
            for (int i = 0; i < 4; i++)
                As[c][r + 16*i] = g_ctx[(size_t)(m0 + r + 16*i)*ND + k0 + c];
        }
        #pragma unroll
        for (int i = 0; i < 4; i++) {
            int idx = tid + 256*i;
            int r = idx >> 6, c = idx & 63;
            Bs[r][c] = Bw[(size_t)(k0 + r)*ND + n0 + c];
        }
        __syncthreads();
        #pragma unroll
        for (int kk = 0; kk < 16; kk++) {
            float4 a4 = *(const float4*)&As[kk][ty*4];
            float4 b4 = *(const float4*)&Bs[kk][tx*4];
            float av[4] = {a4.x, a4.y, a4.z, a4.w};
            float bv[4] = {b4.x, b4.y, b4.z, b4.w};
            #pragma unroll
            for (int i = 0; i < 4; i++)
                #pragma unroll
                for (int j = 0; j < 4; j++)
                    acc[i][j] += av[i] * bv[j];
        }
        __syncthreads();
    }
    #pragma unroll
    for (int i = 0; i < 4; i++) {
        int m = m0 + ty*4 + i;
        float* dst = C + (size_t)m*ND + n0;
        #pragma unroll
        for (int j = 0; j < 4; j++) {
            int n = tx*4 + j;
            dst[n] = acc[i][j] + bias[n0 + n];
        }
    }
}

// ---------------------------------------------------------------------------
extern "C" void kernel_launch(void* const* d_in, const int* in_sizes, int n_in,
                              void* d_out, int out_size)
{
    const float* x     = (const float*)d_in[0];
    const float* Wqkv  = (const float*)d_in[1];
    const float* bqkv  = (const float*)d_in[2];
    const float* Wo    = (const float*)d_in[3];
    const float* bo    = (const float*)d_in[4];
    const float* rel   = (const float*)d_in[5];

    float* out = (float*)d_out;
    // Reference returns (out, attn); assume concatenated in order.
    float* attn;
    if ((size_t)out_size >= OUT_ELEMS + ATTN_ELEMS) {
        attn = out + OUT_ELEMS;
    } else {
        // attn not part of checked output — use scratch
        cudaGetSymbolAddress((void**)&attn, g_attn_fallback);
    }

    qkv_gemm_kernel<<<dim3(48, 128), 256>>>(x, Wqkv, bqkv);
    attn_scores_kernel<<<dim3(32, 256), 256>>>(rel, attn);
    attn_ctx_kernel<<<dim3(32, 256), 256>>>(attn);
    out_gemm_kernel<<<dim3(16, 128), 256>>>(Wo, bo, out);
}

// round 3
// speedup vs baseline: 1.1772x; 1.1772x over previous
#include <cuda_runtime.h>
#include <math.h>

#define NB 16
#define NT 512
#define ND 1024
#define NH 16
#define NDK 64

#define OUT_ELEMS  ((size_t)NB*NT*ND)             // 8,388,608
#define ATTN_ELEMS ((size_t)NB*NH*NT*NT)          // 67,108,864

// Scratch (device globals: allocation-free per harness rules)
__device__ float g_q[NB*NH*NT*NDK];
__device__ float g_k[NB*NH*NT*NDK];
__device__ float g_v[NB*NH*NT*NDK];
__device__ float g_ctx[NB*NT*ND];
__device__ float g_attn_fallback[NB*NH*NT*NT];

// ---------------------------------------------------------------------------
// Packed f32x2 helpers (Blackwell: FFMA2 only reachable via PTX fma.rn.f32x2)
// ---------------------------------------------------------------------------
__device__ __forceinline__ void ffma2(unsigned long long& d,
                                      unsigned long long a,
                                      unsigned long long b) {
    asm("fma.rn.f32x2 %0, %1, %2, %0;" : "+l"(d) : "l"(a), "l"(b));
}
__device__ __forceinline__ unsigned long long bcast2(float x) {
    unsigned long long r;
    asm("mov.b64 %0, {%1, %1};" : "=l"(r) : "f"(x));
    return r;
}
__device__ __forceinline__ void unpack2(unsigned long long v, float& lo, float& hi) {
    asm("mov.b64 {%0, %1}, %2;" : "=f"(lo), "=f"(hi) : "l"(v));
}

// ---------------------------------------------------------------------------
// GEMM 1: QKV projection, scatter into g_q/g_k/g_v as [B,H,T,DK]
// BM=128, BN=64, BK=16, 256 threads, 8(M)x4(N) microtile, M-paired FFMA2.
// ---------------------------------------------------------------------------
__global__ __launch_bounds__(256) void qkv_gemm_kernel(
    const float* __restrict__ A, const float* __restrict__ Bw,
    const float* __restrict__ bias)
{
    __shared__ __align__(16) float As[16][132];   // [k][m]
    __shared__ __align__(16) float Bs[16][64];    // [k][n]
    const int tid = threadIdx.x;
    const int tx = tid & 15, ty = tid >> 4;
    const int m0 = blockIdx.y * 128, n0 = blockIdx.x * 64;
    unsigned long long acc[4][4];
    #pragma unroll
    for (int i = 0; i < 4; i++)
        #pragma unroll
        for (int j = 0; j < 4; j++) acc[i][j] = 0ull;

    for (int k0 = 0; k0 < ND; k0 += 16) {
        {
            int r = tid >> 4, c = tid & 15;
            #pragma unroll
            for (int i = 0; i < 8; i++)
                As[c][r + 16*i] = A[(size_t)(m0 + r + 16*i)*ND + k0 + c];
        }
        #pragma unroll
        for (int i = 0; i < 4; i++) {
            int idx = tid + 256*i;
            int r = idx >> 6, c = idx & 63;
            Bs[r][c] = Bw[(size_t)(k0 + r)*3072 + n0 + c];
        }
        __syncthreads();
        #pragma unroll
        for (int kk = 0; kk < 16; kk++) {
            ulonglong2 a01 = *(const ulonglong2*)&As[kk][ty*8];
            ulonglong2 a23 = *(const ulonglong2*)&As[kk][ty*8 + 4];
            unsigned long long ap0 = a01.x, ap1 = a01.y, ap2 = a23.x, ap3 = a23.y;
            float4 b4 = *(const float4*)&Bs[kk][tx*4];
            unsigned long long bb0 = bcast2(b4.x), bb1 = bcast2(b4.y);
            unsigned long long bb2 = bcast2(b4.z), bb3 = bcast2(b4.w);
            ffma2(acc[0][0], ap0, bb0); ffma2(acc[0][1], ap0, bb1);
            ffma2(acc[0][2], ap0, bb2); ffma2(acc[0][3], ap0, bb3);
            ffma2(acc[1][0], ap1, bb0); ffma2(acc[1][1], ap1, bb1);
            ffma2(acc[1][2], ap1, bb2); ffma2(acc[1][3], ap1, bb3);
            ffma2(acc[2][0], ap2, bb0); ffma2(acc[2][1], ap2, bb1);
            ffma2(acc[2][2], ap2, bb2); ffma2(acc[2][3], ap2, bb3);
            ffma2(acc[3][0], ap3, bb0); ffma2(acc[3][1], ap3, bb1);
            ffma2(acc[3][2], ap3, bb2); ffma2(acc[3][3], ap3, bb3);
        }
        __syncthreads();
    }

    const int chunk = n0 >> 6;
    const int part  = chunk >> 4;     // 0=q, 1=k, 2=v
    const int h     = chunk & 15;
    float* gp = (part == 0) ? g_q : (part == 1) ? g_k : g_v;
    float4 bi = *(const float4*)&bias[n0 + tx*4];
    #pragma unroll
    for (int i2 = 0; i2 < 4; i2++) {
        float lo[4], hi[4];
        #pragma unroll
        for (int j = 0; j < 4; j++) unpack2(acc[i2][j], lo[j], hi[j]);
        int me = m0 + ty*8 + i2*2;
        {
            int b = me >> 9, t = me & 511;
            float4 o = make_float4(lo[0]+bi.x, lo[1]+bi.y, lo[2]+bi.z, lo[3]+bi.w);
            *(float4*)(gp + ((size_t)(b*NH + h)*NT + t)*NDK + tx*4) = o;
        }
        {
            int m = me + 1;
            int b = m >> 9, t = m & 511;
            float4 o = make_float4(hi[0]+bi.x, hi[1]+bi.y, hi[2]+bi.z, hi[3]+bi.w);
            *(float4*)(gp + ((size_t)(b*NH + h)*NT + t)*NDK + tx*4) = o;
        }
    }
}

// ---------------------------------------------------------------------------
// Fused attention: scores + bias + mask + softmax + attn write + ctx = P@V
// One block per (bh, 16-query tile).
// S padded to 320 columns: PV sweeps up to index 319 on the last 64-key block;
// entries beyond the key span are zero-initialized and never written.
// ---------------------------------------------------------------------------
#define SPAD 320

__global__ __launch_bounds__(256) void attn_fused_kernel(
    const float* __restrict__ rel_table, float* __restrict__ attn)
{
    __shared__ __align__(16) float Qs[64][17];    // [d][q]
    __shared__ __align__(16) float Ks[64][68];    // scores: [d][j]; PV: Vs[j][d]
    __shared__ __align__(16) float S[16][SPAD];   // [q][j - ws]
    const int tid = threadIdx.x;
    const int tx = tid & 15, ty = tid >> 4;
    const int bh = blockIdx.y;
    const int b  = bh >> 4, h = bh & 15;
    const int q0 = blockIdx.x * 16;
    const int ws = max(0, q0 - 128);
    const int we = min(NT, q0 + 16 + 128);

    // zero S (full padded width) so PV can blindly sweep 64-wide blocks
    for (int i = tid; i < 16*SPAD; i += 256)
        ((float*)S)[i] = 0.f;

    const float* qptr = g_q + ((size_t)bh*NT + q0)*NDK;
    #pragma unroll
    for (int i = 0; i < 4; i++) {
        int idx = tid + 256*i;
        int r = idx >> 6, c = idx & 63;
        Qs[c][r] = qptr[(size_t)r*NDK + c];
    }
    const float* kbase = g_k + (size_t)bh*NT*NDK;

    // ---- scores ----
    for (int c0 = ws; c0 < we; c0 += 64) {
        __syncthreads();
        #pragma unroll
        for (int i = 0; i < 16; i++) {
            int idx = tid + 256*i;
            int r = idx >> 6, c = idx & 63;   // r = local j, c = d
            int jg = c0 + r;
            Ks[c][r] = (jg < we) ? kbase[(size_t)jg*NDK + c] : 0.f;
        }
        __syncthreads();
        unsigned long long s01 = 0ull, s23 = 0ull;
        #pragma unroll
        for (int d = 0; d < 64; d++) {
            unsigned long long qb = bcast2(Qs[d][ty]);
            ulonglong2 kv = *(const ulonglong2*)&Ks[d][tx*4];
            ffma2(s01, qb, kv.x);
            ffma2(s23, qb, kv.y);
        }
        float sc[4];
        unpack2(s01, sc[0], sc[1]);
        unpack2(s23, sc[2], sc[3]);
        const int qi = q0 + ty;
        #pragma unroll
        for (int j = 0; j < 4; j++) {
            int jg = c0 + tx*4 + j;
            if (jg < we)
                S[ty][jg - ws] = sc[j]*0.125f
                               + rel_table[(size_t)(jg - qi + 511)*NH + h];
        }
    }
    __syncthreads();

    // ---- softmax (8 warps x 2 rows) + attn write ----
    const int warp = tid >> 5, lane = tid & 31;
    #pragma unroll
    for (int rr = 0; rr < 2; rr++) {
        int r  = warp*2 + rr;
        int qi = q0 + r;
        int jlo = max(0, qi - 128), jhi = min(NT - 1, qi + 128);
        int lo = jlo - ws, hi = jhi - ws;
        float mx = -1e30f;
        for (int idx = lo + lane; idx <= hi; idx += 32)
            mx = fmaxf(mx, S[r][idx]);
        #pragma unroll
        for (int o = 16; o > 0; o >>= 1)
            mx = fmaxf(mx, __shfl_xor_sync(0xffffffffu, mx, o));
        float sum = 0.f;
        for (int idx = lo + lane; idx <= hi; idx += 32) {
            float e = __expf(S[r][idx] - mx);
            S[r][idx] = e;
            sum += e;
        }
        #pragma unroll
        for (int o = 16; o > 0; o >>= 1)
            sum += __shfl_xor_sync(0xffffffffu, sum, o);
        float inv = 1.f / sum;
        // normalize in place, zero entries outside this row's window
        int span = we - ws;
        for (int idx = lane; idx < span; idx += 32) {
            float v = (idx >= lo && idx <= hi) ? S[r][idx]*inv : 0.f;
            S[r][idx] = v;
        }
        __syncwarp();
        // full attn row, float4 stores (S already zero outside row window)
        float* arow = attn + ((size_t)bh*NT + qi)*NT;
        for (int j4 = lane; j4 < 128; j4 += 32) {
            int j = j4*4;
            float4 o;
            o.x = (j+0 >= ws && j+0 < we) ? S[r][j+0 - ws] : 0.f;
            o.y = (j+1 >= ws && j+1 < we) ? S[r][j+1 - ws] : 0.f;
            o.z = (j+2 >= ws && j+2 < we) ? S[r][j+2 - ws] : 0.f;
            o.w = (j+3 >= ws && j+3 < we) ? S[r][j+3 - ws] : 0.f;
            ((float4*)arow)[j4] = o;
        }
    }

    // ---- ctx = P @ V (reuse Ks buffer as Vs[j][d]) ----
    const float* vbase = g_v + (size_t)bh*NT*NDK;
    unsigned long long c01 = 0ull, c23 = 0ull;
    for (int c0 = ws; c0 < we; c0 += 64) {
        __syncthreads();
        #pragma unroll
        for (int i = 0; i < 16; i++) {
            int idx = tid + 256*i;
            int r = idx >> 6, c = idx & 63;   // r = local j, c = d
            int jg = c0 + r;
            Ks[r][c] = (jg < we) ? vbase[(size_t)jg*NDK + c] : 0.f;
        }
        __syncthreads();
        const int base = c0 - ws;
        #pragma unroll
        for (int j = 0; j < 64; j++) {
            unsigned long long pb = bcast2(S[ty][base + j]);
            ulonglong2 v2 = *(const ulonglong2*)&Ks[j][tx*4];
            ffma2(c01, pb, v2.x);
            ffma2(c23, pb, v2.y);
        }
    }
    float c[4];
    unpack2(c01, c[0], c[1]);
    unpack2(c23, c[2], c[3]);
    int qi = q0 + ty;
    *(float4*)(g_ctx + ((size_t)(b*NT + qi))*ND + h*NDK + tx*4) =
        make_float4(c[0], c[1], c[2], c[3]);
}

// ---------------------------------------------------------------------------
// GEMM 2: out = g_ctx @ Wo + bo  (same packed core)
// ---------------------------------------------------------------------------
__global__ __launch_bounds__(256) void out_gemm_kernel(
    const float* __restrict__ Bw, const float* __restrict__ bias,
    float* __restrict__ C)
{
    __shared__ __align__(16) float As[16][132];
    __shared__ __align__(16) float Bs[16][64];
    const int tid = threadIdx.x;
    const int tx = tid & 15, ty = tid >> 4;
    const int m0 = blockIdx.y * 128, n0 = blockIdx.x * 64;
    unsigned long long acc[4][4];
    #pragma unroll
    for (int i = 0; i < 4; i++)
        #pragma unroll
        for (int j = 0; j < 4; j++) acc[i][j] = 0ull;

    for (int k0 = 0; k0 < ND; k0 += 16) {
        {
            int r = tid >> 4, c = tid & 15;
            #pragma unroll
            for (int i = 0; i < 8; i++)
                As[c][r + 16*i] = g_ctx[(size_t)(m0 + r + 16*i)*ND + k0 + c];
        }
        #pragma unroll
        for (int i = 0; i < 4; i++) {
            int idx = tid + 256*i;
            int r = idx >> 6, c = idx & 63;
            Bs[r][c] = Bw[(size_t)(k0 + r)*ND + n0 + c];
        }
        __syncthreads();
        #pragma unroll
        for (int kk = 0; kk < 16; kk++) {
            ulonglong2 a01 = *(const ulonglong2*)&As[kk][ty*8];
            ulonglong2 a23 = *(const ulonglong2*)&As[kk][ty*8 + 4];
            unsigned long long ap0 = a01.x, ap1 = a01.y, ap2 = a23.x, ap3 = a23.y;
            float4 b4 = *(const float4*)&Bs[kk][tx*4];
            unsigned long long bb0 = bcast2(b4.x), bb1 = bcast2(b4.y);
            unsigned long long bb2 = bcast2(b4.z), bb3 = bcast2(b4.w);
            ffma2(acc[0][0], ap0, bb0); ffma2(acc[0][1], ap0, bb1);
            ffma2(acc[0][2], ap0, bb2); ffma2(acc[0][3], ap0, bb3);
            ffma2(acc[1][0], ap1, bb0); ffma2(acc[1][1], ap1, bb1);
            ffma2(acc[1][2], ap1, bb2); ffma2(acc[1][3], ap1, bb3);
            ffma2(acc[2][0], ap2, bb0); ffma2(acc[2][1], ap2, bb1);
            ffma2(acc[2][2], ap2, bb2); ffma2(acc[2][3], ap2, bb3);
            ffma2(acc[3][0], ap3, bb0); ffma2(acc[3][1], ap3, bb1);
            ffma2(acc[3][2], ap3, bb2); ffma2(acc[3][3], ap3, bb3);
        }
        __syncthreads();
    }

    float4 bi = *(const float4*)&bias[n0 + tx*4];
    #pragma unroll
    for (int i2 = 0; i2 < 4; i2++) {
        float lo[4], hi[4];
        #pragma unroll
        for (int j = 0; j < 4; j++) unpack2(acc[i2][j], lo[j], hi[j]);
        int me = m0 + ty*8 + i2*2;
        *(float4*)(C + (size_t)me*ND + n0 + tx*4) =
            make_float4(lo[0]+bi.x, lo[1]+bi.y, lo[2]+bi.z, lo[3]+bi.w);
        *(float4*)(C + (size_t)(me+1)*ND + n0 + tx*4) =
            make_float4(hi[0]+bi.x, hi[1]+bi.y, hi[2]+bi.z, hi[3]+bi.w);
    }
}

// ---------------------------------------------------------------------------
extern "C" void kernel_launch(void* const* d_in, const int* in_sizes, int n_in,
                              void* d_out, int out_size)
{
    const float* x     = (const float*)d_in[0];
    const float* Wqkv  = (const float*)d_in[1];
    const float* bqkv  = (const float*)d_in[2];
    const float* Wo    = (const float*)d_in[3];
    const float* bo    = (const float*)d_in[4];
    const float* rel   = (const float*)d_in[5];

    float* out = (float*)d_out;
    float* attn;
    if ((size_t)out_size >= OUT_ELEMS + ATTN_ELEMS) {
        attn = out + OUT_ELEMS;
    } else {
        cudaGetSymbolAddress((void**)&attn, g_attn_fallback);
    }

    qkv_gemm_kernel<<<dim3(48, 64), 256>>>(x, Wqkv, bqkv);
    attn_fused_kernel<<<dim3(32, 256), 256>>>(rel, attn);
    out_gemm_kernel<<<dim3(16, 64), 256>>>(Wo, bo, out);
}

// round 5
// speedup vs baseline: 1.6988x; 1.4431x over previous
#include <cuda_runtime.h>
#include <cuda_bf16.h>
#include <math.h>
#include <stdint.h>

#define NB 16
#define NT 512
#define ND 1024
#define NH 16
#define NDK 64
#define KP 3072   // expanded K (3x split terms)

#define OUT_ELEMS  ((size_t)NB*NT*ND)             // 8,388,608
#define ATTN_ELEMS ((size_t)NB*NH*NT*NT)          // 67,108,864

// ---------------------------------------------------------------------------
// Scratch (device globals: allocation-free per harness rules)
// ---------------------------------------------------------------------------
__device__ float g_q[NB*NH*NT*NDK];
__device__ float g_k[NB*NH*NT*NDK];
__device__ float g_v[NB*NH*NT*NDK];
__device__ float g_ctx[NB*NT*ND];
__device__ float g_attn_fallback[NB*NH*NT*NT];

__device__ __align__(16) __nv_bfloat16 g_ap[8192ull*KP];   // x  split/interleaved
__device__ __align__(16) __nv_bfloat16 g_bq[3072ull*KP];   // Wqkv^T split/interleaved
__device__ __align__(16) __nv_bfloat16 g_bo2[1024ull*KP];  // Wo^T split/interleaved
__device__ __align__(16) __nv_bfloat16 g_cp[8192ull*KP];   // ctx split/interleaved

// ---------------------------------------------------------------------------
// helpers
// ---------------------------------------------------------------------------
__device__ __forceinline__ uint32_t smem_u32(const void* p) {
    uint32_t a;
    asm("{ .reg .u64 t; cvta.to.shared.u64 t, %1; cvt.u32.u64 %0, t; }"
        : "=r"(a) : "l"(p));
    return a;
}
__device__ __forceinline__ void ldsm_x4(uint32_t& r0, uint32_t& r1,
                                        uint32_t& r2, uint32_t& r3, uint32_t addr) {
    asm volatile("ldmatrix.sync.aligned.m8n8.x4.shared.b16 {%0,%1,%2,%3}, [%4];"
                 : "=r"(r0), "=r"(r1), "=r"(r2), "=r"(r3) : "r"(addr));
}
__device__ __forceinline__ void mma16816(float* d, const uint32_t* a, const uint32_t* b) {
    asm volatile("mma.sync.aligned.m16n8k16.row.col.f32.bf16.bf16.f32 "
                 "{%0,%1,%2,%3}, {%4,%5,%6,%7}, {%8,%9}, {%0,%1,%2,%3};"
                 : "+f"(d[0]), "+f"(d[1]), "+f"(d[2]), "+f"(d[3])
                 : "r"(a[0]), "r"(a[1]), "r"(a[2]), "r"(a[3]),
                   "r"(b[0]), "r"(b[1]));
}
__device__ __forceinline__ void split_bf16(float x, unsigned short& h, unsigned short& l) {
    __nv_bfloat16 hb = __float2bfloat16_rn(x);
    float hr = __bfloat162float(hb);
    __nv_bfloat16 lb = __float2bfloat16_rn(x - hr);
    h = *(unsigned short*)&hb;
    l = *(unsigned short*)&lb;
}
// f32x2 helpers for attention
__device__ __forceinline__ void ffma2(unsigned long long& d,
                                      unsigned long long a,
                                      unsigned long long b) {
    asm("fma.rn.f32x2 %0, %1, %2, %0;" : "+l"(d) : "l"(a), "l"(b));
}
__device__ __forceinline__ unsigned long long bcast2(float x) {
    unsigned long long r;
    asm("mov.b64 %0, {%1, %1};" : "=l"(r) : "f"(x));
    return r;
}
__device__ __forceinline__ void unpack2(unsigned long long v, float& lo, float& hi) {
    asm("mov.b64 {%0, %1}, %2;" : "=f"(lo), "=f"(hi) : "l"(v));
}

// ---------------------------------------------------------------------------
// Prep: A-side interleave  A'[m][3k+{0,1,2}] = {hi,hi,lo}
// grid 8192 x 256 threads, 4 k per thread.
// ---------------------------------------------------------------------------
__global__ __launch_bounds__(256) void interleave_a_kernel(
    const float* __restrict__ src, __nv_bfloat16* __restrict__ dst)
{
    int gid = blockIdx.x * 256 + threadIdx.x;
    int m  = gid >> 8;
    int k4 = (gid & 255) * 4;
    float4 v = *(const float4*)(src + (size_t)m*1024 + k4);
    unsigned short h[4], l[4];
    split_bf16(v.x, h[0], l[0]);
    split_bf16(v.y, h[1], l[1]);
    split_bf16(v.z, h[2], l[2]);
    split_bf16(v.w, h[3], l[3]);
    ushort4* d4 = (ushort4*)(dst + (size_t)m*KP + (size_t)k4*3);
    d4[0] = make_ushort4(h[0], h[0], l[0], h[1]);
    d4[1] = make_ushort4(h[1], l[1], h[2], h[2]);
    d4[2] = make_ushort4(l[2], h[3], h[3], l[3]);
}

// ---------------------------------------------------------------------------
// Prep: B-side transpose + interleave.  W[k][n] -> B'[n][3k+{0,1,2}] = {hi,lo,hi}
// block 256, 32x32 tile.
// ---------------------------------------------------------------------------
__global__ __launch_bounds__(256) void transpose_w_kernel(
    const float* __restrict__ W, int Ncols, __nv_bfloat16* __restrict__ dst)
{
    __shared__ float s[32][33];
    const int tid = threadIdx.x;
    const int tx = tid & 31, ty = tid >> 5;   // load: tx = n local, ty(+8i) = k local
    const int n0 = blockIdx.x * 32, k0 = blockIdx.y * 32;
    #pragma unroll
    for (int i = 0; i < 4; i++)
        s[tx][ty + 8*i] = W[(size_t)(k0 + ty + 8*i)*Ncols + n0 + tx];
    __syncthreads();
    const int nn = tid >> 3;          // 0..31
    const int kq = (tid & 7) * 4;     // 0..28
    unsigned short h[4], l[4];
    #pragma unroll
    for (int t = 0; t < 4; t++)
        split_bf16(s[nn][kq + t], h[t], l[t]);
    ushort4* d4 = (ushort4*)(dst + (size_t)(n0 + nn)*KP + (size_t)(k0 + kq)*3);
    d4[0] = make_ushort4(h[0], l[0], h[0], h[1]);
    d4[1] = make_ushort4(l[1], h[1], h[2], l[2]);
    d4[2] = make_ushort4(h[2], h[3], l[3], h[3]);
}

// ---------------------------------------------------------------------------
// bf16 mma.sync GEMM:  C[M][N] = A'[M][KP] * B'[N][KP]^T (+bias)
// Tile 128x128, BK=64 (48 K-tiles), 8 warps as 2(M)x4(N), warp tile 64x32.
// smem rows padded to 72 bf16 (144B) -> conflict-free ldmatrix.
// mode 0: scatter into g_q/g_k/g_v; mode 1: row-major C.
// ---------------------------------------------------------------------------
__global__ __launch_bounds__(256) void mma_gemm_kernel(
    const __nv_bfloat16* __restrict__ Ap, const __nv_bfloat16* __restrict__ Bp,
    const float* __restrict__ bias, float* __restrict__ C, int mode)
{
    __shared__ __align__(16) __nv_bfloat16 As[128*72];
    __shared__ __align__(16) __nv_bfloat16 Bs[128*72];
    const int tid = threadIdx.x;
    const int lane = tid & 31, wid = tid >> 5;
    const int wm = wid >> 2, wn = wid & 3;
    const int m0 = blockIdx.y * 128, n0 = blockIdx.x * 128;
    float acc[4][4][4];
    #pragma unroll
    for (int i = 0; i < 4; i++)
        #pragma unroll
        for (int j = 0; j < 4; j++)
            #pragma unroll
            for (int r = 0; r < 4; r++) acc[i][j][r] = 0.f;

    const uint32_t asb = smem_u32(As), bsb = smem_u32(Bs);
    // A ldmatrix lane address (mf=0, ks=0): rows 0-15 -> k0, 16-31 -> k0+8
    const uint32_t a_addr = asb + (uint32_t)((wm*64 + (lane & 15))*144 + ((lane >> 4) << 4));
    // B ldmatrix lane address (x4 covers nf pair): g = lane>>3
    const int g = lane >> 3, rl = lane & 7;
    const uint32_t b_addr = bsb + (uint32_t)((wn*32 + (g >> 1)*8 + rl)*144 + ((g & 1) << 4));

    for (int kt = 0; kt < 48; kt++) {
        const int kb = kt * 64;
        __syncthreads();
        #pragma unroll
        for (int i = 0; i < 4; i++) {
            int e = tid + 256*i;
            int r = e >> 3, c8 = (e & 7) * 8;
            *(uint4*)(As + r*72 + c8) = *(const uint4*)(Ap + (size_t)(m0 + r)*KP + kb + c8);
            *(uint4*)(Bs + r*72 + c8) = *(const uint4*)(Bp + (size_t)(n0 + r)*KP + kb + c8);
        }
        __syncthreads();
        #pragma unroll
        for (int ks = 0; ks < 4; ks++) {
            uint32_t af[4][4];
            #pragma unroll
            for (int mf = 0; mf < 4; mf++)
                ldsm_x4(af[mf][0], af[mf][1], af[mf][2], af[mf][3],
                        a_addr + mf*16*144 + ks*32);
            uint32_t bf[4][2];
            #pragma unroll
            for (int np = 0; np < 2; np++) {
                uint32_t r0, r1, r2, r3;
                ldsm_x4(r0, r1, r2, r3, b_addr + np*16*144 + ks*32);
                bf[np*2][0] = r0;   bf[np*2][1] = r1;
                bf[np*2+1][0] = r2; bf[np*2+1][1] = r3;
            }
            #pragma unroll
            for (int mf = 0; mf < 4; mf++)
                #pragma unroll
                for (int nf = 0; nf < 4; nf++)
                    mma16816(acc[mf][nf], af[mf], bf[nf]);
        }
    }

    // epilogue: thread holds (row, col..col+1) and (row+8, col..col+1)
    const int qr = lane >> 2, qc = (lane & 3) * 2;
    #pragma unroll
    for (int mf = 0; mf < 4; mf++) {
        #pragma unroll
        for (int nf = 0; nf < 4; nf++) {
            int row = m0 + wm*64 + mf*16 + qr;
            int col = n0 + wn*32 + nf*8 + qc;
            float2 bi = *(const float2*)(bias + col);
            float2 v0 = make_float2(acc[mf][nf][0] + bi.x, acc[mf][nf][1] + bi.y);
            float2 v1 = make_float2(acc[mf][nf][2] + bi.x, acc[mf][nf][3] + bi.y);
            if (mode == 0) {
                int chunk = col >> 6, part = chunk >> 4, h = chunk & 15, dk = col & 63;
                float* gp = (part == 0) ? g_q : (part == 1) ? g_k : g_v;
                int b0 = row >> 9, t0 = row & 511;
                *(float2*)(gp + ((size_t)(b0*NH + h)*NT + t0)*NDK + dk) = v0;
                int r1 = row + 8;
                int b1 = r1 >> 9, t1 = r1 & 511;
                *(float2*)(gp + ((size_t)(b1*NH + h)*NT + t1)*NDK + dk) = v1;
            } else {
                *(float2*)(C + (size_t)row*1024 + col) = v0;
                *(float2*)(C + (size_t)(row + 8)*1024 + col) = v1;
            }
        }
    }
}

// ---------------------------------------------------------------------------
// Fused attention (unchanged from R3-passing version; writes fp32 g_ctx)
// ---------------------------------------------------------------------------
#define SPAD 320

__global__ __launch_bounds__(256) void attn_fused_kernel(
    const float* __restrict__ rel_table, float* __restrict__ attn)
{
    __shared__ __align__(16) float Qs[64][17];
    __shared__ __align__(16) float Ks[64][68];
    __shared__ __align__(16) float S[16][SPAD];
    const int tid = threadIdx.x;
    const int tx = tid & 15, ty = tid >> 4;
    const int bh = blockIdx.y;
    const int b  = bh >> 4, h = bh & 15;
    const int q0 = blockIdx.x * 16;
    const int ws = max(0, q0 - 128);
    const int we = min(NT, q0 + 16 + 128);

    for (int i = tid; i < 16*SPAD; i += 256)
        ((float*)S)[i] = 0.f;

    const float* qptr = g_q + ((size_t)bh*NT + q0)*NDK;
    #pragma unroll
    for (int i = 0; i < 4; i++) {
        int idx = tid + 256*i;
        int r = idx >> 6, c = idx & 63;
        Qs[c][r] = qptr[(size_t)r*NDK + c];
    }
    const float* kbase = g_k + (size_t)bh*NT*NDK;

    for (int c0 = ws; c0 < we; c0 += 64) {
        __syncthreads();
        #pragma unroll
        for (int i = 0; i < 16; i++) {
            int idx = tid + 256*i;
            int r = idx >> 6, c = idx & 63;
            int jg = c0 + r;
            Ks[c][r] = (jg < we) ? kbase[(size_t)jg*NDK + c] : 0.f;
        }
        __syncthreads();
        unsigned long long s01 = 0ull, s23 = 0ull;
        #pragma unroll
        for (int d = 0; d < 64; d++) {
            unsigned long long qb = bcast2(Qs[d][ty]);
            ulonglong2 kv = *(const ulonglong2*)&Ks[d][tx*4];
            ffma2(s01, qb, kv.x);
            ffma2(s23, qb, kv.y);
        }
        float sc[4];
        unpack2(s01, sc[0], sc[1]);
        unpack2(s23, sc[2], sc[3]);
        const int qi = q0 + ty;
        #pragma unroll
        for (int j = 0; j < 4; j++) {
            int jg = c0 + tx*4 + j;
            if (jg < we)
                S[ty][jg - ws] = sc[j]*0.125f
                               + rel_table[(size_t)(jg - qi + 511)*NH + h];
        }
    }
    __syncthreads();

    const int warp = tid >> 5, lane = tid & 31;
    #pragma unroll
    for (int rr = 0; rr < 2; rr++) {
        int r  = warp*2 + rr;
        int qi = q0 + r;
        int jlo = max(0, qi - 128), jhi = min(NT - 1, qi + 128);
        int lo = jlo - ws, hi = jhi - ws;
        float mx = -1e30f;
        for (int idx = lo + lane; idx <= hi; idx += 32)
            mx = fmaxf(mx, S[r][idx]);
        #pragma unroll
        for (int o = 16; o > 0; o >>= 1)
            mx = fmaxf(mx, __shfl_xor_sync(0xffffffffu, mx, o));
        float sum = 0.f;
        for (int idx = lo + lane; idx <= hi; idx += 32) {
            float e = __expf(S[r][idx] - mx);
            S[r][idx] = e;
            sum += e;
        }
        #pragma unroll
        for (int o = 16; o > 0; o >>= 1)
            sum += __shfl_xor_sync(0xffffffffu, sum, o);
        float inv = 1.f / sum;
        int span = we - ws;
        for (int idx = lane; idx < span; idx += 32) {
            float v = (idx >= lo && idx <= hi) ? S[r][idx]*inv : 0.f;
            S[r][idx] = v;
        }
        __syncwarp();
        float* arow = attn + ((size_t)bh*NT + qi)*NT;
        for (int j4 = lane; j4 < 128; j4 += 32) {
            int j = j4*4;
            float4 o;
            o.x = (j+0 >= ws && j+0 < we) ? S[r][j+0 - ws] : 0.f;
            o.y = (j+1 >= ws && j+1 < we) ? S[r][j+1 - ws] : 0.f;
            o.z = (j+2 >= ws && j+2 < we) ? S[r][j+2 - ws] : 0.f;
            o.w = (j+3 >= ws && j+3 < we) ? S[r][j+3 - ws] : 0.f;
            ((float4*)arow)[j4] = o;
        }
    }

    // ctx = P @ V
    const float* vbase = g_v + (size_t)bh*NT*NDK;
    unsigned long long c01 = 0ull, c23 = 0ull;
    for (int c0 = ws; c0 < we; c0 += 64) {
        __syncthreads();
        #pragma unroll
        for (int i = 0; i < 16; i++) {
            int idx = tid + 256*i;
            int r = idx >> 6, c = idx & 63;
            int jg = c0 + r;
            Ks[r][c] = (jg < we) ? vbase[(size_t)jg*NDK + c] : 0.f;
        }
        __syncthreads();
        const int base = c0 - ws;
        #pragma unroll
        for (int j = 0; j < 64; j++) {
            unsigned long long pb = bcast2(S[ty][base + j]);
            ulonglong2 v2 = *(const ulonglong2*)&Ks[j][tx*4];
            ffma2(c01, pb, v2.x);
            ffma2(c23, pb, v2.y);
        }
    }
    float c[4];
    unpack2(c01, c[0], c[1]);
    unpack2(c23, c[2], c[3]);
    int qi = q0 + ty;
    *(float4*)(g_ctx + ((size_t)(b*NT + qi))*ND + h*NDK + tx*4) =
        make_float4(c[0], c[1], c[2], c[3]);
}

// ---------------------------------------------------------------------------
extern "C" void kernel_launch(void* const* d_in, const int* in_sizes, int n_in,
                              void* d_out, int out_size)
{
    const float* x     = (const float*)d_in[0];
    const float* Wqkv  = (const float*)d_in[1];
    const float* bqkv  = (const float*)d_in[2];
    const float* Wo    = (const float*)d_in[3];
    const float* bo    = (const float*)d_in[4];
    const float* rel   = (const float*)d_in[5];

    float* out = (float*)d_out;
    float* attn;
    if ((size_t)out_size >= OUT_ELEMS + ATTN_ELEMS) {
        attn = out + OUT_ELEMS;
    } else {
        cudaGetSymbolAddress((void**)&attn, g_attn_fallback);
    }

    __nv_bfloat16 *ap, *bq, *bo2, *cp;
    float* ctx;
    cudaGetSymbolAddress((void**)&ap,  g_ap);
    cudaGetSymbolAddress((void**)&bq,  g_bq);
    cudaGetSymbolAddress((void**)&bo2, g_bo2);
    cudaGetSymbolAddress((void**)&cp,  g_cp);
    cudaGetSymbolAddress((void**)&ctx, g_ctx);

    // prep
    interleave_a_kernel<<<8192, 256>>>(x, ap);
    transpose_w_kernel<<<dim3(96, 32), 256>>>(Wqkv, 3072, bq);
    transpose_w_kernel<<<dim3(32, 32), 256>>>(Wo, 1024, bo2);

    // QKV projection (tensor cores via mma.sync)
    mma_gemm_kernel<<<dim3(24, 64), 256>>>(ap, bq, bqkv, nullptr, 0);
    // fused attention
    attn_fused_kernel<<<dim3(32, 256), 256>>>(rel, attn);
    // ctx prep + out projection
    interleave_a_kernel<<<8192, 256>>>(ctx, cp);
    mma_gemm_kernel<<<dim3(8, 64), 256>>>(cp, bo2, bo, out, 1);
}

// round 7
// speedup vs baseline: 1.8037x; 1.0618x over previous
#include <cuda_runtime.h>
#include <cuda_bf16.h>
#include <math.h>
#include <stdint.h>

#define NB 16
#define NT 512
#define ND 1024
#define NH 16
#define NDK 64
#define KP 3072   // expanded K (3x split terms)

#define OUT_ELEMS  ((size_t)NB*NT*ND)             // 8,388,608
#define ATTN_ELEMS ((size_t)NB*NH*NT*NT)          // 67,108,864

// ---------------------------------------------------------------------------
// Scratch (device globals: allocation-free per harness rules)
// ---------------------------------------------------------------------------
__device__ float g_q[NB*NH*NT*NDK];
__device__ float g_k[NB*NH*NT*NDK];
__device__ float g_v[NB*NH*NT*NDK];
__device__ float g_attn_fallback[NB*NH*NT*NT];

__device__ __align__(16) __nv_bfloat16 g_ap[8192ull*KP];   // x  split/interleaved
__device__ __align__(16) __nv_bfloat16 g_bq[3072ull*KP];   // Wqkv^T split/interleaved
__device__ __align__(16) __nv_bfloat16 g_bo2[1024ull*KP];  // Wo^T split/interleaved
__device__ __align__(16) __nv_bfloat16 g_cp[8192ull*KP];   // ctx split/interleaved

// ---------------------------------------------------------------------------
// helpers
// ---------------------------------------------------------------------------
__device__ __forceinline__ uint32_t smem_u32(const void* p) {
    uint32_t a;
    asm("{ .reg .u64 t; cvta.to.shared.u64 t, %1; cvt.u32.u64 %0, t; }"
        : "=r"(a) : "l"(p));
    return a;
}
__device__ __forceinline__ void ldsm_x4(uint32_t& r0, uint32_t& r1,
                                        uint32_t& r2, uint32_t& r3, uint32_t addr) {
    asm volatile("ldmatrix.sync.aligned.m8n8.x4.shared.b16 {%0,%1,%2,%3}, [%4];"
                 : "=r"(r0), "=r"(r1), "=r"(r2), "=r"(r3) : "r"(addr));
}
__device__ __forceinline__ void mma16816(float* d, const uint32_t* a, const uint32_t* b) {
    asm volatile("mma.sync.aligned.m16n8k16.row.col.f32.bf16.bf16.f32 "
                 "{%0,%1,%2,%3}, {%4,%5,%6,%7}, {%8,%9}, {%0,%1,%2,%3};"
                 : "+f"(d[0]), "+f"(d[1]), "+f"(d[2]), "+f"(d[3])
                 : "r"(a[0]), "r"(a[1]), "r"(a[2]), "r"(a[3]),
                   "r"(b[0]), "r"(b[1]));
}
#define CP_ASYNC16(dst, src) \
    asm volatile("cp.async.cg.shared.global [%0], [%1], 16;" :: "r"(dst), "l"(src))
#define CP_COMMIT()  asm volatile("cp.async.commit_group;" ::: "memory")
#define CP_WAIT0()   asm volatile("cp.async.wait_group 0;" ::: "memory")
#define CP_WAIT1()   asm volatile("cp.async.wait_group 1;" ::: "memory")

__device__ __forceinline__ void split_bf16(float x, unsigned short& h, unsigned short& l) {
    __nv_bfloat16 hb = __float2bfloat16_rn(x);
    float hr = __bfloat162float(hb);
    __nv_bfloat16 lb = __float2bfloat16_rn(x - hr);
    h = *(unsigned short*)&hb;
    l = *(unsigned short*)&lb;
}
// f32x2 helpers for attention
__device__ __forceinline__ void ffma2(unsigned long long& d,
                                      unsigned long long a,
                                      unsigned long long b) {
    asm("fma.rn.f32x2 %0, %1, %2, %0;" : "+l"(d) : "l"(a), "l"(b));
}
__device__ __forceinline__ unsigned long long bcast2(float x) {
    unsigned long long r;
    asm("mov.b64 %0, {%1, %1};" : "=l"(r) : "f"(x));
    return r;
}
__device__ __forceinline__ void unpack2(unsigned long long v, float& lo, float& hi) {
    asm("mov.b64 {%0, %1}, %2;" : "=f"(lo), "=f"(hi) : "l"(v));
}

// ---------------------------------------------------------------------------
// Prep: A-side interleave  A'[m][3k+{0,1,2}] = {hi,hi,lo}
// ---------------------------------------------------------------------------
__global__ __launch_bounds__(256) void interleave_a_kernel(
    const float* __restrict__ src, __nv_bfloat16* __restrict__ dst)
{
    int gid = blockIdx.x * 256 + threadIdx.x;
    int m  = gid >> 8;
    int k4 = (gid & 255) * 4;
    float4 v = *(const float4*)(src + (size_t)m*1024 + k4);
    unsigned short h[4], l[4];
    split_bf16(v.x, h[0], l[0]);
    split_bf16(v.y, h[1], l[1]);
    split_bf16(v.z, h[2], l[2]);
    split_bf16(v.w, h[3], l[3]);
    ushort4* d4 = (ushort4*)(dst + (size_t)m*KP + (size_t)k4*3);
    d4[0] = make_ushort4(h[0], h[0], l[0], h[1]);
    d4[1] = make_ushort4(h[1], l[1], h[2], h[2]);
    d4[2] = make_ushort4(l[2], h[3], h[3], l[3]);
}

// ---------------------------------------------------------------------------
// Prep: B-side transpose + interleave.  W[k][n] -> B'[n][3k+{0,1,2}] = {hi,lo,hi}
// ---------------------------------------------------------------------------
__global__ __launch_bounds__(256) void transpose_w_kernel(
    const float* __restrict__ W, int Ncols, __nv_bfloat16* __restrict__ dst)
{
    __shared__ float s[32][33];
    const int tid = threadIdx.x;
    const int tx = tid & 31, ty = tid >> 5;
    const int n0 = blockIdx.x * 32, k0 = blockIdx.y * 32;
    #pragma unroll
    for (int i = 0; i < 4; i++)
        s[tx][ty + 8*i] = W[(size_t)(k0 + ty + 8*i)*Ncols + n0 + tx];
    __syncthreads();
    const int nn = tid >> 3;
    const int kq = (tid & 7) * 4;
    unsigned short h[4], l[4];
    #pragma unroll
    for (int t = 0; t < 4; t++)
        split_bf16(s[nn][kq + t], h[t], l[t]);
    ushort4* d4 = (ushort4*)(dst + (size_t)(n0 + nn)*KP + (size_t)(k0 + kq)*3);
    d4[0] = make_ushort4(h[0], l[0], h[0], h[1]);
    d4[1] = make_ushort4(l[1], h[1], h[2], l[2]);
    d4[2] = make_ushort4(h[2], h[3], l[3], h[3]);
}

// ---------------------------------------------------------------------------
// bf16 mma.sync GEMM, 2-stage cp.async pipeline.
// Tile 128x128, BK=64 (48 K-tiles), 8 warps as 2(M)x4(N), warp tile 64x32.
// smem rows padded to 72 bf16 (144B). Dynamic smem: 2 stages x (A+B) = 73728B.
// mode 0: scatter into g_q/g_k/g_v; mode 1: row-major C.
// ---------------------------------------------------------------------------
#define STAGE_BYTES 36864           // A(18432) + B(18432) per stage
#define GEMM_SMEM   73728

__global__ __launch_bounds__(256) void mma_gemm_kernel(
    const __nv_bfloat16* __restrict__ Ap, const __nv_bfloat16* __restrict__ Bp,
    const float* __restrict__ bias, float* __restrict__ C, int mode)
{
    extern __shared__ __align__(16) char smem[];
    const int tid = threadIdx.x;
    const int lane = tid & 31, wid = tid >> 5;
    const int wm = wid >> 2, wn = wid & 3;
    const int m0 = blockIdx.y * 128, n0 = blockIdx.x * 128;
    const uint32_t sb = smem_u32(smem);
    float acc[4][4][4];
    #pragma unroll
    for (int i = 0; i < 4; i++)
        #pragma unroll
        for (int j = 0; j < 4; j++)
            #pragma unroll
            for (int r = 0; r < 4; r++) acc[i][j][r] = 0.f;

    // per-thread copy coords (4 x 16B chunks per matrix per stage)
    int cr[4], cc[4];
    #pragma unroll
    for (int i = 0; i < 4; i++) {
        int e = tid + 256*i;
        cr[i] = e >> 3;
        cc[i] = (e & 7) * 8;
    }

    // ldmatrix lane addresses (offsets within a stage)
    const uint32_t a_off = (uint32_t)((wm*64 + (lane & 15))*144 + ((lane >> 4) << 4));
    const int g = lane >> 3, rl = lane & 7;
    const uint32_t b_off = (uint32_t)(18432 + (wn*32 + (g >> 1)*8 + rl)*144 + ((g & 1) << 4));

    // prologue: stage 0
    {
        #pragma unroll
        for (int i = 0; i < 4; i++) {
            uint32_t da = sb + (uint32_t)(cr[i]*144 + cc[i]*2);
            CP_ASYNC16(da, Ap + (size_t)(m0 + cr[i])*KP + cc[i]);
            CP_ASYNC16(da + 18432, Bp + (size_t)(n0 + cr[i])*KP + cc[i]);
        }
        CP_COMMIT();
    }

    for (int kt = 0; kt < 48; kt++) {
        const int s = kt & 1;
        if (kt + 1 < 48) {
            const int kb = (kt + 1) * 64;
            const uint32_t st = (uint32_t)((s ^ 1) * STAGE_BYTES);
            #pragma unroll
            for (int i = 0; i < 4; i++) {
                uint32_t da = sb + st + (uint32_t)(cr[i]*144 + cc[i]*2);
                CP_ASYNC16(da, Ap + (size_t)(m0 + cr[i])*KP + kb + cc[i]);
                CP_ASYNC16(da + 18432, Bp + (size_t)(n0 + cr[i])*KP + kb + cc[i]);
            }
            CP_COMMIT();
            CP_WAIT1();
        } else {
            CP_WAIT0();
        }
        __syncthreads();

        const uint32_t sbase = sb + (uint32_t)(s * STAGE_BYTES);
        const uint32_t a_addr = sbase + a_off;
        const uint32_t b_addr = sbase + b_off;
        #pragma unroll
        for (int ks = 0; ks < 4; ks++) {
            uint32_t af[4][4];
            #pragma unroll
            for (int mf = 0; mf < 4; mf++)
                ldsm_x4(af[mf][0], af[mf][1], af[mf][2], af[mf][3],
                        a_addr + mf*16*144 + ks*32);
            uint32_t bf[4][2];
            #pragma unroll
            for (int np = 0; np < 2; np++) {
                uint32_t r0, r1, r2, r3;
                ldsm_x4(r0, r1, r2, r3, b_addr + np*16*144 + ks*32);
                bf[np*2][0] = r0;   bf[np*2][1] = r1;
                bf[np*2+1][0] = r2; bf[np*2+1][1] = r3;
            }
            #pragma unroll
            for (int mf = 0; mf < 4; mf++)
                #pragma unroll
                for (int nf = 0; nf < 4; nf++)
                    mma16816(acc[mf][nf], af[mf], bf[nf]);
        }
        __syncthreads();
    }

    // epilogue
    const int qr = lane >> 2, qc = (lane & 3) * 2;
    #pragma unroll
    for (int mf = 0; mf < 4; mf++) {
        #pragma unroll
        for (int nf = 0; nf < 4; nf++) {
            int row = m0 + wm*64 + mf*16 + qr;
            int col = n0 + wn*32 + nf*8 + qc;
            float2 bi = *(const float2*)(bias + col);
            float2 v0 = make_float2(acc[mf][nf][0] + bi.x, acc[mf][nf][1] + bi.y);
            float2 v1 = make_float2(acc[mf][nf][2] + bi.x, acc[mf][nf][3] + bi.y);
            if (mode == 0) {
                int chunk = col >> 6, part = chunk >> 4, h = chunk & 15, dk = col & 63;
                float* gp = (part == 0) ? g_q : (part == 1) ? g_k : g_v;
                int b0 = row >> 9, t0 = row & 511;
                *(float2*)(gp + ((size_t)(b0*NH + h)*NT + t0)*NDK + dk) = v0;
                int r1 = row + 8;
                int b1 = r1 >> 9, t1 = r1 & 511;
                *(float2*)(gp + ((size_t)(b1*NH + h)*NT + t1)*NDK + dk) = v1;
            } else {
                *(float2*)(C + (size_t)row*1024 + col) = v0;
                *(float2*)(C + (size_t)(row + 8)*1024 + col) = v1;
            }
        }
    }
}

// ---------------------------------------------------------------------------
// Fused attention; ctx written directly as split/interleaved bf16 into g_cp.
// ---------------------------------------------------------------------------
#define SPAD 320

__global__ __launch_bounds__(256) void attn_fused_kernel(
    const float* __restrict__ rel_table, float* __restrict__ attn)
{
    __shared__ __align__(16) float Qs[64][17];
    __shared__ __align__(16) float Ks[64][68];
    __shared__ __align__(16) float S[16][SPAD];
    const int tid = threadIdx.x;
    const int tx = tid & 15, ty = tid >> 4;
    const int bh = blockIdx.y;
    const int b  = bh >> 4, h = bh & 15;
    const int q0 = blockIdx.x * 16;
    const int ws = max(0, q0 - 128);
    const int we = min(NT, q0 + 16 + 128);

    for (int i = tid; i < 16*SPAD; i += 256)
        ((float*)S)[i] = 0.f;

    const float* qptr = g_q + ((size_t)bh*NT + q0)*NDK;
    #pragma unroll
    for (int i = 0; i < 4; i++) {
        int idx = tid + 256*i;
        int r = idx >> 6, c = idx & 63;
        Qs[c][r] = qptr[(size_t)r*NDK + c];
    }
    const float* kbase = g_k + (size_t)bh*NT*NDK;

    for (int c0 = ws; c0 < we; c0 += 64) {
        __syncthreads();
        #pragma unroll
        for (int i = 0; i < 16; i++) {
            int idx = tid + 256*i;
            int r = idx >> 6, c = idx & 63;
            int jg = c0 + r;
            Ks[c][r] = (jg < we) ? kbase[(size_t)jg*NDK + c] : 0.f;
        }
        __syncthreads();
        unsigned long long s01 = 0ull, s23 = 0ull;
        #pragma unroll
        for (int d = 0; d < 64; d++) {
            unsigned long long qb = bcast2(Qs[d][ty]);
            ulonglong2 kv = *(const ulonglong2*)&Ks[d][tx*4];
            ffma2(s01, qb, kv.x);
            ffma2(s23, qb, kv.y);
        }
        float sc[4];
        unpack2(s01, sc[0], sc[1]);
        unpack2(s23, sc[2], sc[3]);
        const int qi = q0 + ty;
        #pragma unroll
        for (int j = 0; j < 4; j++) {
            int jg = c0 + tx*4 + j;
            if (jg < we)
                S[ty][jg - ws] = sc[j]*0.125f
                               + rel_table[(size_t)(jg - qi + 511)*NH + h];
        }
    }
    __syncthreads();

    const int warp = tid >> 5, lane = tid & 31;
    #pragma unroll
    for (int rr = 0; rr < 2; rr++) {
        int r  = warp*2 + rr;
        int qi = q0 + r;
        int jlo = max(0, qi - 128), jhi = min(NT - 1, qi + 128);
        int lo = jlo - ws, hi = jhi - ws;
        float mx = -1e30f;
        for (int idx = lo + lane; idx <= hi; idx += 32)
            mx = fmaxf(mx, S[r][idx]);
        #pragma unroll
        for (int o = 16; o > 0; o >>= 1)
            mx = fmaxf(mx, __shfl_xor_sync(0xffffffffu, mx, o));
        float sum = 0.f;
        for (int idx = lo + lane; idx <= hi; idx += 32) {
            float e = __expf(S[r][idx] - mx);
            S[r][idx] = e;
            sum += e;
        }
        #pragma unroll
        for (int o = 16; o > 0; o >>= 1)
            sum += __shfl_xor_sync(0xffffffffu, sum, o);
        float inv = 1.f / sum;
        int span = we - ws;
        for (int idx = lane; idx < span; idx += 32) {
            float v = (idx >= lo && idx <= hi) ? S[r][idx]*inv : 0.f;
            S[r][idx] = v;
        }
        __syncwarp();
        float* arow = attn + ((size_t)bh*NT + qi)*NT;
        for (int j4 = lane; j4 < 128; j4 += 32) {
            int j = j4*4;
            float4 o;
            o.x = (j+0 >= ws && j+0 < we) ? S[r][j+0 - ws] : 0.f;
            o.y = (j+1 >= ws && j+1 < we) ? S[r][j+1 - ws] : 0.f;
            o.z = (j+2 >= ws && j+2 < we) ? S[r][j+2 - ws] : 0.f;
            o.w = (j+3 >= ws && j+3 < we) ? S[r][j+3 - ws] : 0.f;
            ((float4*)arow)[j4] = o;
        }
    }

    // ctx = P @ V; write split/interleaved bf16 directly (A-side pattern)
    const float* vbase = g_v + (size_t)bh*NT*NDK;
    unsigned long long c01 = 0ull, c23 = 0ull;
    for (int c0 = ws; c0 < we; c0 += 64) {
        __syncthreads();
        #pragma unroll
        for (int i = 0; i < 16; i++) {
            int idx = tid + 256*i;
            int r = idx >> 6, c = idx & 63;
            int jg = c0 + r;
            Ks[r][c] = (jg < we) ? vbase[(size_t)jg*NDK + c] : 0.f;
        }
        __syncthreads();
        const int base = c0 - ws;
        #pragma unroll
        for (int j = 0; j < 64; j++) {
            unsigned long long pb = bcast2(S[ty][base + j]);
            ulonglong2 v2 = *(const ulonglong2*)&Ks[j][tx*4];
            ffma2(c01, pb, v2.x);
            ffma2(c23, pb, v2.y);
        }
    }
    float c[4];
    unpack2(c01, c[0], c[1]);
    unpack2(c23, c[2], c[3]);
    int qi = q0 + ty;
    unsigned short hh[4], ll[4];
    #pragma unroll
    for (int t = 0; t < 4; t++) split_bf16(c[t], hh[t], ll[t]);
    int m = b*NT + qi;
    int kk = h*NDK + tx*4;
    ushort4* d4 = (ushort4*)(g_cp + (size_t)m*KP + (size_t)kk*3);
    d4[0] = make_ushort4(hh[0], hh[0], ll[0], hh[1]);
    d4[1] = make_ushort4(hh[1], ll[1], hh[2], hh[2]);
    d4[2] = make_ushort4(ll[2], hh[3], hh[3], ll[3]);
}

// ---------------------------------------------------------------------------
extern "C" void kernel_launch(void* const* d_in, const int* in_sizes, int n_in,
                              void* d_out, int out_size)
{
    const float* x     = (const float*)d_in[0];
    const float* Wqkv  = (const float*)d_in[1];
    const float* bqkv  = (const float*)d_in[2];
    const float* Wo    = (const float*)d_in[3];
    const float* bo    = (const float*)d_in[4];
    const float* rel   = (const float*)d_in[5];

    float* out = (float*)d_out;
    float* attn;
    if ((size_t)out_size >= OUT_ELEMS + ATTN_ELEMS) {
        attn = out + OUT_ELEMS;
    } else {
        cudaGetSymbolAddress((void**)&attn, g_attn_fallback);
    }

    __nv_bfloat16 *ap, *bq, *bo2, *cp;
    cudaGetSymbolAddress((void**)&ap,  g_ap);
    cudaGetSymbolAddress((void**)&bq,  g_bq);
    cudaGetSymbolAddress((void**)&bo2, g_bo2);
    cudaGetSymbolAddress((void**)&cp,  g_cp);

    cudaFuncSetAttribute(mma_gemm_kernel,
                         cudaFuncAttributeMaxDynamicSharedMemorySize, GEMM_SMEM);

    // prep
    interleave_a_kernel<<<8192, 256>>>(x, ap);
    transpose_w_kernel<<<dim3(96, 32), 256>>>(Wqkv, 3072, bq);
    transpose_w_kernel<<<dim3(32, 32), 256>>>(Wo, 1024, bo2);

    // QKV projection
    mma_gemm_kernel<<<dim3(24, 64), 256, GEMM_SMEM>>>(ap, bq, bqkv, nullptr, 0);
    // fused attention (writes attn + split ctx)
    attn_fused_kernel<<<dim3(32, 256), 256>>>(rel, attn);
    // out projection
    mma_gemm_kernel<<<dim3(8, 64), 256, GEMM_SMEM>>>(cp, bo2, bo, out, 1);
}

// round 12
// speedup vs baseline: 2.0755x; 1.1506x over previous
#include <cuda_runtime.h>
#include <cuda_bf16.h>
#include <math.h>
#include <stdint.h>

#define NB 16
#define NT 512
#define ND 1024
#define NH 16
#define NDK 64
#define KP 3072   // expanded K (3x split terms)

#define OUT_ELEMS  ((size_t)NB*NT*ND)             // 8,388,608
#define ATTN_ELEMS ((size_t)NB*NH*NT*NT)          // 67,108,864

// ---------------------------------------------------------------------------
// Scratch (device globals: allocation-free per harness rules)
// ---------------------------------------------------------------------------
__device__ float g_q[NB*NH*NT*NDK];
__device__ float g_k[NB*NH*NT*NDK];
__device__ float g_v[NB*NH*NT*NDK];
__device__ float g_attn_fallback[NB*NH*NT*NT];

__device__ __align__(16) __nv_bfloat16 g_ap[8192ull*KP];    // x  split/interleaved
__device__ __align__(16) __nv_bfloat16 g_bq[3072ull*KP];    // Wqkv^T split/interleaved
__device__ __align__(16) __nv_bfloat16 g_bo2[1024ull*KP];   // Wo^T split/interleaved
__device__ __align__(16) __nv_bfloat16 g_cp[8192ull*KP];    // ctx split/interleaved
__device__ __align__(16) __nv_bfloat16 g_qp[(size_t)NB*NH*NT*192];  // Q' A-side
__device__ __align__(16) __nv_bfloat16 g_kp[(size_t)NB*NH*NT*192];  // K' B-side
__device__ __align__(16) __nv_bfloat16 g_vp[(size_t)NB*NH*NDK*1536]; // V'^T B-side

// ---------------------------------------------------------------------------
// helpers
// ---------------------------------------------------------------------------
__device__ __forceinline__ uint32_t smem_u32(const void* p) {
    uint32_t a;
    asm("{ .reg .u64 t; cvta.to.shared.u64 t, %1; cvt.u32.u64 %0, t; }"
        : "=r"(a) : "l"(p));
    return a;
}
__device__ __forceinline__ void ldsm_x4(uint32_t& r0, uint32_t& r1,
                                        uint32_t& r2, uint32_t& r3, uint32_t addr) {
    asm volatile("ldmatrix.sync.aligned.m8n8.x4.shared.b16 {%0,%1,%2,%3}, [%4];"
                 : "=r"(r0), "=r"(r1), "=r"(r2), "=r"(r3) : "r"(addr));
}
__device__ __forceinline__ void mma16816(float* d, const uint32_t* a, const uint32_t* b) {
    asm volatile("mma.sync.aligned.m16n8k16.row.col.f32.bf16.bf16.f32 "
                 "{%0,%1,%2,%3}, {%4,%5,%6,%7}, {%8,%9}, {%0,%1,%2,%3};"
                 : "+f"(d[0]), "+f"(d[1]), "+f"(d[2]), "+f"(d[3])
                 : "r"(a[0]), "r"(a[1]), "r"(a[2]), "r"(a[3]),
                   "r"(b[0]), "r"(b[1]));
}
#define CP_ASYNC16(dst, src) \
    asm volatile("cp.async.cg.shared.global [%0], [%1], 16;" :: "r"(dst), "l"(src))
#define CP_COMMIT()  asm volatile("cp.async.commit_group;" ::: "memory")
#define CP_WAIT0()   asm volatile("cp.async.wait_group 0;" ::: "memory")
#define CP_WAIT1()   asm volatile("cp.async.wait_group 1;" ::: "memory")

__device__ __forceinline__ void split_bf16(float x, unsigned short& h, unsigned short& l) {
    __nv_bfloat16 hb = __float2bfloat16_rn(x);
    float hr = __bfloat162float(hb);
    __nv_bfloat16 lb = __float2bfloat16_rn(x - hr);
    h = *(unsigned short*)&hb;
    l = *(unsigned short*)&lb;
}
__device__ __forceinline__ void write_a_pat(ushort4* d4, const unsigned short* h,
                                            const unsigned short* l) {
    d4[0] = make_ushort4(h[0], h[0], l[0], h[1]);
    d4[1] = make_ushort4(h[1], l[1], h[2], h[2]);
    d4[2] = make_ushort4(l[2], h[3], h[3], l[3]);
}
__device__ __forceinline__ void write_b_pat(ushort4* d4, const unsigned short* h,
                                            const unsigned short* l) {
    d4[0] = make_ushort4(h[0], l[0], h[0], h[1]);
    d4[1] = make_ushort4(l[1], h[1], h[2], l[2]);
    d4[2] = make_ushort4(h[2], h[3], l[3], h[3]);
}

// ---------------------------------------------------------------------------
// Prep: A-side interleave  A'[m][3k+{0,1,2}] = {hi,hi,lo}   (K=1024 rows)
// ---------------------------------------------------------------------------
__global__ __launch_bounds__(256) void interleave_a_kernel(
    const float* __restrict__ src, __nv_bfloat16* __restrict__ dst)
{
    int gid = blockIdx.x * 256 + threadIdx.x;
    int m  = gid >> 8;
    int k4 = (gid & 255) * 4;
    float4 v = *(const float4*)(src + (size_t)m*1024 + k4);
    unsigned short h[4], l[4];
    split_bf16(v.x, h[0], l[0]);
    split_bf16(v.y, h[1], l[1]);
    split_bf16(v.z, h[2], l[2]);
    split_bf16(v.w, h[3], l[3]);
    write_a_pat((ushort4*)(dst + (size_t)m*KP + (size_t)k4*3), h, l);
}

// ---------------------------------------------------------------------------
// Prep: B-side transpose + interleave.  W[k][n] -> B'[n][3k+{0,1,2}] = {hi,lo,hi}
// ---------------------------------------------------------------------------
__global__ __launch_bounds__(256) void transpose_w_kernel(
    const float* __restrict__ W, int Ncols, __nv_bfloat16* __restrict__ dst)
{
    __shared__ float s[32][33];
    const int tid = threadIdx.x;
    const int tx = tid & 31, ty = tid >> 5;
    const int n0 = blockIdx.x * 32, k0 = blockIdx.y * 32;
    #pragma unroll
    for (int i = 0; i < 4; i++)
        s[tx][ty + 8*i] = W[(size_t)(k0 + ty + 8*i)*Ncols + n0 + tx];
    __syncthreads();
    const int nn = tid >> 3;
    const int kq = (tid & 7) * 4;
    unsigned short h[4], l[4];
    #pragma unroll
    for (int t = 0; t < 4; t++)
        split_bf16(s[nn][kq + t], h[t], l[t]);
    write_b_pat((ushort4*)(dst + (size_t)(n0 + nn)*KP + (size_t)(k0 + kq)*3), h, l);
}

// ---------------------------------------------------------------------------
// Prep: Q'/K' from fp32 [row][64] -> [row][192] interleaved (bpat: 0=A, 1=B)
// ---------------------------------------------------------------------------
__global__ __launch_bounds__(256) void prep_qkp_kernel(
    const float* __restrict__ src, __nv_bfloat16* __restrict__ dst, int bpat)
{
    int gid = blockIdx.x * 256 + threadIdx.x;
    int row = gid >> 4;
    int d4  = (gid & 15) * 4;
    float4 v = *(const float4*)(src + (size_t)row*64 + d4);
    unsigned short h[4], l[4];
    split_bf16(v.x, h[0], l[0]);
    split_bf16(v.y, h[1], l[1]);
    split_bf16(v.z, h[2], l[2]);
    split_bf16(v.w, h[3], l[3]);
    ushort4* o = (ushort4*)(dst + (size_t)row*192 + d4*3);
    if (bpat) write_b_pat(o, h, l);
    else      write_a_pat(o, h, l);
}

// ---------------------------------------------------------------------------
// Prep: V transpose+interleave per bh: g_v[bh][j][d] -> g_vp[bh*64+d][3j] B-side
// ---------------------------------------------------------------------------
__global__ __launch_bounds__(256) void prep_vp_kernel()
{
    __shared__ float t[64][65];
    const int tid = threadIdx.x;
    const int bh = blockIdx.y, jb = blockIdx.x;
    const float* src = g_v + ((size_t)bh*NT + jb*64)*NDK;
    #pragma unroll
    for (int i = 0; i < 16; i++) {
        int e = tid + 256*i;
        t[e >> 6][e & 63] = src[e];
    }
    __syncthreads();
    #pragma unroll
    for (int i = 0; i < 4; i++) {
        int e = tid + 256*i;       // 0..1023
        int d = e >> 4, j4 = e & 15;
        unsigned short h[4], l[4];
        #pragma unroll
        for (int u = 0; u < 4; u++)
            split_bf16(t[j4*4 + u][d], h[u], l[u]);
        write_b_pat((ushort4*)(g_vp + ((size_t)(bh*NDK + d))*1536
                               + (size_t)(jb*64 + j4*4)*3), h, l);
    }
}

// ---------------------------------------------------------------------------
// bf16 mma.sync GEMM, 2-stage cp.async pipeline (unchanged from R7).
// ---------------------------------------------------------------------------
#define STAGE_BYTES 36864
#define GEMM_SMEM   73728

__global__ __launch_bounds__(256) void mma_gemm_kernel(
    const __nv_bfloat16* __restrict__ Ap, const __nv_bfloat16* __restrict__ Bp,
    const float* __restrict__ bias, float* __restrict__ C, int mode)
{
    extern __shared__ __align__(16) char smem[];
    const int tid = threadIdx.x;
    const int lane = tid & 31, wid = tid >> 5;
    const int wm = wid >> 2, wn = wid & 3;
    const int m0 = blockIdx.y * 128, n0 = blockIdx.x * 128;
    const uint32_t sb = smem_u32(smem);
    float acc[4][4][4];
    #pragma unroll
    for (int i = 0; i < 4; i++)
        #pragma unroll
        for (int j = 0; j < 4; j++)
            #pragma unroll
            for (int r = 0; r < 4; r++) acc[i][j][r] = 0.f;

    int cr[4], cc[4];
    #pragma unroll
    for (int i = 0; i < 4; i++) {
        int e = tid + 256*i;
        cr[i] = e >> 3;
        cc[i] = (e & 7) * 8;
    }
    const uint32_t a_off = (uint32_t)((wm*64 + (lane & 15))*144 + ((lane >> 4) << 4));
    const int g = lane >> 3, rl = lane & 7;
    const uint32_t b_off = (uint32_t)(18432 + (wn*32 + (g >> 1)*8 + rl)*144 + ((g & 1) << 4));

    {
        #pragma unroll
        for (int i = 0; i < 4; i++) {
            uint32_t da = sb + (uint32_t)(cr[i]*144 + cc[i]*2);
            CP_ASYNC16(da, Ap + (size_t)(m0 + cr[i])*KP + cc[i]);
            CP_ASYNC16(da + 18432, Bp + (size_t)(n0 + cr[i])*KP + cc[i]);
        }
        CP_COMMIT();
    }

    for (int kt = 0; kt < 48; kt++) {
        const int s = kt & 1;
        if (kt + 1 < 48) {
            const int kb = (kt + 1) * 64;
            const uint32_t st = (uint32_t)((s ^ 1) * STAGE_BYTES);
            #pragma unroll
            for (int i = 0; i < 4; i++) {
                uint32_t da = sb + st + (uint32_t)(cr[i]*144 + cc[i]*2);
                CP_ASYNC16(da, Ap + (size_t)(m0 + cr[i])*KP + kb + cc[i]);
                CP_ASYNC16(da + 18432, Bp + (size_t)(n0 + cr[i])*KP + kb + cc[i]);
            }
            CP_COMMIT();
            CP_WAIT1();
        } else {
            CP_WAIT0();
        }
        __syncthreads();

        const uint32_t sbase = sb + (uint32_t)(s * STAGE_BYTES);
        const uint32_t a_addr = sbase + a_off;
        const uint32_t b_addr = sbase + b_off;
        #pragma unroll
        for (int ks = 0; ks < 4; ks++) {
            uint32_t af[4][4];
            #pragma unroll
            for (int mf = 0; mf < 4; mf++)
                ldsm_x4(af[mf][0], af[mf][1], af[mf][2], af[mf][3],
                        a_addr + mf*16*144 + ks*32);
            uint32_t bf[4][2];
            #pragma unroll
            for (int np = 0; np < 2; np++) {
                uint32_t r0, r1, r2, r3;
                ldsm_x4(r0, r1, r2, r3, b_addr + np*16*144 + ks*32);
                bf[np*2][0] = r0;   bf[np*2][1] = r1;
                bf[np*2+1][0] = r2; bf[np*2+1][1] = r3;
            }
            #pragma unroll
            for (int mf = 0; mf < 4; mf++)
                #pragma unroll
                for (int nf = 0; nf < 4; nf++)
                    mma16816(acc[mf][nf], af[mf], bf[nf]);
        }
        __syncthreads();
    }

    const int qr = lane >> 2, qc = (lane & 3) * 2;
    #pragma unroll
    for (int mf = 0; mf < 4; mf++) {
        #pragma unroll
        for (int nf = 0; nf < 4; nf++) {
            int row = m0 + wm*64 + mf*16 + qr;
            int col = n0 + wn*32 + nf*8 + qc;
            float2 bi = *(const float2*)(bias + col);
            float2 v0 = make_float2(acc[mf][nf][0] + bi.x, acc[mf][nf][1] + bi.y);
            float2 v1 = make_float2(acc[mf][nf][2] + bi.x, acc[mf][nf][3] + bi.y);
            if (mode == 0) {
                int chunk = col >> 6, part = chunk >> 4, h = chunk & 15, dk = col & 63;
                float* gp = (part == 0) ? g_q : (part == 1) ? g_k : g_v;
                int b0 = row >> 9, t0 = row & 511;
                *(float2*)(gp + ((size_t)(b0*NH + h)*NT + t0)*NDK + dk) = v0;
                int r1 = row + 8;
                int b1 = r1 >> 9, t1 = r1 & 511;
                *(float2*)(gp + ((size_t)(b1*NH + h)*NT + t1)*NDK + dk) = v1;
            } else {
                *(float2*)(C + (size_t)row*1024 + col) = v0;
                *(float2*)(C + (size_t)(row + 8)*1024 + col) = v1;
            }
        }
    }
}

// ---------------------------------------------------------------------------
// Tensor-core attention. One block per (bh, 64-query tile), 256 threads.
// Dense scores via bf16-split mma (K'=192), fp32 S in smem, masked softmax,
// attn write, dense P@V via bf16-split mma, ctx -> g_cp split/interleaved.
// ---------------------------------------------------------------------------
#define SROW 516                    // S row stride (floats)
#define QROWB 400                   // bf16 buffer row stride (bytes)
#define OFF_BIAS 132096
#define OFF_BUF1 136192             // Q' / P'
#define OFF_BUF2 161792             // K' / V'
#define ATTN_SMEM 187392

__global__ __launch_bounds__(256) void attn_tc_kernel(
    const float* __restrict__ rel_table, float* __restrict__ attn)
{
    extern __shared__ __align__(16) char smem[];
    float* S = (float*)smem;
    float* sbias = (float*)(smem + OFF_BIAS);
    const uint32_t sb = smem_u32(smem);
    const int tid = threadIdx.x;
    const int lane = tid & 31, wid = tid >> 5;
    const int wm = wid >> 1, wn = wid & 1;      // 4(M) x 2(N)
    const int bh = blockIdx.y;
    const int b = bh >> 4, h = bh & 15;
    const int q0 = blockIdx.x * 64;

    // bias column for this head
    for (int i = tid; i < 1023; i += 256)
        sbias[i] = rel_table[(size_t)i*NH + h];

    // load Q' tile (64 rows x 384B) into buf1
    {
        const __nv_bfloat16* qsrc = g_qp + (size_t)(bh*NT + q0)*192;
        #pragma unroll
        for (int i = tid; i < 1536; i += 256) {
            int r = i / 24, c = i % 24;
            *(uint4*)(smem + OFF_BUF1 + r*QROWB + c*16) =
                *(const uint4*)((const char*)(qsrc + (size_t)r*192) + c*16);
        }
    }

    const uint32_t a_off = (uint32_t)((wm*16 + (lane & 15))*QROWB + ((lane >> 4) << 4));
    const int g = lane >> 3, rl = lane & 7;
    const uint32_t b_off = (uint32_t)((wn*32 + (g >> 1)*8 + rl)*QROWB + ((g & 1) << 4));
    const int qr = lane >> 2, qc = (lane & 3) * 2;
    const int rl0 = wm*16 + qr;

    // ---- scores: 8 key-blocks of 64 ----
    for (int jb = 0; jb < 8; jb++) {
        __syncthreads();
        const __nv_bfloat16* ksrc = g_kp + (size_t)(bh*NT + jb*64)*192;
        #pragma unroll
        for (int i = tid; i < 1536; i += 256) {
            int r = i / 24, c = i % 24;
            *(uint4*)(smem + OFF_BUF2 + r*QROWB + c*16) =
                *(const uint4*)((const char*)(ksrc + (size_t)r*192) + c*16);
        }
        __syncthreads();

        float acc[4][4];
        #pragma unroll
        for (int nf = 0; nf < 4; nf++)
            #pragma unroll
            for (int r = 0; r < 4; r++) acc[nf][r] = 0.f;

        #pragma unroll
        for (int ks = 0; ks < 12; ks++) {
            uint32_t af[4];
            ldsm_x4(af[0], af[1], af[2], af[3], sb + OFF_BUF1 + a_off + ks*32);
            uint32_t bf[4][2];
            #pragma unroll
            for (int np = 0; np < 2; np++) {
                uint32_t r0, r1, r2, r3;
                ldsm_x4(r0, r1, r2, r3, sb + OFF_BUF2 + b_off + np*16*QROWB + ks*32);
                bf[np*2][0] = r0;   bf[np*2][1] = r1;
                bf[np*2+1][0] = r2; bf[np*2+1][1] = r3;
            }
            #pragma unroll
            for (int nf = 0; nf < 4; nf++)
                mma16816(acc[nf], af, bf[nf]);
        }

        const int qi0 = q0 + rl0;
        #pragma unroll
        for (int nf = 0; nf < 4; nf++) {
            int cl = jb*64 + wn*32 + nf*8 + qc;
            S[rl0*SROW + cl]     = acc[nf][0]*0.125f + sbias[cl - qi0 + 511];
            S[rl0*SROW + cl + 1] = acc[nf][1]*0.125f + sbias[cl + 1 - qi0 + 511];
            S[(rl0+8)*SROW + cl]     = acc[nf][2]*0.125f + sbias[cl - qi0 - 8 + 511];
            S[(rl0+8)*SROW + cl + 1] = acc[nf][3]*0.125f + sbias[cl + 1 - qi0 - 8 + 511];
        }
    }
    __syncthreads();

    // ---- softmax + attn write: each warp owns 8 rows ----
    #pragma unroll
    for (int rr = 0; rr < 8; rr++) {
        int r = wid*8 + rr;
        int qi = q0 + r;
        int jlo = max(0, qi - 128), jhi = min(NT - 1, qi + 128);
        float mx = -1e30f;
        for (int j = jlo + lane; j <= jhi; j += 32)
            mx = fmaxf(mx, S[r*SROW + j]);
        #pragma unroll
        for (int o = 16; o > 0; o >>= 1)
            mx = fmaxf(mx, __shfl_xor_sync(0xffffffffu, mx, o));
        float sum = 0.f;
        for (int j = jlo + lane; j <= jhi; j += 32) {
            float e = __expf(S[r*SROW + j] - mx);
            S[r*SROW + j] = e;
            sum += e;
        }
        #pragma unroll
        for (int o = 16; o > 0; o >>= 1)
            sum += __shfl_xor_sync(0xffffffffu, sum, o);
        float inv = 1.f / sum;
        float* arow = attn + ((size_t)bh*NT + qi)*NT;
        for (int j = lane; j < NT; j += 32) {
            float v = (j >= jlo && j <= jhi) ? S[r*SROW + j]*inv : 0.f;
            S[r*SROW + j] = v;
            arow[j] = v;
        }
    }
    __syncthreads();

    // ---- PV: 8 key-blocks; P split to buf1, V' tile to buf2 ----
    float cacc[4][4];
    #pragma unroll
    for (int nf = 0; nf < 4; nf++)
        #pragma unroll
        for (int r = 0; r < 4; r++) cacc[nf][r] = 0.f;

    for (int jb = 0; jb < 8; jb++) {
        __syncthreads();
        // convert P chunk [64 q][64 j] -> A-side interleave in buf1
        #pragma unroll
        for (int i = 0; i < 4; i++) {
            int e = tid + 256*i;      // 0..1023
            int q = e >> 4, j4 = e & 15;
            const float* sp = &S[q*SROW + jb*64 + j4*4];
            unsigned short hh[4], ll[4];
            #pragma unroll
            for (int u = 0; u < 4; u++) split_bf16(sp[u], hh[u], ll[u]);
            write_a_pat((ushort4*)(smem + OFF_BUF1 + q*QROWB + j4*24), hh, ll);
        }
        // load V' tile (rows = d)
        const __nv_bfloat16* vsrc = g_vp + (size_t)(bh*NDK)*1536 + (size_t)jb*192;
        #pragma unroll
        for (int i = tid; i < 1536; i += 256) {
            int r = i / 24, c = i % 24;
            *(uint4*)(smem + OFF_BUF2 + r*QROWB + c*16) =
                *(const uint4*)((const char*)(vsrc + (size_t)r*1536) + c*16);
        }
        __syncthreads();

        #pragma unroll
        for (int ks = 0; ks < 12; ks++) {
            uint32_t af[4];
            ldsm_x4(af[0], af[1], af[2], af[3], sb + OFF_BUF1 + a_off + ks*32);
            uint32_t bf[4][2];
            #pragma unroll
            for (int np = 0; np < 2; np++) {
                uint32_t r0, r1, r2, r3;
                ldsm_x4(r0, r1, r2, r3, sb + OFF_BUF2 + b_off + np*16*QROWB + ks*32);
                bf[np*2][0] = r0;   bf[np*2][1] = r1;
                bf[np*2+1][0] = r2; bf[np*2+1][1] = r3;
            }
            #pragma unroll
            for (int nf = 0; nf < 4; nf++)
                mma16816(cacc[nf], af, bf[nf]);
        }
    }
    __syncthreads();

    // stage ctx (64 q x 64 d) into S cols 0..63
    #pragma unroll
    for (int nf = 0; nf < 4; nf++) {
        int cl = wn*32 + nf*8 + qc;
        S[rl0*SROW + cl]     = cacc[nf][0];
        S[rl0*SROW + cl + 1] = cacc[nf][1];
        S[(rl0+8)*SROW + cl]     = cacc[nf][2];
        S[(rl0+8)*SROW + cl + 1] = cacc[nf][3];
    }
    __syncthreads();

    // write ctx as split/interleaved bf16 into g_cp
    #pragma unroll
    for (int i = 0; i < 4; i++) {
        int e = tid + 256*i;
        int q = e >> 4, d4 = e & 15;
        const float* sp = &S[q*SROW + d4*4];
        unsigned short hh[4], ll[4];
        #pragma unroll
        for (int u = 0; u < 4; u++) split_bf16(sp[u], hh[u], ll[u]);
        size_t m = (size_t)b*NT + q0 + q;
        write_a_pat((ushort4*)(g_cp + m*KP + (size_t)(h*NDK + d4*4)*3), hh, ll);
    }
}

// ---------------------------------------------------------------------------
extern "C" void kernel_launch(void* const* d_in, const int* in_sizes, int n_in,
                              void* d_out, int out_size)
{
    const float* x     = (const float*)d_in[0];
    const float* Wqkv  = (const float*)d_in[1];
    const float* bqkv  = (const float*)d_in[2];
    const float* Wo    = (const float*)d_in[3];
    const float* bo    = (const float*)d_in[4];
    const float* rel   = (const float*)d_in[5];

    float* out = (float*)d_out;
    float* attn;
    if ((size_t)out_size >= OUT_ELEMS + ATTN_ELEMS) {
        attn = out + OUT_ELEMS;
    } else {
        cudaGetSymbolAddress((void**)&attn, g_attn_fallback);
    }

    __nv_bfloat16 *ap, *bq, *bo2, *cp, *qp, *kp;
    float *qf, *kf;
    cudaGetSymbolAddress((void**)&ap,  g_ap);
    cudaGetSymbolAddress((void**)&bq,  g_bq);
    cudaGetSymbolAddress((void**)&bo2, g_bo2);
    cudaGetSymbolAddress((void**)&cp,  g_cp);
    cudaGetSymbolAddress((void**)&qp,  g_qp);
    cudaGetSymbolAddress((void**)&kp,  g_kp);
    cudaGetSymbolAddress((void**)&qf,  g_q);
    cudaGetSymbolAddress((void**)&kf,  g_k);

    cudaFuncSetAttribute(mma_gemm_kernel,
                         cudaFuncAttributeMaxDynamicSharedMemorySize, GEMM_SMEM);
    cudaFuncSetAttribute(attn_tc_kernel,
                         cudaFuncAttributeMaxDynamicSharedMemorySize, ATTN_SMEM);

    // prep inputs
    interleave_a_kernel<<<8192, 256>>>(x, ap);
    transpose_w_kernel<<<dim3(96, 32), 256>>>(Wqkv, 3072, bq);
    transpose_w_kernel<<<dim3(32, 32), 256>>>(Wo, 1024, bo2);

    // QKV projection (writes fp32 g_q/g_k/g_v)
    mma_gemm_kernel<<<dim3(24, 64), 256, GEMM_SMEM>>>(ap, bq, bqkv, nullptr, 0);

    // attention preps
    prep_qkp_kernel<<<8192, 256>>>(qf, qp, 0);
    prep_qkp_kernel<<<8192, 256>>>(kf, kp, 1);
    prep_vp_kernel<<<dim3(8, 256), 256>>>();

    // tensor-core attention (writes attn + split ctx)
    attn_tc_kernel<<<dim3(8, 256), 256, ATTN_SMEM>>>(rel, attn);

    // out projection
    mma_gemm_kernel<<<dim3(8, 64), 256, GEMM_SMEM>>>(cp, bo2, bo, out, 1);
}

// round 13
// speedup vs baseline: 2.3156x; 1.1157x over previous
#include <cuda_runtime.h>
#include <cuda_bf16.h>
#include <math.h>
#include <stdint.h>

#define NB 16
#define NT 512
#define ND 1024
#define NH 16
#define NDK 64
#define KP 3072   // expanded K (3x split terms)

#define OUT_ELEMS  ((size_t)NB*NT*ND)             // 8,388,608
#define ATTN_ELEMS ((size_t)NB*NH*NT*NT)          // 67,108,864

// ---------------------------------------------------------------------------
// Scratch (device globals: allocation-free per harness rules)
// ---------------------------------------------------------------------------
__device__ float g_q[NB*NH*NT*NDK];
__device__ float g_k[NB*NH*NT*NDK];
__device__ float g_v[NB*NH*NT*NDK];
__device__ float g_attn_fallback[NB*NH*NT*NT];

__device__ __align__(16) __nv_bfloat16 g_ap[8192ull*KP];    // x  split/interleaved
__device__ __align__(16) __nv_bfloat16 g_bq[3072ull*KP];    // Wqkv^T split/interleaved
__device__ __align__(16) __nv_bfloat16 g_bo2[1024ull*KP];   // Wo^T split/interleaved
__device__ __align__(16) __nv_bfloat16 g_cp[8192ull*KP];    // ctx split/interleaved
__device__ __align__(16) __nv_bfloat16 g_qp[(size_t)NB*NH*NT*192];  // Q' A-side
__device__ __align__(16) __nv_bfloat16 g_kp[(size_t)NB*NH*NT*192];  // K' B-side
__device__ __align__(16) __nv_bfloat16 g_vp[(size_t)NB*NH*NDK*1536]; // V'^T B-side

// ---------------------------------------------------------------------------
// helpers
// ---------------------------------------------------------------------------
__device__ __forceinline__ uint32_t smem_u32(const void* p) {
    uint32_t a;
    asm("{ .reg .u64 t; cvta.to.shared.u64 t, %1; cvt.u32.u64 %0, t; }"
        : "=r"(a) : "l"(p));
    return a;
}
__device__ __forceinline__ void ldsm_x4(uint32_t& r0, uint32_t& r1,
                                        uint32_t& r2, uint32_t& r3, uint32_t addr) {
    asm volatile("ldmatrix.sync.aligned.m8n8.x4.shared.b16 {%0,%1,%2,%3}, [%4];"
                 : "=r"(r0), "=r"(r1), "=r"(r2), "=r"(r3) : "r"(addr));
}
__device__ __forceinline__ void mma16816(float* d, const uint32_t* a, const uint32_t* b) {
    asm volatile("mma.sync.aligned.m16n8k16.row.col.f32.bf16.bf16.f32 "
                 "{%0,%1,%2,%3}, {%4,%5,%6,%7}, {%8,%9}, {%0,%1,%2,%3};"
                 : "+f"(d[0]), "+f"(d[1]), "+f"(d[2]), "+f"(d[3])
                 : "r"(a[0]), "r"(a[1]), "r"(a[2]), "r"(a[3]),
                   "r"(b[0]), "r"(b[1]));
}
#define CP_ASYNC16(dst, src) \
    asm volatile("cp.async.cg.shared.global [%0], [%1], 16;" :: "r"(dst), "l"(src))
#define CP_COMMIT()  asm volatile("cp.async.commit_group;" ::: "memory")
#define CP_WAIT0()   asm volatile("cp.async.wait_group 0;" ::: "memory")
#define CP_WAIT1()   asm volatile("cp.async.wait_group 1;" ::: "memory")

__device__ __forceinline__ void split_bf16(float x, unsigned short& h, unsigned short& l) {
    __nv_bfloat16 hb = __float2bfloat16_rn(x);
    float hr = __bfloat162float(hb);
    __nv_bfloat16 lb = __float2bfloat16_rn(x - hr);
    h = *(unsigned short*)&hb;
    l = *(unsigned short*)&lb;
}
__device__ __forceinline__ void write_a_pat(ushort4* d4, const unsigned short* h,
                                            const unsigned short* l) {
    d4[0] = make_ushort4(h[0], h[0], l[0], h[1]);
    d4[1] = make_ushort4(h[1], l[1], h[2], h[2]);
    d4[2] = make_ushort4(l[2], h[3], h[3], l[3]);
}
__device__ __forceinline__ void write_b_pat(ushort4* d4, const unsigned short* h,
                                            const unsigned short* l) {
    d4[0] = make_ushort4(h[0], l[0], h[0], h[1]);
    d4[1] = make_ushort4(l[1], h[1], h[2], l[2]);
    d4[2] = make_ushort4(h[2], h[3], l[3], h[3]);
}

// ---------------------------------------------------------------------------
// Prep kernels (unchanged from R12)
// ---------------------------------------------------------------------------
__global__ __launch_bounds__(256) void interleave_a_kernel(
    const float* __restrict__ src, __nv_bfloat16* __restrict__ dst)
{
    int gid = blockIdx.x * 256 + threadIdx.x;
    int m  = gid >> 8;
    int k4 = (gid & 255) * 4;
    float4 v = *(const float4*)(src + (size_t)m*1024 + k4);
    unsigned short h[4], l[4];
    split_bf16(v.x, h[0], l[0]);
    split_bf16(v.y, h[1], l[1]);
    split_bf16(v.z, h[2], l[2]);
    split_bf16(v.w, h[3], l[3]);
    write_a_pat((ushort4*)(dst + (size_t)m*KP + (size_t)k4*3), h, l);
}

__global__ __launch_bounds__(256) void transpose_w_kernel(
    const float* __restrict__ W, int Ncols, __nv_bfloat16* __restrict__ dst)
{
    __shared__ float s[32][33];
    const int tid = threadIdx.x;
    const int tx = tid & 31, ty = tid >> 5;
    const int n0 = blockIdx.x * 32, k0 = blockIdx.y * 32;
    #pragma unroll
    for (int i = 0; i < 4; i++)
        s[tx][ty + 8*i] = W[(size_t)(k0 + ty + 8*i)*Ncols + n0 + tx];
    __syncthreads();
    const int nn = tid >> 3;
    const int kq = (tid & 7) * 4;
    unsigned short h[4], l[4];
    #pragma unroll
    for (int t = 0; t < 4; t++)
        split_bf16(s[nn][kq + t], h[t], l[t]);
    write_b_pat((ushort4*)(dst + (size_t)(n0 + nn)*KP + (size_t)(k0 + kq)*3), h, l);
}

__global__ __launch_bounds__(256) void prep_qkp_kernel(
    const float* __restrict__ src, __nv_bfloat16* __restrict__ dst, int bpat)
{
    int gid = blockIdx.x * 256 + threadIdx.x;
    int row = gid >> 4;
    int d4  = (gid & 15) * 4;
    float4 v = *(const float4*)(src + (size_t)row*64 + d4);
    unsigned short h[4], l[4];
    split_bf16(v.x, h[0], l[0]);
    split_bf16(v.y, h[1], l[1]);
    split_bf16(v.z, h[2], l[2]);
    split_bf16(v.w, h[3], l[3]);
    ushort4* o = (ushort4*)(dst + (size_t)row*192 + d4*3);
    if (bpat) write_b_pat(o, h, l);
    else      write_a_pat(o, h, l);
}

__global__ __launch_bounds__(256) void prep_vp_kernel()
{
    __shared__ float t[64][65];
    const int tid = threadIdx.x;
    const int bh = blockIdx.y, jb = blockIdx.x;
    const float* src = g_v + ((size_t)bh*NT + jb*64)*NDK;
    #pragma unroll
    for (int i = 0; i < 16; i++) {
        int e = tid + 256*i;
        t[e >> 6][e & 63] = src[e];
    }
    __syncthreads();
    #pragma unroll
    for (int i = 0; i < 4; i++) {
        int e = tid + 256*i;
        int d = e >> 4, j4 = e & 15;
        unsigned short h[4], l[4];
        #pragma unroll
        for (int u = 0; u < 4; u++)
            split_bf16(t[j4*4 + u][d], h[u], l[u]);
        write_b_pat((ushort4*)(g_vp + ((size_t)(bh*NDK + d))*1536
                               + (size_t)(jb*64 + j4*4)*3), h, l);
    }
}

// ---------------------------------------------------------------------------
// bf16 mma.sync GEMM, 3-stage cp.async pipeline, ONE sync per K-tile.
// Safety: prefetch of slot (kt+2)%3 is issued AFTER sync(kt); readers of that
// slot (iter kt-1) all passed sync(kt) first.
// ---------------------------------------------------------------------------
#define STAGE_BYTES 36864
#define GEMM_SMEM   110592          // 3 stages

__global__ __launch_bounds__(256) void mma_gemm_kernel(
    const __nv_bfloat16* __restrict__ Ap, const __nv_bfloat16* __restrict__ Bp,
    const float* __restrict__ bias, float* __restrict__ C, int mode)
{
    extern __shared__ __align__(16) char smem[];
    const int tid = threadIdx.x;
    const int lane = tid & 31, wid = tid >> 5;
    const int wm = wid >> 2, wn = wid & 3;
    const int m0 = blockIdx.y * 128, n0 = blockIdx.x * 128;
    const uint32_t sb = smem_u32(smem);
    float acc[4][4][4];
    #pragma unroll
    for (int i = 0; i < 4; i++)
        #pragma unroll
        for (int j = 0; j < 4; j++)
            #pragma unroll
            for (int r = 0; r < 4; r++) acc[i][j][r] = 0.f;

    int cr[4], cc[4];
    #pragma unroll
    for (int i = 0; i < 4; i++) {
        int e = tid + 256*i;
        cr[i] = e >> 3;
        cc[i] = (e & 7) * 8;
    }
    const uint32_t a_off = (uint32_t)((wm*64 + (lane & 15))*144 + ((lane >> 4) << 4));
    const int g = lane >> 3, rl = lane & 7;
    const uint32_t b_off = (uint32_t)(18432 + (wn*32 + (g >> 1)*8 + rl)*144 + ((g & 1) << 4));

    // prologue: stages 0 and 1
    #pragma unroll
    for (int s = 0; s < 2; s++) {
        const uint32_t st = (uint32_t)(s * STAGE_BYTES);
        const int kb = s * 64;
        #pragma unroll
        for (int i = 0; i < 4; i++) {
            uint32_t da = sb + st + (uint32_t)(cr[i]*144 + cc[i]*2);
            CP_ASYNC16(da, Ap + (size_t)(m0 + cr[i])*KP + kb + cc[i]);
            CP_ASYNC16(da + 18432, Bp + (size_t)(n0 + cr[i])*KP + kb + cc[i]);
        }
        CP_COMMIT();
    }

    for (int kt = 0; kt < 48; kt++) {
        if (kt == 47) CP_WAIT0(); else CP_WAIT1();
        __syncthreads();
        if (kt + 2 < 48) {
            const int kb = (kt + 2) * 64;
            const uint32_t st = (uint32_t)(((kt + 2) % 3) * STAGE_BYTES);
            #pragma unroll
            for (int i = 0; i < 4; i++) {
                uint32_t da = sb + st + (uint32_t)(cr[i]*144 + cc[i]*2);
                CP_ASYNC16(da, Ap + (size_t)(m0 + cr[i])*KP + kb + cc[i]);
                CP_ASYNC16(da + 18432, Bp + (size_t)(n0 + cr[i])*KP + kb + cc[i]);
            }
            CP_COMMIT();
        }

        const uint32_t sbase = sb + (uint32_t)((kt % 3) * STAGE_BYTES);
        const uint32_t a_addr = sbase + a_off;
        const uint32_t b_addr = sbase + b_off;
        #pragma unroll
        for (int ks = 0; ks < 4; ks++) {
            uint32_t af[4][4];
            #pragma unroll
            for (int mf = 0; mf < 4; mf++)
                ldsm_x4(af[mf][0], af[mf][1], af[mf][2], af[mf][3],
                        a_addr + mf*16*144 + ks*32);
            uint32_t bf[4][2];
            #pragma unroll
            for (int np = 0; np < 2; np++) {
                uint32_t r0, r1, r2, r3;
                ldsm_x4(r0, r1, r2, r3, b_addr + np*16*144 + ks*32);
                bf[np*2][0] = r0;   bf[np*2][1] = r1;
                bf[np*2+1][0] = r2; bf[np*2+1][1] = r3;
            }
            #pragma unroll
            for (int mf = 0; mf < 4; mf++)
                #pragma unroll
                for (int nf = 0; nf < 4; nf++)
                    mma16816(acc[mf][nf], af[mf], bf[nf]);
        }
    }
    __syncthreads();

    const int qr = lane >> 2, qc = (lane & 3) * 2;
    #pragma unroll
    for (int mf = 0; mf < 4; mf++) {
        #pragma unroll
        for (int nf = 0; nf < 4; nf++) {
            int row = m0 + wm*64 + mf*16 + qr;
            int col = n0 + wn*32 + nf*8 + qc;
            float2 bi = *(const float2*)(bias + col);
            float2 v0 = make_float2(acc[mf][nf][0] + bi.x, acc[mf][nf][1] + bi.y);
            float2 v1 = make_float2(acc[mf][nf][2] + bi.x, acc[mf][nf][3] + bi.y);
            if (mode == 0) {
                int chunk = col >> 6, part = chunk >> 4, h = chunk & 15, dk = col & 63;
                float* gp = (part == 0) ? g_q : (part == 1) ? g_k : g_v;
                int b0 = row >> 9, t0 = row & 511;
                *(float2*)(gp + ((size_t)(b0*NH + h)*NT + t0)*NDK + dk) = v0;
                int r1 = row + 8;
                int b1 = r1 >> 9, t1 = r1 & 511;
                *(float2*)(gp + ((size_t)(b1*NH + h)*NT + t1)*NDK + dk) = v1;
            } else {
                *(float2*)(C + (size_t)row*1024 + col) = v0;
                *(float2*)(C + (size_t)(row + 8)*1024 + col) = v1;
            }
        }
    }
}

// ---------------------------------------------------------------------------
// Tensor-core attention, WINDOWED: only key blocks [q0-128, q0+192) (3-5 of 8).
// S is windowed (<=320 cols). K'/V' tiles double-buffered via cp.async.
// ---------------------------------------------------------------------------
#define SROW 324                    // S row stride (floats), 320 + 4 pad
#define QROWB 400                   // bf16 buffer row stride (bytes)
#define OFF_BIAS 82944
#define OFF_BUF1 87040              // Q' / P'
#define OFF_BUF2 112640             // K' / V' (2 stages x 25600)
#define KV_STAGE 25600
#define ATTN_SMEM 163840

__global__ __launch_bounds__(256) void attn_tc_kernel(
    const float* __restrict__ rel_table, float* __restrict__ attn)
{
    extern __shared__ __align__(16) char smem[];
    float* S = (float*)smem;
    float* sbias = (float*)(smem + OFF_BIAS);
    const uint32_t sb = smem_u32(smem);
    const int tid = threadIdx.x;
    const int lane = tid & 31, wid = tid >> 5;
    const int wm = wid >> 1, wn = wid & 1;      // 4(M) x 2(N)
    const int bh = blockIdx.y;
    const int b = bh >> 4, h = bh & 15;
    const int q0 = blockIdx.x * 64;
    const int js = max(0, q0 - 128);
    const int je = min(NT, q0 + 64 + 128);
    const int jb_lo = js >> 6;
    const int nblk = (je - js) >> 6;            // 3..5, all blocks full

    // bias column for this head
    for (int i = tid; i < 1023; i += 256)
        sbias[i] = rel_table[(size_t)i*NH + h];

    // load Q' tile (64 rows x 384B) into buf1
    {
        const __nv_bfloat16* qsrc = g_qp + (size_t)(bh*NT + q0)*192;
        for (int i = tid; i < 1536; i += 256) {
            int r = i / 24, c = i % 24;
            *(uint4*)(smem + OFF_BUF1 + r*QROWB + c*16) =
                *(const uint4*)((const char*)(qsrc + (size_t)r*192) + c*16);
        }
    }

    const uint32_t a_off = (uint32_t)((wm*16 + (lane & 15))*QROWB + ((lane >> 4) << 4));
    const int g = lane >> 3, rl = lane & 7;
    const uint32_t b_off = (uint32_t)((wn*32 + (g >> 1)*8 + rl)*QROWB + ((g & 1) << 4));
    const int qr = lane >> 2, qc = (lane & 3) * 2;
    const int rl0 = wm*16 + qr;

    // ---- scores: prologue prefetch of first K block ----
    {
        const __nv_bfloat16* ksrc = g_kp + (size_t)(bh*NT + jb_lo*64)*192;
        for (int i = tid; i < 1536; i += 256) {
            int r = i / 24, c = i % 24;
            CP_ASYNC16(sb + OFF_BUF2 + (uint32_t)(r*QROWB + c*16),
                       (const char*)(ksrc + (size_t)r*192) + c*16);
        }
        CP_COMMIT();
    }

    for (int ib = 0; ib < nblk; ib++) {
        CP_WAIT0();
        __syncthreads();
        if (ib + 1 < nblk) {
            const __nv_bfloat16* ksrc = g_kp + (size_t)(bh*NT + (jb_lo + ib + 1)*64)*192;
            const uint32_t st = (uint32_t)(((ib + 1) & 1) * KV_STAGE);
            for (int i = tid; i < 1536; i += 256) {
                int r = i / 24, c = i % 24;
                CP_ASYNC16(sb + OFF_BUF2 + st + (uint32_t)(r*QROWB + c*16),
                           (const char*)(ksrc + (size_t)r*192) + c*16);
            }
            CP_COMMIT();
        }

        float acc[4][4];
        #pragma unroll
        for (int nf = 0; nf < 4; nf++)
            #pragma unroll
            for (int r = 0; r < 4; r++) acc[nf][r] = 0.f;

        const uint32_t kbase = sb + OFF_BUF2 + (uint32_t)((ib & 1) * KV_STAGE);
        #pragma unroll
        for (int ks = 0; ks < 12; ks++) {
            uint32_t af[4];
            ldsm_x4(af[0], af[1], af[2], af[3], sb + OFF_BUF1 + a_off + ks*32);
            uint32_t bf[4][2];
            #pragma unroll
            for (int np = 0; np < 2; np++) {
                uint32_t r0, r1, r2, r3;
                ldsm_x4(r0, r1, r2, r3, kbase + b_off + np*16*QROWB + ks*32);
                bf[np*2][0] = r0;   bf[np*2][1] = r1;
                bf[np*2+1][0] = r2; bf[np*2+1][1] = r3;
            }
            #pragma unroll
            for (int nf = 0; nf < 4; nf++)
                mma16816(acc[nf], af, bf[nf]);
        }

        #pragma unroll
        for (int nf = 0; nf < 4; nf++) {
            int cl = ib*64 + wn*32 + nf*8 + qc;      // local col
            int j  = js + cl;                         // global key
            int qiA = q0 + rl0, qiB = qiA + 8;
            S[rl0*SROW + cl]     = acc[nf][0]*0.125f + sbias[j - qiA + 511];
            S[rl0*SROW + cl + 1] = acc[nf][1]*0.125f + sbias[j + 1 - qiA + 511];
            S[(rl0+8)*SROW + cl]     = acc[nf][2]*0.125f + sbias[j - qiB + 511];
            S[(rl0+8)*SROW + cl + 1] = acc[nf][3]*0.125f + sbias[j + 1 - qiB + 511];
        }
    }
    __syncthreads();

    // ---- softmax + attn write: each warp owns 8 rows ----
    #pragma unroll
    for (int rr = 0; rr < 8; rr++) {
        int r = wid*8 + rr;
        int qi = q0 + r;
        int jlo = max(0, qi - 128), jhi = min(NT - 1, qi + 128);
        float mx = -1e30f;
        for (int j = jlo + lane; j <= jhi; j += 32)
            mx = fmaxf(mx, S[r*SROW + j - js]);
        #pragma unroll
        for (int o = 16; o > 0; o >>= 1)
            mx = fmaxf(mx, __shfl_xor_sync(0xffffffffu, mx, o));
        float sum = 0.f;
        for (int j = jlo + lane; j <= jhi; j += 32) {
            float e = __expf(S[r*SROW + j - js] - mx);
            S[r*SROW + j - js] = e;
            sum += e;
        }
        #pragma unroll
        for (int o = 16; o > 0; o >>= 1)
            sum += __shfl_xor_sync(0xffffffffu, sum, o);
        float inv = 1.f / sum;
        float* arow = attn + ((size_t)bh*NT + qi)*NT;
        for (int j = lane; j < NT; j += 32) {
            float v = 0.f;
            if (j >= jlo && j <= jhi) {
                v = S[r*SROW + j - js]*inv;
                S[r*SROW + j - js] = v;
            } else if (j >= js && j < je) {
                S[r*SROW + j - js] = 0.f;    // masked in-window entries -> 0 for PV
            }
            arow[j] = v;
        }
    }
    __syncthreads();

    // ---- PV over the same window ----
    float cacc[4][4];
    #pragma unroll
    for (int nf = 0; nf < 4; nf++)
        #pragma unroll
        for (int r = 0; r < 4; r++) cacc[nf][r] = 0.f;

    // prologue prefetch of first V block
    {
        const __nv_bfloat16* vsrc = g_vp + (size_t)(bh*NDK)*1536 + (size_t)jb_lo*192;
        for (int i = tid; i < 1536; i += 256) {
            int r = i / 24, c = i % 24;
            CP_ASYNC16(sb + OFF_BUF2 + (uint32_t)(r*QROWB + c*16),
                       (const char*)(vsrc + (size_t)r*1536) + c*16);
        }
        CP_COMMIT();
    }

    for (int ib = 0; ib < nblk; ib++) {
        CP_WAIT0();
        if (ib + 1 < nblk) {
            const __nv_bfloat16* vsrc = g_vp + (size_t)(bh*NDK)*1536
                                        + (size_t)(jb_lo + ib + 1)*192;
            const uint32_t st = (uint32_t)(((ib + 1) & 1) * KV_STAGE);
            for (int i = tid; i < 1536; i += 256) {
                int r = i / 24, c = i % 24;
                CP_ASYNC16(sb + OFF_BUF2 + st + (uint32_t)(r*QROWB + c*16),
                           (const char*)(vsrc + (size_t)r*1536) + c*16);
            }
            CP_COMMIT();
        }
        // convert P chunk ib -> A-side interleave in buf1
        #pragma unroll
        for (int i = 0; i < 4; i++) {
            int e = tid + 256*i;
            int q = e >> 4, j4 = e & 15;
            const float* sp = &S[q*SROW + ib*64 + j4*4];
            unsigned short hh[4], ll[4];
            #pragma unroll
            for (int u = 0; u < 4; u++) split_bf16(sp[u], hh[u], ll[u]);
            write_a_pat((ushort4*)(smem + OFF_BUF1 + q*QROWB + j4*24), hh, ll);
        }
        __syncthreads();

        const uint32_t vbase = sb + OFF_BUF2 + (uint32_t)((ib & 1) * KV_STAGE);
        #pragma unroll
        for (int ks = 0; ks < 12; ks++) {
            uint32_t af[4];
            ldsm_x4(af[0], af[1], af[2], af[3], sb + OFF_BUF1 + a_off + ks*32);
            uint32_t bf[4][2];
            #pragma unroll
            for (int np = 0; np < 2; np++) {
                uint32_t r0, r1, r2, r3;
                ldsm_x4(r0, r1, r2, r3, vbase + b_off + np*16*QROWB + ks*32);
                bf[np*2][0] = r0;   bf[np*2][1] = r1;
                bf[np*2+1][0] = r2; bf[np*2+1][1] = r3;
            }
            #pragma unroll
            for (int nf = 0; nf < 4; nf++)
                mma16816(cacc[nf], af, bf[nf]);
        }
        __syncthreads();
    }

    // stage ctx (64 q x 64 d) into S cols 0..63
    #pragma unroll
    for (int nf = 0; nf < 4; nf++) {
        int cl = wn*32 + nf*8 + qc;
        S[rl0*SROW + cl]     = cacc[nf][0];
        S[rl0*SROW + cl + 1] = cacc[nf][1];
        S[(rl0+8)*SROW + cl]     = cacc[nf][2];
        S[(rl0+8)*SROW + cl + 1] = cacc[nf][3];
    }
    __syncthreads();

    // write ctx as split/interleaved bf16 into g_cp
    #pragma unroll
    for (int i = 0; i < 4; i++) {
        int e = tid + 256*i;
        int q = e >> 4, d4 = e & 15;
        const float* sp = &S[q*SROW + d4*4];
        unsigned short hh[4], ll[4];
        #pragma unroll
        for (int u = 0; u < 4; u++) split_bf16(sp[u], hh[u], ll[u]);
        size_t m = (size_t)b*NT + q0 + q;
        write_a_pat((ushort4*)(g_cp + m*KP + (size_t)(h*NDK + d4*4)*3), hh, ll);
    }
}

// ---------------------------------------------------------------------------
extern "C" void kernel_launch(void* const* d_in, const int* in_sizes, int n_in,
                              void* d_out, int out_size)
{
    const float* x     = (const float*)d_in[0];
    const float* Wqkv  = (const float*)d_in[1];
    const float* bqkv  = (const float*)d_in[2];
    const float* Wo    = (const float*)d_in[3];
    const float* bo    = (const float*)d_in[4];
    const float* rel   = (const float*)d_in[5];

    float* out = (float*)d_out;
    float* attn;
    if ((size_t)out_size >= OUT_ELEMS + ATTN_ELEMS) {
        attn = out + OUT_ELEMS;
    } else {
        cudaGetSymbolAddress((void**)&attn, g_attn_fallback);
    }

    __nv_bfloat16 *ap, *bq, *bo2, *cp, *qp, *kp;
    float *qf, *kf;
    cudaGetSymbolAddress((void**)&ap,  g_ap);
    cudaGetSymbolAddress((void**)&bq,  g_bq);
    cudaGetSymbolAddress((void**)&bo2, g_bo2);
    cudaGetSymbolAddress((void**)&cp,  g_cp);
    cudaGetSymbolAddress((void**)&qp,  g_qp);
    cudaGetSymbolAddress((void**)&kp,  g_kp);
    cudaGetSymbolAddress((void**)&qf,  g_q);
    cudaGetSymbolAddress((void**)&kf,  g_k);

    cudaFuncSetAttribute(mma_gemm_kernel,
                         cudaFuncAttributeMaxDynamicSharedMemorySize, GEMM_SMEM);
    cudaFuncSetAttribute(attn_tc_kernel,
                         cudaFuncAttributeMaxDynamicSharedMemorySize, ATTN_SMEM);

    // prep inputs
    interleave_a_kernel<<<8192, 256>>>(x, ap);
    transpose_w_kernel<<<dim3(96, 32), 256>>>(Wqkv, 3072, bq);
    transpose_w_kernel<<<dim3(32, 32), 256>>>(Wo, 1024, bo2);

    // QKV projection (writes fp32 g_q/g_k/g_v)
    mma_gemm_kernel<<<dim3(24, 64), 256, GEMM_SMEM>>>(ap, bq, bqkv, nullptr, 0);

    // attention preps
    prep_qkp_kernel<<<8192, 256>>>(qf, qp, 0);
    prep_qkp_kernel<<<8192, 256>>>(kf, kp, 1);
    prep_vp_kernel<<<dim3(8, 256), 256>>>();

    // tensor-core attention (writes attn + split ctx)
    attn_tc_kernel<<<dim3(8, 256), 256, ATTN_SMEM>>>(rel, attn);

    // out projection
    mma_gemm_kernel<<<dim3(8, 64), 256, GEMM_SMEM>>>(cp, bo2, bo, out, 1);
}

// round 14
// speedup vs baseline: 2.4595x; 1.0622x over previous
#include <cuda_runtime.h>
#include <cuda_bf16.h>
#include <math.h>
#include <stdint.h>

#define NB 16
#define NT 512
#define ND 1024
#define NH 16
#define NDK 64
#define KP 3072   // expanded K (3x split terms)

#define OUT_ELEMS  ((size_t)NB*NT*ND)             // 8,388,608
#define ATTN_ELEMS ((size_t)NB*NH*NT*NT)          // 67,108,864

// ---------------------------------------------------------------------------
// Scratch (device globals: allocation-free per harness rules)
// ---------------------------------------------------------------------------
__device__ float g_attn_fallback[NB*NH*NT*NT];

__device__ __align__(16) __nv_bfloat16 g_ap[8192ull*KP];    // x  split/interleaved
__device__ __align__(16) __nv_bfloat16 g_bq[3072ull*KP];    // Wqkv^T split/interleaved
__device__ __align__(16) __nv_bfloat16 g_bo2[1024ull*KP];   // Wo^T split/interleaved
__device__ __align__(16) __nv_bfloat16 g_cp[8192ull*KP];    // ctx split/interleaved
__device__ __align__(16) __nv_bfloat16 g_qp[(size_t)NB*NH*NT*192];  // Q' A-side
__device__ __align__(16) __nv_bfloat16 g_kp[(size_t)NB*NH*NT*192];  // K' B-side
__device__ __align__(16) __nv_bfloat16 g_vp[(size_t)NB*NH*NDK*1536]; // V'^T B-side

// ---------------------------------------------------------------------------
// helpers
// ---------------------------------------------------------------------------
__device__ __forceinline__ uint32_t smem_u32(const void* p) {
    uint32_t a;
    asm("{ .reg .u64 t; cvta.to.shared.u64 t, %1; cvt.u32.u64 %0, t; }"
        : "=r"(a) : "l"(p));
    return a;
}
__device__ __forceinline__ void ldsm_x4(uint32_t& r0, uint32_t& r1,
                                        uint32_t& r2, uint32_t& r3, uint32_t addr) {
    asm volatile("ldmatrix.sync.aligned.m8n8.x4.shared.b16 {%0,%1,%2,%3}, [%4];"
                 : "=r"(r0), "=r"(r1), "=r"(r2), "=r"(r3) : "r"(addr));
}
__device__ __forceinline__ void mma16816(float* d, const uint32_t* a, const uint32_t* b) {
    asm volatile("mma.sync.aligned.m16n8k16.row.col.f32.bf16.bf16.f32 "
                 "{%0,%1,%2,%3}, {%4,%5,%6,%7}, {%8,%9}, {%0,%1,%2,%3};"
                 : "+f"(d[0]), "+f"(d[1]), "+f"(d[2]), "+f"(d[3])
                 : "r"(a[0]), "r"(a[1]), "r"(a[2]), "r"(a[3]),
                   "r"(b[0]), "r"(b[1]));
}
#define CP_ASYNC16(dst, src) \
    asm volatile("cp.async.cg.shared.global [%0], [%1], 16;" :: "r"(dst), "l"(src))
#define CP_COMMIT()  asm volatile("cp.async.commit_group;" ::: "memory")
#define CP_WAIT0()   asm volatile("cp.async.wait_group 0;" ::: "memory")
#define CP_WAIT1()   asm volatile("cp.async.wait_group 1;" ::: "memory")

__device__ __forceinline__ void split_bf16(float x, unsigned short& h, unsigned short& l) {
    __nv_bfloat16 hb = __float2bfloat16_rn(x);
    float hr = __bfloat162float(hb);
    __nv_bfloat16 lb = __float2bfloat16_rn(x - hr);
    h = *(unsigned short*)&hb;
    l = *(unsigned short*)&lb;
}
__device__ __forceinline__ void write_a_pat(ushort4* d4, const unsigned short* h,
                                            const unsigned short* l) {
    d4[0] = make_ushort4(h[0], h[0], l[0], h[1]);
    d4[1] = make_ushort4(h[1], l[1], h[2], h[2]);
    d4[2] = make_ushort4(l[2], h[3], h[3], l[3]);
}
__device__ __forceinline__ void write_b_pat(ushort4* d4, const unsigned short* h,
                                            const unsigned short* l) {
    d4[0] = make_ushort4(h[0], l[0], h[0], h[1]);
    d4[1] = make_ushort4(l[1], h[1], h[2], l[2]);
    d4[2] = make_ushort4(h[2], h[3], l[3], h[3]);
}

// ---------------------------------------------------------------------------
// Prep kernels (input side only)
// ---------------------------------------------------------------------------
__global__ __launch_bounds__(256) void interleave_a_kernel(
    const float* __restrict__ src, __nv_bfloat16* __restrict__ dst)
{
    int gid = blockIdx.x * 256 + threadIdx.x;
    int m  = gid >> 8;
    int k4 = (gid & 255) * 4;
    float4 v = *(const float4*)(src + (size_t)m*1024 + k4);
    unsigned short h[4], l[4];
    split_bf16(v.x, h[0], l[0]);
    split_bf16(v.y, h[1], l[1]);
    split_bf16(v.z, h[2], l[2]);
    split_bf16(v.w, h[3], l[3]);
    write_a_pat((ushort4*)(dst + (size_t)m*KP + (size_t)k4*3), h, l);
}

__global__ __launch_bounds__(256) void transpose_w_kernel(
    const float* __restrict__ W, int Ncols, __nv_bfloat16* __restrict__ dst)
{
    __shared__ float s[32][33];
    const int tid = threadIdx.x;
    const int tx = tid & 31, ty = tid >> 5;
    const int n0 = blockIdx.x * 32, k0 = blockIdx.y * 32;
    #pragma unroll
    for (int i = 0; i < 4; i++)
        s[tx][ty + 8*i] = W[(size_t)(k0 + ty + 8*i)*Ncols + n0 + tx];
    __syncthreads();
    const int nn = tid >> 3;
    const int kq = (tid & 7) * 4;
    unsigned short h[4], l[4];
    #pragma unroll
    for (int t = 0; t < 4; t++)
        split_bf16(s[nn][kq + t], h[t], l[t]);
    write_b_pat((ushort4*)(dst + (size_t)(n0 + nn)*KP + (size_t)(k0 + kq)*3), h, l);
}

// ---------------------------------------------------------------------------
// bf16 mma.sync GEMM, 2-stage cp.async pipeline (R7 config — measured best).
// mode 0: epilogue stages tile in smem and emits Q'/K'/V' interleaved directly
//         (prep kernels fused away). mode 1: row-major C + bias.
// ---------------------------------------------------------------------------
#define STAGE_BYTES 36864
#define GEMM_SMEM   73728

__global__ __launch_bounds__(256) void mma_gemm_kernel(
    const __nv_bfloat16* __restrict__ Ap, const __nv_bfloat16* __restrict__ Bp,
    const float* __restrict__ bias, float* __restrict__ C, int mode)
{
    extern __shared__ __align__(16) char smem[];
    const int tid = threadIdx.x;
    const int lane = tid & 31, wid = tid >> 5;
    const int wm = wid >> 2, wn = wid & 3;
    const int m0 = blockIdx.y * 128, n0 = blockIdx.x * 128;
    const uint32_t sb = smem_u32(smem);
    float acc[4][4][4];
    #pragma unroll
    for (int i = 0; i < 4; i++)
        #pragma unroll
        for (int j = 0; j < 4; j++)
            #pragma unroll
            for (int r = 0; r < 4; r++) acc[i][j][r] = 0.f;

    int cr[4], cc[4];
    #pragma unroll
    for (int i = 0; i < 4; i++) {
        int e = tid + 256*i;
        cr[i] = e >> 3;
        cc[i] = (e & 7) * 8;
    }
    const uint32_t a_off = (uint32_t)((wm*64 + (lane & 15))*144 + ((lane >> 4) << 4));
    const int g = lane >> 3, rl = lane & 7;
    const uint32_t b_off = (uint32_t)(18432 + (wn*32 + (g >> 1)*8 + rl)*144 + ((g & 1) << 4));

    {
        #pragma unroll
        for (int i = 0; i < 4; i++) {
            uint32_t da = sb + (uint32_t)(cr[i]*144 + cc[i]*2);
            CP_ASYNC16(da, Ap + (size_t)(m0 + cr[i])*KP + cc[i]);
            CP_ASYNC16(da + 18432, Bp + (size_t)(n0 + cr[i])*KP + cc[i]);
        }
        CP_COMMIT();
    }

    for (int kt = 0; kt < 48; kt++) {
        const int s = kt & 1;
        if (kt + 1 < 48) {
            const int kb = (kt + 1) * 64;
            const uint32_t st = (uint32_t)((s ^ 1) * STAGE_BYTES);
            #pragma unroll
            for (int i = 0; i < 4; i++) {
                uint32_t da = sb + st + (uint32_t)(cr[i]*144 + cc[i]*2);
                CP_ASYNC16(da, Ap + (size_t)(m0 + cr[i])*KP + kb + cc[i]);
                CP_ASYNC16(da + 18432, Bp + (size_t)(n0 + cr[i])*KP + kb + cc[i]);
            }
            CP_COMMIT();
            CP_WAIT1();
        } else {
            CP_WAIT0();
        }
        __syncthreads();

        const uint32_t sbase = sb + (uint32_t)(s * STAGE_BYTES);
        const uint32_t a_addr = sbase + a_off;
        const uint32_t b_addr = sbase + b_off;
        #pragma unroll
        for (int ks = 0; ks < 4; ks++) {
            uint32_t af[4][4];
            #pragma unroll
            for (int mf = 0; mf < 4; mf++)
                ldsm_x4(af[mf][0], af[mf][1], af[mf][2], af[mf][3],
                        a_addr + mf*16*144 + ks*32);
            uint32_t bf[4][2];
            #pragma unroll
            for (int np = 0; np < 2; np++) {
                uint32_t r0, r1, r2, r3;
                ldsm_x4(r0, r1, r2, r3, b_addr + np*16*144 + ks*32);
                bf[np*2][0] = r0;   bf[np*2][1] = r1;
                bf[np*2+1][0] = r2; bf[np*2+1][1] = r3;
            }
            #pragma unroll
            for (int mf = 0; mf < 4; mf++)
                #pragma unroll
                for (int nf = 0; nf < 4; nf++)
                    mma16816(acc[mf][nf], af[mf], bf[nf]);
        }
        __syncthreads();
    }

    const int qr = lane >> 2, qc = (lane & 3) * 2;

    if (mode == 1) {
        #pragma unroll
        for (int mf = 0; mf < 4; mf++) {
            #pragma unroll
            for (int nf = 0; nf < 4; nf++) {
                int row = m0 + wm*64 + mf*16 + qr;
                int col = n0 + wn*32 + nf*8 + qc;
                float2 bi = *(const float2*)(bias + col);
                *(float2*)(C + (size_t)row*1024 + col) =
                    make_float2(acc[mf][nf][0] + bi.x, acc[mf][nf][1] + bi.y);
                *(float2*)(C + (size_t)(row + 8)*1024 + col) =
                    make_float2(acc[mf][nf][2] + bi.x, acc[mf][nf][3] + bi.y);
            }
        }
        return;
    }

    // ---- mode 0: stage tile (+bias) in smem, emit Q'/K'/V' directly ----
    float* stage = (float*)smem;             // 128 x 132 fp32 = 67584 B
    #pragma unroll
    for (int mf = 0; mf < 4; mf++) {
        #pragma unroll
        for (int nf = 0; nf < 4; nf++) {
            int r = wm*64 + mf*16 + qr;
            int c = wn*32 + nf*8 + qc;
            float2 bi = *(const float2*)(bias + n0 + c);
            stage[(size_t)r*132 + c]     = acc[mf][nf][0] + bi.x;
            stage[(size_t)r*132 + c + 1] = acc[mf][nf][1] + bi.y;
            stage[(size_t)(r+8)*132 + c]     = acc[mf][nf][2] + bi.x;
            stage[(size_t)(r+8)*132 + c + 1] = acc[mf][nf][3] + bi.y;
        }
    }
    __syncthreads();

    #pragma unroll
    for (int ch = 0; ch < 2; ch++) {
        const int gcol0 = n0 + ch*64;
        const int chunk = gcol0 >> 6;        // 0..47
        const int part  = chunk >> 4;        // 0=q, 1=k, 2=v
        const int h     = chunk & 15;
        if (part < 2) {
            __nv_bfloat16* dst = (part == 0) ? g_qp : g_kp;
            #pragma unroll
            for (int it = 0; it < 8; it++) {
                int task = tid + 256*it;     // 0..2047
                int r = task >> 4, dq = task & 15;
                const float* sp = &stage[(size_t)r*132 + ch*64 + dq*4];
                unsigned short hh[4], ll[4];
                #pragma unroll
                for (int u = 0; u < 4; u++) split_bf16(sp[u], hh[u], ll[u]);
                int m = m0 + r;
                int bb = m >> 9, t = m & 511;
                ushort4* o = (ushort4*)(dst + ((size_t)((bb*NH + h)*NT + t))*192
                                        + (size_t)dq*12);
                if (part == 0) write_a_pat(o, hh, ll);
                else           write_b_pat(o, hh, ll);
            }
        } else {
            #pragma unroll
            for (int it = 0; it < 8; it++) {
                int task = tid + 256*it;     // 0..2047
                int d = task >> 5, jq = task & 31;
                unsigned short hh[4], ll[4];
                #pragma unroll
                for (int u = 0; u < 4; u++)
                    split_bf16(stage[(size_t)(jq*4 + u)*132 + ch*64 + d],
                               hh[u], ll[u]);
                int m = m0 + jq*4;           // 4 consecutive seq positions, same b
                int bb = m >> 9, t = m & 511;
                int bh = bb*NH + h;
                write_b_pat((ushort4*)(g_vp + ((size_t)(bh*NDK + d))*1536
                                       + (size_t)t*3), hh, ll);
            }
        }
    }
}

// ---------------------------------------------------------------------------
// Tensor-core attention, WINDOWED (unchanged from R13).
// ---------------------------------------------------------------------------
#define SROW 324
#define QROWB 400
#define OFF_BIAS 82944
#define OFF_BUF1 87040
#define OFF_BUF2 112640
#define KV_STAGE 25600
#define ATTN_SMEM 163840

__global__ __launch_bounds__(256) void attn_tc_kernel(
    const float* __restrict__ rel_table, float* __restrict__ attn)
{
    extern __shared__ __align__(16) char smem[];
    float* S = (float*)smem;
    float* sbias = (float*)(smem + OFF_BIAS);
    const uint32_t sb = smem_u32(smem);
    const int tid = threadIdx.x;
    const int lane = tid & 31, wid = tid >> 5;
    const int wm = wid >> 1, wn = wid & 1;      // 4(M) x 2(N)
    const int bh = blockIdx.y;
    const int b = bh >> 4, h = bh & 15;
    const int q0 = blockIdx.x * 64;
    const int js = max(0, q0 - 128);
    const int je = min(NT, q0 + 64 + 128);
    const int jb_lo = js >> 6;
    const int nblk = (je - js) >> 6;

    for (int i = tid; i < 1023; i += 256)
        sbias[i] = rel_table[(size_t)i*NH + h];

    {
        const __nv_bfloat16* qsrc = g_qp + (size_t)(bh*NT + q0)*192;
        for (int i = tid; i < 1536; i += 256) {
            int r = i / 24, c = i % 24;
            *(uint4*)(smem + OFF_BUF1 + r*QROWB + c*16) =
                *(const uint4*)((const char*)(qsrc + (size_t)r*192) + c*16);
        }
    }

    const uint32_t a_off = (uint32_t)((wm*16 + (lane & 15))*QROWB + ((lane >> 4) << 4));
    const int g = lane >> 3, rl = lane & 7;
    const uint32_t b_off = (uint32_t)((wn*32 + (g >> 1)*8 + rl)*QROWB + ((g & 1) << 4));
    const int qr = lane >> 2, qc = (lane & 3) * 2;
    const int rl0 = wm*16 + qr;

    {
        const __nv_bfloat16* ksrc = g_kp + (size_t)(bh*NT + jb_lo*64)*192;
        for (int i = tid; i < 1536; i += 256) {
            int r = i / 24, c = i % 24;
            CP_ASYNC16(sb + OFF_BUF2 + (uint32_t)(r*QROWB + c*16),
                       (const char*)(ksrc + (size_t)r*192) + c*16);
        }
        CP_COMMIT();
    }

    for (int ib = 0; ib < nblk; ib++) {
        CP_WAIT0();
        __syncthreads();
        if (ib + 1 < nblk) {
            const __nv_bfloat16* ksrc = g_kp + (size_t)(bh*NT + (jb_lo + ib + 1)*64)*192;
            const uint32_t st = (uint32_t)(((ib + 1) & 1) * KV_STAGE);
            for (int i = tid; i < 1536; i += 256) {
                int r = i / 24, c = i % 24;
                CP_ASYNC16(sb + OFF_BUF2 + st + (uint32_t)(r*QROWB + c*16),
                           (const char*)(ksrc + (size_t)r*192) + c*16);
            }
            CP_COMMIT();
        }

        float acc[4][4];
        #pragma unroll
        for (int nf = 0; nf < 4; nf++)
            #pragma unroll
            for (int r = 0; r < 4; r++) acc[nf][r] = 0.f;

        const uint32_t kbase = sb + OFF_BUF2 + (uint32_t)((ib & 1) * KV_STAGE);
        #pragma unroll
        for (int ks = 0; ks < 12; ks++) {
            uint32_t af[4];
            ldsm_x4(af[0], af[1], af[2], af[3], sb + OFF_BUF1 + a_off + ks*32);
            uint32_t bf[4][2];
            #pragma unroll
            for (int np = 0; np < 2; np++) {
                uint32_t r0, r1, r2, r3;
                ldsm_x4(r0, r1, r2, r3, kbase + b_off + np*16*QROWB + ks*32);
                bf[np*2][0] = r0;   bf[np*2][1] = r1;
                bf[np*2+1][0] = r2; bf[np*2+1][1] = r3;
            }
            #pragma unroll
            for (int nf = 0; nf < 4; nf++)
                mma16816(acc[nf], af, bf[nf]);
        }

        #pragma unroll
        for (int nf = 0; nf < 4; nf++) {
            int cl = ib*64 + wn*32 + nf*8 + qc;
            int j  = js + cl;
            int qiA = q0 + rl0, qiB = qiA + 8;
            S[rl0*SROW + cl]     = acc[nf][0]*0.125f + sbias[j - qiA + 511];
            S[rl0*SROW + cl + 1] = acc[nf][1]*0.125f + sbias[j + 1 - qiA + 511];
            S[(rl0+8)*SROW + cl]     = acc[nf][2]*0.125f + sbias[j - qiB + 511];
            S[(rl0+8)*SROW + cl + 1] = acc[nf][3]*0.125f + sbias[j + 1 - qiB + 511];
        }
    }
    __syncthreads();

    #pragma unroll
    for (int rr = 0; rr < 8; rr++) {
        int r = wid*8 + rr;
        int qi = q0 + r;
        int jlo = max(0, qi - 128), jhi = min(NT - 1, qi + 128);
        float mx = -1e30f;
        for (int j = jlo + lane; j <= jhi; j += 32)
            mx = fmaxf(mx, S[r*SROW + j - js]);
        #pragma unroll
        for (int o = 16; o > 0; o >>= 1)
            mx = fmaxf(mx, __shfl_xor_sync(0xffffffffu, mx, o));
        float sum = 0.f;
        for (int j = jlo + lane; j <= jhi; j += 32) {
            float e = __expf(S[r*SROW + j - js] - mx);
            S[r*SROW + j - js] = e;
            sum += e;
        }
        #pragma unroll
        for (int o = 16; o > 0; o >>= 1)
            sum += __shfl_xor_sync(0xffffffffu, sum, o);
        float inv = 1.f / sum;
        float* arow = attn + ((size_t)bh*NT + qi)*NT;
        for (int j = lane; j < NT; j += 32) {
            float v = 0.f;
            if (j >= jlo && j <= jhi) {
                v = S[r*SROW + j - js]*inv;
                S[r*SROW + j - js] = v;
            } else if (j >= js && j < je) {
                S[r*SROW + j - js] = 0.f;
            }
            arow[j] = v;
        }
    }
    __syncthreads();

    float cacc[4][4];
    #pragma unroll
    for (int nf = 0; nf < 4; nf++)
        #pragma unroll
        for (int r = 0; r < 4; r++) cacc[nf][r] = 0.f;

    {
        const __nv_bfloat16* vsrc = g_vp + (size_t)(bh*NDK)*1536 + (size_t)jb_lo*192;
        for (int i = tid; i < 1536; i += 256) {
            int r = i / 24, c = i % 24;
            CP_ASYNC16(sb + OFF_BUF2 + (uint32_t)(r*QROWB + c*16),
                       (const char*)(vsrc + (size_t)r*1536) + c*16);
        }
        CP_COMMIT();
    }

    for (int ib = 0; ib < nblk; ib++) {
        CP_WAIT0();
        if (ib + 1 < nblk) {
            const __nv_bfloat16* vsrc = g_vp + (size_t)(bh*NDK)*1536
                                        + (size_t)(jb_lo + ib + 1)*192;
            const uint32_t st = (uint32_t)(((ib + 1) & 1) * KV_STAGE);
            for (int i = tid; i < 1536; i += 256) {
                int r = i / 24, c = i % 24;
                CP_ASYNC16(sb + OFF_BUF2 + st + (uint32_t)(r*QROWB + c*16),
                           (const char*)(vsrc + (size_t)r*1536) + c*16);
            }
            CP_COMMIT();
        }
        #pragma unroll
        for (int i = 0; i < 4; i++) {
            int e = tid + 256*i;
            int q = e >> 4, j4 = e & 15;
            const float* sp = &S[q*SROW + ib*64 + j4*4];
            unsigned short hh[4], ll[4];
            #pragma unroll
            for (int u = 0; u < 4; u++) split_bf16(sp[u], hh[u], ll[u]);
            write_a_pat((ushort4*)(smem + OFF_BUF1 + q*QROWB + j4*24), hh, ll);
        }
        __syncthreads();

        const uint32_t vbase = sb + OFF_BUF2 + (uint32_t)((ib & 1) * KV_STAGE);
        #pragma unroll
        for (int ks = 0; ks < 12; ks++) {
            uint32_t af[4];
            ldsm_x4(af[0], af[1], af[2], af[3], sb + OFF_BUF1 + a_off + ks*32);
            uint32_t bf[4][2];
            #pragma unroll
            for (int np = 0; np < 2; np++) {
                uint32_t r0, r1, r2, r3;
                ldsm_x4(r0, r1, r2, r3, vbase + b_off + np*16*QROWB + ks*32);
                bf[np*2][0] = r0;   bf[np*2][1] = r1;
                bf[np*2+1][0] = r2; bf[np*2+1][1] = r3;
            }
            #pragma unroll
            for (int nf = 0; nf < 4; nf++)
                mma16816(cacc[nf], af, bf[nf]);
        }
        __syncthreads();
    }

    #pragma unroll
    for (int nf = 0; nf < 4; nf++) {
        int cl = wn*32 + nf*8 + qc;
        S[rl0*SROW + cl]     = cacc[nf][0];
        S[rl0*SROW + cl + 1] = cacc[nf][1];
        S[(rl0+8)*SROW + cl]     = cacc[nf][2];
        S[(rl0+8)*SROW + cl + 1] = cacc[nf][3];
    }
    __syncthreads();

    #pragma unroll
    for (int i = 0; i < 4; i++) {
        int e = tid + 256*i;
        int q = e >> 4, d4 = e & 15;
        const float* sp = &S[q*SROW + d4*4];
        unsigned short hh[4], ll[4];
        #pragma unroll
        for (int u = 0; u < 4; u++) split_bf16(sp[u], hh[u], ll[u]);
        size_t m = (size_t)b*NT + q0 + q;
        write_a_pat((ushort4*)(g_cp + m*KP + (size_t)(h*NDK + d4*4)*3), hh, ll);
    }
}

// ---------------------------------------------------------------------------
extern "C" void kernel_launch(void* const* d_in, const int* in_sizes, int n_in,
                              void* d_out, int out_size)
{
    const float* x     = (const float*)d_in[0];
    const float* Wqkv  = (const float*)d_in[1];
    const float* bqkv  = (const float*)d_in[2];
    const float* Wo    = (const float*)d_in[3];
    const float* bo    = (const float*)d_in[4];
    const float* rel   = (const float*)d_in[5];

    float* out = (float*)d_out;
    float* attn;
    if ((size_t)out_size >= OUT_ELEMS + ATTN_ELEMS) {
        attn = out + OUT_ELEMS;
    } else {
        cudaGetSymbolAddress((void**)&attn, g_attn_fallback);
    }

    __nv_bfloat16 *ap, *bq, *bo2, *cp;
    cudaGetSymbolAddress((void**)&ap,  g_ap);
    cudaGetSymbolAddress((void**)&bq,  g_bq);
    cudaGetSymbolAddress((void**)&bo2, g_bo2);
    cudaGetSymbolAddress((void**)&cp,  g_cp);

    cudaFuncSetAttribute(mma_gemm_kernel,
                         cudaFuncAttributeMaxDynamicSharedMemorySize, GEMM_SMEM);
    cudaFuncSetAttribute(attn_tc_kernel,
                         cudaFuncAttributeMaxDynamicSharedMemorySize, ATTN_SMEM);

    // prep inputs
    interleave_a_kernel<<<8192, 256>>>(x, ap);
    transpose_w_kernel<<<dim3(96, 32), 256>>>(Wqkv, 3072, bq);
    transpose_w_kernel<<<dim3(32, 32), 256>>>(Wo, 1024, bo2);

    // QKV projection (epilogue emits Q'/K'/V' interleaved directly)
    mma_gemm_kernel<<<dim3(24, 64), 256, GEMM_SMEM>>>(ap, bq, bqkv, nullptr, 0);

    // tensor-core attention (writes attn + split ctx)
    attn_tc_kernel<<<dim3(8, 256), 256, ATTN_SMEM>>>(rel, attn);

    // out projection
    mma_gemm_kernel<<<dim3(8, 64), 256, GEMM_SMEM>>>(cp, bo2, bo, out, 1);
}

// round 15
// speedup vs baseline: 3.0546x; 1.2419x over previous
#include <cuda_runtime.h>
#include <cuda_bf16.h>
#include <cuda_fp16.h>
#include <math.h>
#include <stdint.h>

#define NB 16
#define NT 512
#define ND 1024
#define NH 16
#define NDK 64
#define KP2 2048   // expanded K for GEMMs (2x fp16 split terms)

#define OUT_ELEMS  ((size_t)NB*NT*ND)             // 8,388,608
#define ATTN_ELEMS ((size_t)NB*NH*NT*NT)          // 67,108,864

// ---------------------------------------------------------------------------
// Scratch (device globals: allocation-free per harness rules)
// ---------------------------------------------------------------------------
__device__ float g_attn_fallback[NB*NH*NT*NT];

__device__ __align__(16) __half g_ap[8192ull*KP2];    // x  split/interleaved (fp16 A-pat)
__device__ __align__(16) __half g_bq[3072ull*KP2];    // Wqkv^T replicated (fp16 B-pat)
__device__ __align__(16) __half g_bo2[1024ull*KP2];   // Wo^T replicated
__device__ __align__(16) __half g_cp[8192ull*KP2];    // ctx split/interleaved
__device__ __align__(16) __nv_bfloat16 g_qp[(size_t)NB*NH*NT*192];  // Q' A-side (bf16-3)
__device__ __align__(16) __nv_bfloat16 g_kp[(size_t)NB*NH*NT*192];  // K' B-side
__device__ __align__(16) __nv_bfloat16 g_vp[(size_t)NB*NH*NDK*1536]; // V'^T B-side

// ---------------------------------------------------------------------------
// helpers
// ---------------------------------------------------------------------------
__device__ __forceinline__ uint32_t smem_u32(const void* p) {
    uint32_t a;
    asm("{ .reg .u64 t; cvta.to.shared.u64 t, %1; cvt.u32.u64 %0, t; }"
        : "=r"(a) : "l"(p));
    return a;
}
__device__ __forceinline__ void ldsm_x4(uint32_t& r0, uint32_t& r1,
                                        uint32_t& r2, uint32_t& r3, uint32_t addr) {
    asm volatile("ldmatrix.sync.aligned.m8n8.x4.shared.b16 {%0,%1,%2,%3}, [%4];"
                 : "=r"(r0), "=r"(r1), "=r"(r2), "=r"(r3) : "r"(addr));
}
__device__ __forceinline__ void mma_bf16(float* d, const uint32_t* a, const uint32_t* b) {
    asm volatile("mma.sync.aligned.m16n8k16.row.col.f32.bf16.bf16.f32 "
                 "{%0,%1,%2,%3}, {%4,%5,%6,%7}, {%8,%9}, {%0,%1,%2,%3};"
                 : "+f"(d[0]), "+f"(d[1]), "+f"(d[2]), "+f"(d[3])
                 : "r"(a[0]), "r"(a[1]), "r"(a[2]), "r"(a[3]),
                   "r"(b[0]), "r"(b[1]));
}
__device__ __forceinline__ void mma_f16(float* d, const uint32_t* a, const uint32_t* b) {
    asm volatile("mma.sync.aligned.m16n8k16.row.col.f32.f16.f16.f32 "
                 "{%0,%1,%2,%3}, {%4,%5,%6,%7}, {%8,%9}, {%0,%1,%2,%3};"
                 : "+f"(d[0]), "+f"(d[1]), "+f"(d[2]), "+f"(d[3])
                 : "r"(a[0]), "r"(a[1]), "r"(a[2]), "r"(a[3]),
                   "r"(b[0]), "r"(b[1]));
}
#define CP_ASYNC16(dst, src) \
    asm volatile("cp.async.cg.shared.global [%0], [%1], 16;" :: "r"(dst), "l"(src))
#define CP_COMMIT()  asm volatile("cp.async.commit_group;" ::: "memory")
#define CP_WAIT0()   asm volatile("cp.async.wait_group 0;" ::: "memory")
#define CP_WAIT1()   asm volatile("cp.async.wait_group 1;" ::: "memory")

__device__ __forceinline__ void split_bf16(float x, unsigned short& h, unsigned short& l) {
    __nv_bfloat16 hb = __float2bfloat16_rn(x);
    float hr = __bfloat162float(hb);
    __nv_bfloat16 lb = __float2bfloat16_rn(x - hr);
    h = *(unsigned short*)&hb;
    l = *(unsigned short*)&lb;
}
__device__ __forceinline__ void split_f16(float x, unsigned short& h, unsigned short& l) {
    __half hb = __float2half_rn(x);
    float hr = __half2float(hb);
    __half lb = __float2half_rn(x - hr);
    h = *(unsigned short*)&hb;
    l = *(unsigned short*)&lb;
}
__device__ __forceinline__ unsigned short f16_hi(float x) {
    __half hb = __float2half_rn(x);
    return *(unsigned short*)&hb;
}
__device__ __forceinline__ void write_a_pat(ushort4* d4, const unsigned short* h,
                                            const unsigned short* l) {
    d4[0] = make_ushort4(h[0], h[0], l[0], h[1]);
    d4[1] = make_ushort4(h[1], l[1], h[2], h[2]);
    d4[2] = make_ushort4(l[2], h[3], h[3], l[3]);
}
__device__ __forceinline__ void write_b_pat(ushort4* d4, const unsigned short* h,
                                            const unsigned short* l) {
    d4[0] = make_ushort4(h[0], l[0], h[0], h[1]);
    d4[1] = make_ushort4(l[1], h[1], h[2], l[2]);
    d4[2] = make_ushort4(h[2], h[3], l[3], h[3]);
}

// ---------------------------------------------------------------------------
// Prep: A-side fp16 split interleave  A'[m][2k+{0,1}] = {hi, lo}
// ---------------------------------------------------------------------------
__global__ __launch_bounds__(256) void interleave_a_kernel(
    const float* __restrict__ src, __half* __restrict__ dst)
{
    int gid = blockIdx.x * 256 + threadIdx.x;
    int m  = gid >> 8;
    int k4 = (gid & 255) * 4;
    float4 v = *(const float4*)(src + (size_t)m*1024 + k4);
    unsigned short h[4], l[4];
    split_f16(v.x, h[0], l[0]);
    split_f16(v.y, h[1], l[1]);
    split_f16(v.z, h[2], l[2]);
    split_f16(v.w, h[3], l[3]);
    ushort4* d4 = (ushort4*)(dst + (size_t)m*KP2 + (size_t)k4*2);
    d4[0] = make_ushort4(h[0], l[0], h[1], l[1]);
    d4[1] = make_ushort4(h[2], l[2], h[3], l[3]);
}

// ---------------------------------------------------------------------------
// Prep: B-side transpose + fp16 replicate.  W[k][n] -> B'[n][2k+{0,1}] = {hi,hi}
// ---------------------------------------------------------------------------
__global__ __launch_bounds__(256) void transpose_w_kernel(
    const float* __restrict__ W, int Ncols, __half* __restrict__ dst)
{
    __shared__ float s[32][33];
    const int tid = threadIdx.x;
    const int tx = tid & 31, ty = tid >> 5;
    const int n0 = blockIdx.x * 32, k0 = blockIdx.y * 32;
    #pragma unroll
    for (int i = 0; i < 4; i++)
        s[tx][ty + 8*i] = W[(size_t)(k0 + ty + 8*i)*Ncols + n0 + tx];
    __syncthreads();
    const int nn = tid >> 3;
    const int kq = (tid & 7) * 4;
    unsigned short h[4];
    #pragma unroll
    for (int t = 0; t < 4; t++)
        h[t] = f16_hi(s[nn][kq + t]);
    ushort4* d4 = (ushort4*)(dst + (size_t)(n0 + nn)*KP2 + (size_t)(k0 + kq)*2);
    d4[0] = make_ushort4(h[0], h[0], h[1], h[1]);
    d4[1] = make_ushort4(h[2], h[2], h[3], h[3]);
}

// ---------------------------------------------------------------------------
// fp16 mma.sync GEMM, 2-stage cp.async pipeline. KP2=2048, 32 K-tiles.
// mode 0: epilogue emits Q'/K'/V' (bf16-3 format, unchanged); mode 1: C + bias.
// ---------------------------------------------------------------------------
#define STAGE_BYTES 36864
#define GEMM_SMEM   73728
#define NKT 32

__global__ __launch_bounds__(256) void mma_gemm_kernel(
    const __half* __restrict__ Ap, const __half* __restrict__ Bp,
    const float* __restrict__ bias, float* __restrict__ C, int mode)
{
    extern __shared__ __align__(16) char smem[];
    const int tid = threadIdx.x;
    const int lane = tid & 31, wid = tid >> 5;
    const int wm = wid >> 2, wn = wid & 3;
    const int m0 = blockIdx.y * 128, n0 = blockIdx.x * 128;
    const uint32_t sb = smem_u32(smem);
    float acc[4][4][4];
    #pragma unroll
    for (int i = 0; i < 4; i++)
        #pragma unroll
        for (int j = 0; j < 4; j++)
            #pragma unroll
            for (int r = 0; r < 4; r++) acc[i][j][r] = 0.f;

    int cr[4], cc[4];
    #pragma unroll
    for (int i = 0; i < 4; i++) {
        int e = tid + 256*i;
        cr[i] = e >> 3;
        cc[i] = (e & 7) * 8;
    }
    const uint32_t a_off = (uint32_t)((wm*64 + (lane & 15))*144 + ((lane >> 4) << 4));
    const int g = lane >> 3, rl = lane & 7;
    const uint32_t b_off = (uint32_t)(18432 + (wn*32 + (g >> 1)*8 + rl)*144 + ((g & 1) << 4));

    {
        #pragma unroll
        for (int i = 0; i < 4; i++) {
            uint32_t da = sb + (uint32_t)(cr[i]*144 + cc[i]*2);
            CP_ASYNC16(da, Ap + (size_t)(m0 + cr[i])*KP2 + cc[i]);
            CP_ASYNC16(da + 18432, Bp + (size_t)(n0 + cr[i])*KP2 + cc[i]);
        }
        CP_COMMIT();
    }

    for (int kt = 0; kt < NKT; kt++) {
        const int s = kt & 1;
        if (kt + 1 < NKT) {
            const int kb = (kt + 1) * 64;
            const uint32_t st = (uint32_t)((s ^ 1) * STAGE_BYTES);
            #pragma unroll
            for (int i = 0; i < 4; i++) {
                uint32_t da = sb + st + (uint32_t)(cr[i]*144 + cc[i]*2);
                CP_ASYNC16(da, Ap + (size_t)(m0 + cr[i])*KP2 + kb + cc[i]);
                CP_ASYNC16(da + 18432, Bp + (size_t)(n0 + cr[i])*KP2 + kb + cc[i]);
            }
            CP_COMMIT();
            CP_WAIT1();
        } else {
            CP_WAIT0();
        }
        __syncthreads();

        const uint32_t sbase = sb + (uint32_t)(s * STAGE_BYTES);
        const uint32_t a_addr = sbase + a_off;
        const uint32_t b_addr = sbase + b_off;
        #pragma unroll
        for (int ks = 0; ks < 4; ks++) {
            uint32_t af[4][4];
            #pragma unroll
            for (int mf = 0; mf < 4; mf++)
                ldsm_x4(af[mf][0], af[mf][1], af[mf][2], af[mf][3],
                        a_addr + mf*16*144 + ks*32);
            uint32_t bf[4][2];
            #pragma unroll
            for (int np = 0; np < 2; np++) {
                uint32_t r0, r1, r2, r3;
                ldsm_x4(r0, r1, r2, r3, b_addr + np*16*144 + ks*32);
                bf[np*2][0] = r0;   bf[np*2][1] = r1;
                bf[np*2+1][0] = r2; bf[np*2+1][1] = r3;
            }
            #pragma unroll
            for (int mf = 0; mf < 4; mf++)
                #pragma unroll
                for (int nf = 0; nf < 4; nf++)
                    mma_f16(acc[mf][nf], af[mf], bf[nf]);
        }
        __syncthreads();
    }

    const int qr = lane >> 2, qc = (lane & 3) * 2;

    if (mode == 1) {
        #pragma unroll
        for (int mf = 0; mf < 4; mf++) {
            #pragma unroll
            for (int nf = 0; nf < 4; nf++) {
                int row = m0 + wm*64 + mf*16 + qr;
                int col = n0 + wn*32 + nf*8 + qc;
                float2 bi = *(const float2*)(bias + col);
                *(float2*)(C + (size_t)row*1024 + col) =
                    make_float2(acc[mf][nf][0] + bi.x, acc[mf][nf][1] + bi.y);
                *(float2*)(C + (size_t)(row + 8)*1024 + col) =
                    make_float2(acc[mf][nf][2] + bi.x, acc[mf][nf][3] + bi.y);
            }
        }
        return;
    }

    // ---- mode 0: stage tile (+bias), emit Q'/K'/V' (bf16-3 attention format) ----
    float* stage = (float*)smem;             // 128 x 132 fp32 = 67584 B
    #pragma unroll
    for (int mf = 0; mf < 4; mf++) {
        #pragma unroll
        for (int nf = 0; nf < 4; nf++) {
            int r = wm*64 + mf*16 + qr;
            int c = wn*32 + nf*8 + qc;
            float2 bi = *(const float2*)(bias + n0 + c);
            stage[(size_t)r*132 + c]     = acc[mf][nf][0] + bi.x;
            stage[(size_t)r*132 + c + 1] = acc[mf][nf][1] + bi.y;
            stage[(size_t)(r+8)*132 + c]     = acc[mf][nf][2] + bi.x;
            stage[(size_t)(r+8)*132 + c + 1] = acc[mf][nf][3] + bi.y;
        }
    }
    __syncthreads();

    #pragma unroll
    for (int ch = 0; ch < 2; ch++) {
        const int gcol0 = n0 + ch*64;
        const int chunk = gcol0 >> 6;        // 0..47
        const int part  = chunk >> 4;        // 0=q, 1=k, 2=v
        const int hd    = chunk & 15;
        if (part < 2) {
            __nv_bfloat16* dst = (part == 0) ? g_qp : g_kp;
            #pragma unroll
            for (int it = 0; it < 8; it++) {
                int task = tid + 256*it;     // 0..2047
                int r = task >> 4, dq = task & 15;
                const float* sp = &stage[(size_t)r*132 + ch*64 + dq*4];
                unsigned short hh[4], ll[4];
                #pragma unroll
                for (int u = 0; u < 4; u++) split_bf16(sp[u], hh[u], ll[u]);
                int m = m0 + r;
                int bb = m >> 9, t = m & 511;
                ushort4* o = (ushort4*)(dst + ((size_t)((bb*NH + hd)*NT + t))*192
                                        + (size_t)dq*12);
                if (part == 0) write_a_pat(o, hh, ll);
                else           write_b_pat(o, hh, ll);
            }
        } else {
            #pragma unroll
            for (int it = 0; it < 8; it++) {
                int task = tid + 256*it;     // 0..2047
                int d = task >> 5, jq = task & 31;
                unsigned short hh[4], ll[4];
                #pragma unroll
                for (int u = 0; u < 4; u++)
                    split_bf16(stage[(size_t)(jq*4 + u)*132 + ch*64 + d],
                               hh[u], ll[u]);
                int m = m0 + jq*4;
                int bb = m >> 9, t = m & 511;
                int bh = bb*NH + hd;
                write_b_pat((ushort4*)(g_vp + ((size_t)(bh*NDK + d))*1536
                                       + (size_t)t*3), hh, ll);
            }
        }
    }
}

// ---------------------------------------------------------------------------
// Tensor-core attention, WINDOWED, bf16-3 internals (unchanged from R14).
// ctx epilogue now emits fp16-2 A-pattern into g_cp.
// ---------------------------------------------------------------------------
#define SROW 324
#define QROWB 400
#define OFF_BIAS 82944
#define OFF_BUF1 87040
#define OFF_BUF2 112640
#define KV_STAGE 25600
#define ATTN_SMEM 163840

__global__ __launch_bounds__(256) void attn_tc_kernel(
    const float* __restrict__ rel_table, float* __restrict__ attn)
{
    extern __shared__ __align__(16) char smem[];
    float* S = (float*)smem;
    float* sbias = (float*)(smem + OFF_BIAS);
    const uint32_t sb = smem_u32(smem);
    const int tid = threadIdx.x;
    const int lane = tid & 31, wid = tid >> 5;
    const int wm = wid >> 1, wn = wid & 1;
    const int bh = blockIdx.y;
    const int b = bh >> 4, h = bh & 15;
    const int q0 = blockIdx.x * 64;
    const int js = max(0, q0 - 128);
    const int je = min(NT, q0 + 64 + 128);
    const int jb_lo = js >> 6;
    const int nblk = (je - js) >> 6;

    for (int i = tid; i < 1023; i += 256)
        sbias[i] = rel_table[(size_t)i*NH + h];

    {
        const __nv_bfloat16* qsrc = g_qp + (size_t)(bh*NT + q0)*192;
        for (int i = tid; i < 1536; i += 256) {
            int r = i / 24, c = i % 24;
            *(uint4*)(smem + OFF_BUF1 + r*QROWB + c*16) =
                *(const uint4*)((const char*)(qsrc + (size_t)r*192) + c*16);
        }
    }

    const uint32_t a_off = (uint32_t)((wm*16 + (lane & 15))*QROWB + ((lane >> 4) << 4));
    const int g = lane >> 3, rl = lane & 7;
    const uint32_t b_off = (uint32_t)((wn*32 + (g >> 1)*8 + rl)*QROWB + ((g & 1) << 4));
    const int qr = lane >> 2, qc = (lane & 3) * 2;
    const int rl0 = wm*16 + qr;

    {
        const __nv_bfloat16* ksrc = g_kp + (size_t)(bh*NT + jb_lo*64)*192;
        for (int i = tid; i < 1536; i += 256) {
            int r = i / 24, c = i % 24;
            CP_ASYNC16(sb + OFF_BUF2 + (uint32_t)(r*QROWB + c*16),
                       (const char*)(ksrc + (size_t)r*192) + c*16);
        }
        CP_COMMIT();
    }

    for (int ib = 0; ib < nblk; ib++) {
        CP_WAIT0();
        __syncthreads();
        if (ib + 1 < nblk) {
            const __nv_bfloat16* ksrc = g_kp + (size_t)(bh*NT + (jb_lo + ib + 1)*64)*192;
            const uint32_t st = (uint32_t)(((ib + 1) & 1) * KV_STAGE);
            for (int i = tid; i < 1536; i += 256) {
                int r = i / 24, c = i % 24;
                CP_ASYNC16(sb + OFF_BUF2 + st + (uint32_t)(r*QROWB + c*16),
                           (const char*)(ksrc + (size_t)r*192) + c*16);
            }
            CP_COMMIT();
        }

        float acc[4][4];
        #pragma unroll
        for (int nf = 0; nf < 4; nf++)
            #pragma unroll
            for (int r = 0; r < 4; r++) acc[nf][r] = 0.f;

        const uint32_t kbase = sb + OFF_BUF2 + (uint32_t)((ib & 1) * KV_STAGE);
        #pragma unroll
        for (int ks = 0; ks < 12; ks++) {
            uint32_t af[4];
            ldsm_x4(af[0], af[1], af[2], af[3], sb + OFF_BUF1 + a_off + ks*32);
            uint32_t bf[4][2];
            #pragma unroll
            for (int np = 0; np < 2; np++) {
                uint32_t r0, r1, r2, r3;
                ldsm_x4(r0, r1, r2, r3, kbase + b_off + np*16*QROWB + ks*32);
                bf[np*2][0] = r0;   bf[np*2][1] = r1;
                bf[np*2+1][0] = r2; bf[np*2+1][1] = r3;
            }
            #pragma unroll
            for (int nf = 0; nf < 4; nf++)
                mma_bf16(acc[nf], af, bf[nf]);
        }

        #pragma unroll
        for (int nf = 0; nf < 4; nf++) {
            int cl = ib*64 + wn*32 + nf*8 + qc;
            int j  = js + cl;
            int qiA = q0 + rl0, qiB = qiA + 8;
            S[rl0*SROW + cl]     = acc[nf][0]*0.125f + sbias[j - qiA + 511];
            S[rl0*SROW + cl + 1] = acc[nf][1]*0.125f + sbias[j + 1 - qiA + 511];
            S[(rl0+8)*SROW + cl]     = acc[nf][2]*0.125f + sbias[j - qiB + 511];
            S[(rl0+8)*SROW + cl + 1] = acc[nf][3]*0.125f + sbias[j + 1 - qiB + 511];
        }
    }
    __syncthreads();

    #pragma unroll
    for (int rr = 0; rr < 8; rr++) {
        int r = wid*8 + rr;
        int qi = q0 + r;
        int jlo = max(0, qi - 128), jhi = min(NT - 1, qi + 128);
        float mx = -1e30f;
        for (int j = jlo + lane; j <= jhi; j += 32)
            mx = fmaxf(mx, S[r*SROW + j - js]);
        #pragma unroll
        for (int o = 16; o > 0; o >>= 1)
            mx = fmaxf(mx, __shfl_xor_sync(0xffffffffu, mx, o));
        float sum = 0.f;
        for (int j = jlo + lane; j <= jhi; j += 32) {
            float e = __expf(S[r*SROW + j - js] - mx);
            S[r*SROW + j - js] = e;
            sum += e;
        }
        #pragma unroll
        for (int o = 16; o > 0; o >>= 1)
            sum += __shfl_xor_sync(0xffffffffu, sum, o);
        float inv = 1.f / sum;
        float* arow = attn + ((size_t)bh*NT + qi)*NT;
        for (int j = lane; j < NT; j += 32) {
            float v = 0.f;
            if (j >= jlo && j <= jhi) {
                v = S[r*SROW + j - js]*inv;
                S[r*SROW + j - js] = v;
            } else if (j >= js && j < je) {
                S[r*SROW + j - js] = 0.f;
            }
            arow[j] = v;
        }
    }
    __syncthreads();

    float cacc[4][4];
    #pragma unroll
    for (int nf = 0; nf < 4; nf++)
        #pragma unroll
        for (int r = 0; r < 4; r++) cacc[nf][r] = 0.f;

    {
        const __nv_bfloat16* vsrc = g_vp + (size_t)(bh*NDK)*1536 + (size_t)jb_lo*192;
        for (int i = tid; i < 1536; i += 256) {
            int r = i / 24, c = i % 24;
            CP_ASYNC16(sb + OFF_BUF2 + (uint32_t)(r*QROWB + c*16),
                       (const char*)(vsrc + (size_t)r*1536) + c*16);
        }
        CP_COMMIT();
    }

    for (int ib = 0; ib < nblk; ib++) {
        CP_WAIT0();
        if (ib + 1 < nblk) {
            const __nv_bfloat16* vsrc = g_vp + (size_t)(bh*NDK)*1536
                                        + (size_t)(jb_lo + ib + 1)*192;
            const uint32_t st = (uint32_t)(((ib + 1) & 1) * KV_STAGE);
            for (int i = tid; i < 1536; i += 256) {
                int r = i / 24, c = i % 24;
                CP_ASYNC16(sb + OFF_BUF2 + st + (uint32_t)(r*QROWB + c*16),
                           (const char*)(vsrc + (size_t)r*1536) + c*16);
            }
            CP_COMMIT();
        }
        #pragma unroll
        for (int i = 0; i < 4; i++) {
            int e = tid + 256*i;
            int q = e >> 4, j4 = e & 15;
            const float* sp = &S[q*SROW + ib*64 + j4*4];
            unsigned short hh[4], ll[4];
            #pragma unroll
            for (int u = 0; u < 4; u++) split_bf16(sp[u], hh[u], ll[u]);
            write_a_pat((ushort4*)(smem + OFF_BUF1 + q*QROWB + j4*24), hh, ll);
        }
        __syncthreads();

        const uint32_t vbase = sb + OFF_BUF2 + (uint32_t)((ib & 1) * KV_STAGE);
        #pragma unroll
        for (int ks = 0; ks < 12; ks++) {
            uint32_t af[4];
            ldsm_x4(af[0], af[1], af[2], af[3], sb + OFF_BUF1 + a_off + ks*32);
            uint32_t bf[4][2];
            #pragma unroll
            for (int np = 0; np < 2; np++) {
                uint32_t r0, r1, r2, r3;
                ldsm_x4(r0, r1, r2, r3, vbase + b_off + np*16*QROWB + ks*32);
                bf[np*2][0] = r0;   bf[np*2][1] = r1;
                bf[np*2+1][0] = r2; bf[np*2+1][1] = r3;
            }
            #pragma unroll
            for (int nf = 0; nf < 4; nf++)
                mma_bf16(cacc[nf], af, bf[nf]);
        }
        __syncthreads();
    }

    #pragma unroll
    for (int nf = 0; nf < 4; nf++) {
        int cl = wn*32 + nf*8 + qc;
        S[rl0*SROW + cl]     = cacc[nf][0];
        S[rl0*SROW + cl + 1] = cacc[nf][1];
        S[(rl0+8)*SROW + cl]     = cacc[nf][2];
        S[(rl0+8)*SROW + cl + 1] = cacc[nf][3];
    }
    __syncthreads();

    // write ctx as fp16-2 split A-pattern into g_cp
    #pragma unroll
    for (int i = 0; i < 4; i++) {
        int e = tid + 256*i;
        int q = e >> 4, dv = e & 15;
        const float* sp = &S[q*SROW + dv*4];
        unsigned short hh[4], ll[4];
        #pragma unroll
        for (int u = 0; u < 4; u++) split_f16(sp[u], hh[u], ll[u]);
        size_t m = (size_t)b*NT + q0 + q;
        ushort4* o = (ushort4*)(g_cp + m*KP2 + (size_t)(h*NDK + dv*4)*2);
        o[0] = make_ushort4(hh[0], ll[0], hh[1], ll[1]);
        o[1] = make_ushort4(hh[2], ll[2], hh[3], ll[3]);
    }
}

// ---------------------------------------------------------------------------
extern "C" void kernel_launch(void* const* d_in, const int* in_sizes, int n_in,
                              void* d_out, int out_size)
{
    const float* x     = (const float*)d_in[0];
    const float* Wqkv  = (const float*)d_in[1];
    const float* bqkv  = (const float*)d_in[2];
    const float* Wo    = (const float*)d_in[3];
    const float* bo    = (const float*)d_in[4];
    const float* rel   = (const float*)d_in[5];

    float* out = (float*)d_out;
    float* attn;
    if ((size_t)out_size >= OUT_ELEMS + ATTN_ELEMS) {
        attn = out + OUT_ELEMS;
    } else {
        cudaGetSymbolAddress((void**)&attn, g_attn_fallback);
    }

    __half *ap, *bq, *bo2, *cp;
    cudaGetSymbolAddress((void**)&ap,  g_ap);
    cudaGetSymbolAddress((void**)&bq,  g_bq);
    cudaGetSymbolAddress((void**)&bo2, g_bo2);
    cudaGetSymbolAddress((void**)&cp,  g_cp);

    cudaFuncSetAttribute(mma_gemm_kernel,
                         cudaFuncAttributeMaxDynamicSharedMemorySize, GEMM_SMEM);
    cudaFuncSetAttribute(attn_tc_kernel,
                         cudaFuncAttributeMaxDynamicSharedMemorySize, ATTN_SMEM);

    // prep inputs
    interleave_a_kernel<<<8192, 256>>>(x, ap);
    transpose_w_kernel<<<dim3(96, 32), 256>>>(Wqkv, 3072, bq);
    transpose_w_kernel<<<dim3(32, 32), 256>>>(Wo, 1024, bo2);

    // QKV projection (epilogue emits Q'/K'/V' bf16-3 directly)
    mma_gemm_kernel<<<dim3(24, 64), 256, GEMM_SMEM>>>(ap, bq, bqkv, nullptr, 0);

    // tensor-core attention (writes attn + fp16-2 ctx)
    attn_tc_kernel<<<dim3(8, 256), 256, ATTN_SMEM>>>(rel, attn);

    // out projection
    mma_gemm_kernel<<<dim3(8, 64), 256, GEMM_SMEM>>>(cp, bo2, bo, out, 1);
}

// round 16
// speedup vs baseline: 3.1703x; 1.0379x over previous
#include <cuda_runtime.h>
#include <cuda_bf16.h>
#include <cuda_fp16.h>
#include <math.h>
#include <stdint.h>

#define NB 16
#define NT 512
#define ND 1024
#define NH 16
#define NDK 64
#define KP2 2048   // expanded K for GEMMs (2x fp16 split terms)

#define OUT_ELEMS  ((size_t)NB*NT*ND)             // 8,388,608
#define ATTN_ELEMS ((size_t)NB*NH*NT*NT)          // 67,108,864

// ---------------------------------------------------------------------------
// Scratch (device globals: allocation-free per harness rules)
// ---------------------------------------------------------------------------
__device__ float g_attn_fallback[NB*NH*NT*NT];

__device__ __align__(16) __half g_ap[8192ull*KP2];    // x  split/interleaved (fp16 A-pat)
__device__ __align__(16) __half g_bq[3072ull*KP2];    // Wqkv^T replicated (fp16 B-pat)
__device__ __align__(16) __half g_bo2[1024ull*KP2];   // Wo^T replicated
__device__ __align__(16) __half g_cp[8192ull*KP2];    // ctx split/interleaved
__device__ __align__(16) __nv_bfloat16 g_qp[(size_t)NB*NH*NT*192];  // Q' A-side (bf16-3)
__device__ __align__(16) __nv_bfloat16 g_kp[(size_t)NB*NH*NT*192];  // K' B-side
__device__ __align__(16) __nv_bfloat16 g_vp[(size_t)NB*NH*NDK*1536]; // V'^T B-side

// ---------------------------------------------------------------------------
// helpers
// ---------------------------------------------------------------------------
__device__ __forceinline__ uint32_t smem_u32(const void* p) {
    uint32_t a;
    asm("{ .reg .u64 t; cvta.to.shared.u64 t, %1; cvt.u32.u64 %0, t; }"
        : "=r"(a) : "l"(p));
    return a;
}
__device__ __forceinline__ void ldsm_x4(uint32_t& r0, uint32_t& r1,
                                        uint32_t& r2, uint32_t& r3, uint32_t addr) {
    asm volatile("ldmatrix.sync.aligned.m8n8.x4.shared.b16 {%0,%1,%2,%3}, [%4];"
                 : "=r"(r0), "=r"(r1), "=r"(r2), "=r"(r3) : "r"(addr));
}
__device__ __forceinline__ void mma_bf16(float* d, const uint32_t* a, const uint32_t* b) {
    asm volatile("mma.sync.aligned.m16n8k16.row.col.f32.bf16.bf16.f32 "
                 "{%0,%1,%2,%3}, {%4,%5,%6,%7}, {%8,%9}, {%0,%1,%2,%3};"
                 : "+f"(d[0]), "+f"(d[1]), "+f"(d[2]), "+f"(d[3])
                 : "r"(a[0]), "r"(a[1]), "r"(a[2]), "r"(a[3]),
                   "r"(b[0]), "r"(b[1]));
}
__device__ __forceinline__ void mma_f16(float* d, const uint32_t* a, const uint32_t* b) {
    asm volatile("mma.sync.aligned.m16n8k16.row.col.f32.f16.f16.f32 "
                 "{%0,%1,%2,%3}, {%4,%5,%6,%7}, {%8,%9}, {%0,%1,%2,%3};"
                 : "+f"(d[0]), "+f"(d[1]), "+f"(d[2]), "+f"(d[3])
                 : "r"(a[0]), "r"(a[1]), "r"(a[2]), "r"(a[3]),
                   "r"(b[0]), "r"(b[1]));
}
#define CP_ASYNC16(dst, src) \
    asm volatile("cp.async.cg.shared.global [%0], [%1], 16;" :: "r"(dst), "l"(src))
#define CP_COMMIT()  asm volatile("cp.async.commit_group;" ::: "memory")
#define CP_WAIT0()   asm volatile("cp.async.wait_group 0;" ::: "memory")
#define CP_WAIT1()   asm volatile("cp.async.wait_group 1;" ::: "memory")
// streaming store: 268MB attn must not wash L2
#define STG_CS4(ptr, v) \
    asm volatile("st.global.cs.v4.f32 [%0], {%1,%2,%3,%4};" \
                 :: "l"(ptr), "f"((v).x), "f"((v).y), "f"((v).z), "f"((v).w) : "memory")

__device__ __forceinline__ void split_bf16(float x, unsigned short& h, unsigned short& l) {
    __nv_bfloat16 hb = __float2bfloat16_rn(x);
    float hr = __bfloat162float(hb);
    __nv_bfloat16 lb = __float2bfloat16_rn(x - hr);
    h = *(unsigned short*)&hb;
    l = *(unsigned short*)&lb;
}
__device__ __forceinline__ void split_f16(float x, unsigned short& h, unsigned short& l) {
    __half hb = __float2half_rn(x);
    float hr = __half2float(hb);
    __half lb = __float2half_rn(x - hr);
    h = *(unsigned short*)&hb;
    l = *(unsigned short*)&lb;
}
__device__ __forceinline__ unsigned short f16_hi(float x) {
    __half hb = __float2half_rn(x);
    return *(unsigned short*)&hb;
}
__device__ __forceinline__ void write_a_pat(ushort4* d4, const unsigned short* h,
                                            const unsigned short* l) {
    d4[0] = make_ushort4(h[0], h[0], l[0], h[1]);
    d4[1] = make_ushort4(h[1], l[1], h[2], h[2]);
    d4[2] = make_ushort4(l[2], h[3], h[3], l[3]);
}
__device__ __forceinline__ void write_b_pat(ushort4* d4, const unsigned short* h,
                                            const unsigned short* l) {
    d4[0] = make_ushort4(h[0], l[0], h[0], h[1]);
    d4[1] = make_ushort4(l[1], h[1], h[2], l[2]);
    d4[2] = make_ushort4(h[2], h[3], l[3], h[3]);
}

// ---------------------------------------------------------------------------
// Prep: A-side fp16 split interleave  A'[m][2k+{0,1}] = {hi, lo}
// ---------------------------------------------------------------------------
__global__ __launch_bounds__(256) void interleave_a_kernel(
    const float* __restrict__ src, __half* __restrict__ dst)
{
    int gid = blockIdx.x * 256 + threadIdx.x;
    int m  = gid >> 8;
    int k4 = (gid & 255) * 4;
    float4 v = *(const float4*)(src + (size_t)m*1024 + k4);
    unsigned short h[4], l[4];
    split_f16(v.x, h[0], l[0]);
    split_f16(v.y, h[1], l[1]);
    split_f16(v.z, h[2], l[2]);
    split_f16(v.w, h[3], l[3]);
    ushort4* d4 = (ushort4*)(dst + (size_t)m*KP2 + (size_t)k4*2);
    d4[0] = make_ushort4(h[0], l[0], h[1], l[1]);
    d4[1] = make_ushort4(h[2], l[2], h[3], l[3]);
}

// ---------------------------------------------------------------------------
// Prep: B-side transpose + fp16 replicate.  W[k][n] -> B'[n][2k+{0,1}] = {hi,hi}
// ---------------------------------------------------------------------------
__global__ __launch_bounds__(256) void transpose_w_kernel(
    const float* __restrict__ W, int Ncols, __half* __restrict__ dst)
{
    __shared__ float s[32][33];
    const int tid = threadIdx.x;
    const int tx = tid & 31, ty = tid >> 5;
    const int n0 = blockIdx.x * 32, k0 = blockIdx.y * 32;
    #pragma unroll
    for (int i = 0; i < 4; i++)
        s[tx][ty + 8*i] = W[(size_t)(k0 + ty + 8*i)*Ncols + n0 + tx];
    __syncthreads();
    const int nn = tid >> 3;
    const int kq = (tid & 7) * 4;
    unsigned short h[4];
    #pragma unroll
    for (int t = 0; t < 4; t++)
        h[t] = f16_hi(s[nn][kq + t]);
    ushort4* d4 = (ushort4*)(dst + (size_t)(n0 + nn)*KP2 + (size_t)(k0 + kq)*2);
    d4[0] = make_ushort4(h[0], h[0], h[1], h[1]);
    d4[1] = make_ushort4(h[2], h[2], h[3], h[3]);
}

// ---------------------------------------------------------------------------
// fp16 mma.sync GEMM, 2-stage cp.async pipeline. KP2=2048, 32 K-tiles.
// mode 0: epilogue emits Q'/K'/V' (bf16-3 format); mode 1: C + bias.
// ---------------------------------------------------------------------------
#define STAGE_BYTES 36864
#define GEMM_SMEM   73728
#define NKT 32

__global__ __launch_bounds__(256) void mma_gemm_kernel(
    const __half* __restrict__ Ap, const __half* __restrict__ Bp,
    const float* __restrict__ bias, float* __restrict__ C, int mode)
{
    extern __shared__ __align__(16) char smem[];
    const int tid = threadIdx.x;
    const int lane = tid & 31, wid = tid >> 5;
    const int wm = wid >> 2, wn = wid & 3;
    const int m0 = blockIdx.y * 128, n0 = blockIdx.x * 128;
    const uint32_t sb = smem_u32(smem);
    float acc[4][4][4];
    #pragma unroll
    for (int i = 0; i < 4; i++)
        #pragma unroll
        for (int j = 0; j < 4; j++)
            #pragma unroll
            for (int r = 0; r < 4; r++) acc[i][j][r] = 0.f;

    int cr[4], cc[4];
    #pragma unroll
    for (int i = 0; i < 4; i++) {
        int e = tid + 256*i;
        cr[i] = e >> 3;
        cc[i] = (e & 7) * 8;
    }
    const uint32_t a_off = (uint32_t)((wm*64 + (lane & 15))*144 + ((lane >> 4) << 4));
    const int g = lane >> 3, rl = lane & 7;
    const uint32_t b_off = (uint32_t)(18432 + (wn*32 + (g >> 1)*8 + rl)*144 + ((g & 1) << 4));

    {
        #pragma unroll
        for (int i = 0; i < 4; i++) {
            uint32_t da = sb + (uint32_t)(cr[i]*144 + cc[i]*2);
            CP_ASYNC16(da, Ap + (size_t)(m0 + cr[i])*KP2 + cc[i]);
            CP_ASYNC16(da + 18432, Bp + (size_t)(n0 + cr[i])*KP2 + cc[i]);
        }
        CP_COMMIT();
    }

    for (int kt = 0; kt < NKT; kt++) {
        const int s = kt & 1;
        if (kt + 1 < NKT) {
            const int kb = (kt + 1) * 64;
            const uint32_t st = (uint32_t)((s ^ 1) * STAGE_BYTES);
            #pragma unroll
            for (int i = 0; i < 4; i++) {
                uint32_t da = sb + st + (uint32_t)(cr[i]*144 + cc[i]*2);
                CP_ASYNC16(da, Ap + (size_t)(m0 + cr[i])*KP2 + kb + cc[i]);
                CP_ASYNC16(da + 18432, Bp + (size_t)(n0 + cr[i])*KP2 + kb + cc[i]);
            }
            CP_COMMIT();
            CP_WAIT1();
        } else {
            CP_WAIT0();
        }
        __syncthreads();

        const uint32_t sbase = sb + (uint32_t)(s * STAGE_BYTES);
        const uint32_t a_addr = sbase + a_off;
        const uint32_t b_addr = sbase + b_off;
        #pragma unroll
        for (int ks = 0; ks < 4; ks++) {
            uint32_t af[4][4];
            #pragma unroll
            for (int mf = 0; mf < 4; mf++)
                ldsm_x4(af[mf][0], af[mf][1], af[mf][2], af[mf][3],
                        a_addr + mf*16*144 + ks*32);
            uint32_t bf[4][2];
            #pragma unroll
            for (int np = 0; np < 2; np++) {
                uint32_t r0, r1, r2, r3;
                ldsm_x4(r0, r1, r2, r3, b_addr + np*16*144 + ks*32);
                bf[np*2][0] = r0;   bf[np*2][1] = r1;
                bf[np*2+1][0] = r2; bf[np*2+1][1] = r3;
            }
            #pragma unroll
            for (int mf = 0; mf < 4; mf++)
                #pragma unroll
                for (int nf = 0; nf < 4; nf++)
                    mma_f16(acc[mf][nf], af[mf], bf[nf]);
        }
        __syncthreads();
    }

    const int qr = lane >> 2, qc = (lane & 3) * 2;

    if (mode == 1) {
        #pragma unroll
        for (int mf = 0; mf < 4; mf++) {
            #pragma unroll
            for (int nf = 0; nf < 4; nf++) {
                int row = m0 + wm*64 + mf*16 + qr;
                int col = n0 + wn*32 + nf*8 + qc;
                float2 bi = *(const float2*)(bias + col);
                *(float2*)(C + (size_t)row*1024 + col) =
                    make_float2(acc[mf][nf][0] + bi.x, acc[mf][nf][1] + bi.y);
                *(float2*)(C + (size_t)(row + 8)*1024 + col) =
                    make_float2(acc[mf][nf][2] + bi.x, acc[mf][nf][3] + bi.y);
            }
        }
        return;
    }

    // ---- mode 0: stage tile (+bias), emit Q'/K'/V' (bf16-3 attention format) ----
    float* stage = (float*)smem;             // 128 x 132 fp32 = 67584 B
    #pragma unroll
    for (int mf = 0; mf < 4; mf++) {
        #pragma unroll
        for (int nf = 0; nf < 4; nf++) {
            int r = wm*64 + mf*16 + qr;
            int c = wn*32 + nf*8 + qc;
            float2 bi = *(const float2*)(bias + n0 + c);
            stage[(size_t)r*132 + c]     = acc[mf][nf][0] + bi.x;
            stage[(size_t)r*132 + c + 1] = acc[mf][nf][1] + bi.y;
            stage[(size_t)(r+8)*132 + c]     = acc[mf][nf][2] + bi.x;
            stage[(size_t)(r+8)*132 + c + 1] = acc[mf][nf][3] + bi.y;
        }
    }
    __syncthreads();

    #pragma unroll
    for (int ch = 0; ch < 2; ch++) {
        const int gcol0 = n0 + ch*64;
        const int chunk = gcol0 >> 6;        // 0..47
        const int part  = chunk >> 4;        // 0=q, 1=k, 2=v
        const int hd    = chunk & 15;
        if (part < 2) {
            __nv_bfloat16* dst = (part == 0) ? g_qp : g_kp;
            #pragma unroll
            for (int it = 0; it < 8; it++) {
                int task = tid + 256*it;     // 0..2047
                int r = task >> 4, dq = task & 15;
                const float* sp = &stage[(size_t)r*132 + ch*64 + dq*4];
                unsigned short hh[4], ll[4];
                #pragma unroll
                for (int u = 0; u < 4; u++) split_bf16(sp[u], hh[u], ll[u]);
                int m = m0 + r;
                int bb = m >> 9, t = m & 511;
                ushort4* o = (ushort4*)(dst + ((size_t)((bb*NH + hd)*NT + t))*192
                                        + (size_t)dq*12);
                if (part == 0) write_a_pat(o, hh, ll);
                else           write_b_pat(o, hh, ll);
            }
        } else {
            #pragma unroll
            for (int it = 0; it < 8; it++) {
                int task = tid + 256*it;     // 0..2047
                int d = task >> 5, jq = task & 31;
                unsigned short hh[4], ll[4];
                #pragma unroll
                for (int u = 0; u < 4; u++)
                    split_bf16(stage[(size_t)(jq*4 + u)*132 + ch*64 + d],
                               hh[u], ll[u]);
                int m = m0 + jq*4;
                int bb = m >> 9, t = m & 511;
                int bh = bb*NH + hd;
                write_b_pat((ushort4*)(g_vp + ((size_t)(bh*NDK + d))*1536
                                       + (size_t)t*3), hh, ll);
            }
        }
    }
}

// ---------------------------------------------------------------------------
// Tensor-core attention, WINDOWED, bf16-3 internals.
// R16: attn rows written as float4 streaming stores (st.global.cs).
// ---------------------------------------------------------------------------
#define SROW 324
#define QROWB 400
#define OFF_BIAS 82944
#define OFF_BUF1 87040
#define OFF_BUF2 112640
#define KV_STAGE 25600
#define ATTN_SMEM 163840

__global__ __launch_bounds__(256) void attn_tc_kernel(
    const float* __restrict__ rel_table, float* __restrict__ attn)
{
    extern __shared__ __align__(16) char smem[];
    float* S = (float*)smem;
    float* sbias = (float*)(smem + OFF_BIAS);
    const uint32_t sb = smem_u32(smem);
    const int tid = threadIdx.x;
    const int lane = tid & 31, wid = tid >> 5;
    const int wm = wid >> 1, wn = wid & 1;
    const int bh = blockIdx.y;
    const int b = bh >> 4, h = bh & 15;
    const int q0 = blockIdx.x * 64;
    const int js = max(0, q0 - 128);
    const int je = min(NT, q0 + 64 + 128);
    const int jb_lo = js >> 6;
    const int nblk = (je - js) >> 6;

    for (int i = tid; i < 1023; i += 256)
        sbias[i] = rel_table[(size_t)i*NH + h];

    {
        const __nv_bfloat16* qsrc = g_qp + (size_t)(bh*NT + q0)*192;
        for (int i = tid; i < 1536; i += 256) {
            int r = i / 24, c = i % 24;
            *(uint4*)(smem + OFF_BUF1 + r*QROWB + c*16) =
                *(const uint4*)((const char*)(qsrc + (size_t)r*192) + c*16);
        }
    }

    const uint32_t a_off = (uint32_t)((wm*16 + (lane & 15))*QROWB + ((lane >> 4) << 4));
    const int g = lane >> 3, rl = lane & 7;
    const uint32_t b_off = (uint32_t)((wn*32 + (g >> 1)*8 + rl)*QROWB + ((g & 1) << 4));
    const int qr = lane >> 2, qc = (lane & 3) * 2;
    const int rl0 = wm*16 + qr;

    {
        const __nv_bfloat16* ksrc = g_kp + (size_t)(bh*NT + jb_lo*64)*192;
        for (int i = tid; i < 1536; i += 256) {
            int r = i / 24, c = i % 24;
            CP_ASYNC16(sb + OFF_BUF2 + (uint32_t)(r*QROWB + c*16),
                       (const char*)(ksrc + (size_t)r*192) + c*16);
        }
        CP_COMMIT();
    }

    for (int ib = 0; ib < nblk; ib++) {
        CP_WAIT0();
        __syncthreads();
        if (ib + 1 < nblk) {
            const __nv_bfloat16* ksrc = g_kp + (size_t)(bh*NT + (jb_lo + ib + 1)*64)*192;
            const uint32_t st = (uint32_t)(((ib + 1) & 1) * KV_STAGE);
            for (int i = tid; i < 1536; i += 256) {
                int r = i / 24, c = i % 24;
                CP_ASYNC16(sb + OFF_BUF2 + st + (uint32_t)(r*QROWB + c*16),
                           (const char*)(ksrc + (size_t)r*192) + c*16);
            }
            CP_COMMIT();
        }

        float acc[4][4];
        #pragma unroll
        for (int nf = 0; nf < 4; nf++)
            #pragma unroll
            for (int r = 0; r < 4; r++) acc[nf][r] = 0.f;

        const uint32_t kbase = sb + OFF_BUF2 + (uint32_t)((ib & 1) * KV_STAGE);
        #pragma unroll
        for (int ks = 0; ks < 12; ks++) {
            uint32_t af[4];
            ldsm_x4(af[0], af[1], af[2], af[3], sb + OFF_BUF1 + a_off + ks*32);
            uint32_t bf[4][2];
            #pragma unroll
            for (int np = 0; np < 2; np++) {
                uint32_t r0, r1, r2, r3;
                ldsm_x4(r0, r1, r2, r3, kbase + b_off + np*16*QROWB + ks*32);
                bf[np*2][0] = r0;   bf[np*2][1] = r1;
                bf[np*2+1][0] = r2; bf[np*2+1][1] = r3;
            }
            #pragma unroll
            for (int nf = 0; nf < 4; nf++)
                mma_bf16(acc[nf], af, bf[nf]);
        }

        #pragma unroll
        for (int nf = 0; nf < 4; nf++) {
            int cl = ib*64 + wn*32 + nf*8 + qc;
            int j  = js + cl;
            int qiA = q0 + rl0, qiB = qiA + 8;
            S[rl0*SROW + cl]     = acc[nf][0]*0.125f + sbias[j - qiA + 511];
            S[rl0*SROW + cl + 1] = acc[nf][1]*0.125f + sbias[j + 1 - qiA + 511];
            S[(rl0+8)*SROW + cl]     = acc[nf][2]*0.125f + sbias[j - qiB + 511];
            S[(rl0+8)*SROW + cl + 1] = acc[nf][3]*0.125f + sbias[j + 1 - qiB + 511];
        }
    }
    __syncthreads();

    // ---- softmax + attn write (float4 streaming stores) ----
    const int span = je - js;
    #pragma unroll
    for (int rr = 0; rr < 8; rr++) {
        int r = wid*8 + rr;
        int qi = q0 + r;
        int jlo = max(0, qi - 128), jhi = min(NT - 1, qi + 128);
        float mx = -1e30f;
        for (int j = jlo + lane; j <= jhi; j += 32)
            mx = fmaxf(mx, S[r*SROW + j - js]);
        #pragma unroll
        for (int o = 16; o > 0; o >>= 1)
            mx = fmaxf(mx, __shfl_xor_sync(0xffffffffu, mx, o));
        float sum = 0.f;
        for (int j = jlo + lane; j <= jhi; j += 32) {
            float e = __expf(S[r*SROW + j - js] - mx);
            S[r*SROW + j - js] = e;
            sum += e;
        }
        #pragma unroll
        for (int o = 16; o > 0; o >>= 1)
            sum += __shfl_xor_sync(0xffffffffu, sum, o);
        float inv = 1.f / sum;
        // normalize in place; zero masked in-window entries (needed for PV)
        for (int idx = lane; idx < span; idx += 32) {
            int j = js + idx;
            float v = (j >= jlo && j <= jhi) ? S[r*SROW + idx]*inv : 0.f;
            S[r*SROW + idx] = v;
        }
        __syncwarp();
        // full attn row: 128 float4 streaming stores (S zero outside row window)
        float* arow = attn + ((size_t)bh*NT + qi)*NT;
        for (int j4 = lane; j4 < 128; j4 += 32) {
            int j = j4*4;
            float4 o;
            o.x = (j   >= js && j   < je) ? S[r*SROW + j   - js] : 0.f;
            o.y = (j+1 >= js && j+1 < je) ? S[r*SROW + j+1 - js] : 0.f;
            o.z = (j+2 >= js && j+2 < je) ? S[r*SROW + j+2 - js] : 0.f;
            o.w = (j+3 >= js && j+3 < je) ? S[r*SROW + j+3 - js] : 0.f;
            STG_CS4(arow + j, o);
        }
    }
    __syncthreads();

    float cacc[4][4];
    #pragma unroll
    for (int nf = 0; nf < 4; nf++)
        #pragma unroll
        for (int r = 0; r < 4; r++) cacc[nf][r] = 0.f;

    {
        const __nv_bfloat16* vsrc = g_vp + (size_t)(bh*NDK)*1536 + (size_t)jb_lo*192;
        for (int i = tid; i < 1536; i += 256) {
            int r = i / 24, c = i % 24;
            CP_ASYNC16(sb + OFF_BUF2 + (uint32_t)(r*QROWB + c*16),
                       (const char*)(vsrc + (size_t)r*1536) + c*16);
        }
        CP_COMMIT();
    }

    for (int ib = 0; ib < nblk; ib++) {
        CP_WAIT0();
        if (ib + 1 < nblk) {
            const __nv_bfloat16* vsrc = g_vp + (size_t)(bh*NDK)*1536
                                        + (size_t)(jb_lo + ib + 1)*192;
            const uint32_t st = (uint32_t)(((ib + 1) & 1) * KV_STAGE);
            for (int i = tid; i < 1536; i += 256) {
                int r = i / 24, c = i % 24;
                CP_ASYNC16(sb + OFF_BUF2 + st + (uint32_t)(r*QROWB + c*16),
                           (const char*)(vsrc + (size_t)r*1536) + c*16);
            }
            CP_COMMIT();
        }
        #pragma unroll
        for (int i = 0; i < 4; i++) {
            int e = tid + 256*i;
            int q = e >> 4, j4 = e & 15;
            const float* sp = &S[q*SROW + ib*64 + j4*4];
            unsigned short hh[4], ll[4];
            #pragma unroll
            for (int u = 0; u < 4; u++) split_bf16(sp[u], hh[u], ll[u]);
            write_a_pat((ushort4*)(smem + OFF_BUF1 + q*QROWB + j4*24), hh, ll);
        }
        __syncthreads();

        const uint32_t vbase = sb + OFF_BUF2 + (uint32_t)((ib & 1) * KV_STAGE);
        #pragma unroll
        for (int ks = 0; ks < 12; ks++) {
            uint32_t af[4];
            ldsm_x4(af[0], af[1], af[2], af[3], sb + OFF_BUF1 + a_off + ks*32);
            uint32_t bf[4][2];
            #pragma unroll
            for (int np = 0; np < 2; np++) {
                uint32_t r0, r1, r2, r3;
                ldsm_x4(r0, r1, r2, r3, vbase + b_off + np*16*QROWB + ks*32);
                bf[np*2][0] = r0;   bf[np*2][1] = r1;
                bf[np*2+1][0] = r2; bf[np*2+1][1] = r3;
            }
            #pragma unroll
            for (int nf = 0; nf < 4; nf++)
                mma_bf16(cacc[nf], af, bf[nf]);
        }
        __syncthreads();
    }

    #pragma unroll
    for (int nf = 0; nf < 4; nf++) {
        int cl = wn*32 + nf*8 + qc;
        S[rl0*SROW + cl]     = cacc[nf][0];
        S[rl0*SROW + cl + 1] = cacc[nf][1];
        S[(rl0+8)*SROW + cl]     = cacc[nf][2];
        S[(rl0+8)*SROW + cl + 1] = cacc[nf][3];
    }
    __syncthreads();

    // write ctx as fp16-2 split A-pattern into g_cp
    #pragma unroll
    for (int i = 0; i < 4; i++) {
        int e = tid + 256*i;
        int q = e >> 4, dv = e & 15;
        const float* sp = &S[q*SROW + dv*4];
        unsigned short hh[4], ll[4];
        #pragma unroll
        for (int u = 0; u < 4; u++) split_f16(sp[u], hh[u], ll[u]);
        size_t m = (size_t)b*NT + q0 + q;
        ushort4* o = (ushort4*)(g_cp + m*KP2 + (size_t)(h*NDK + dv*4)*2);
        o[0] = make_ushort4(hh[0], ll[0], hh[1], ll[1]);
        o[1] = make_ushort4(hh[2], ll[2], hh[3], ll[3]);
    }
}

// ---------------------------------------------------------------------------
extern "C" void kernel_launch(void* const* d_in, const int* in_sizes, int n_in,
                              void* d_out, int out_size)
{
    const float* x     = (const float*)d_in[0];
    const float* Wqkv  = (const float*)d_in[1];
    const float* bqkv  = (const float*)d_in[2];
    const float* Wo    = (const float*)d_in[3];
    const float* bo    = (const float*)d_in[4];
    const float* rel   = (const float*)d_in[5];

    float* out = (float*)d_out;
    float* attn;
    if ((size_t)out_size >= OUT_ELEMS + ATTN_ELEMS) {
        attn = out + OUT_ELEMS;
    } else {
        cudaGetSymbolAddress((void**)&attn, g_attn_fallback);
    }

    __half *ap, *bq, *bo2, *cp;
    cudaGetSymbolAddress((void**)&ap,  g_ap);
    cudaGetSymbolAddress((void**)&bq,  g_bq);
    cudaGetSymbolAddress((void**)&bo2, g_bo2);
    cudaGetSymbolAddress((void**)&cp,  g_cp);

    cudaFuncSetAttribute(mma_gemm_kernel,
                         cudaFuncAttributeMaxDynamicSharedMemorySize, GEMM_SMEM);
    cudaFuncSetAttribute(attn_tc_kernel,
                         cudaFuncAttributeMaxDynamicSharedMemorySize, ATTN_SMEM);

    // prep inputs
    interleave_a_kernel<<<8192, 256>>>(x, ap);
    transpose_w_kernel<<<dim3(96, 32), 256>>>(Wqkv, 3072, bq);
    transpose_w_kernel<<<dim3(32, 32), 256>>>(Wo, 1024, bo2);

    // QKV projection (epilogue emits Q'/K'/V' bf16-3 directly)
    mma_gemm_kernel<<<dim3(24, 64), 256, GEMM_SMEM>>>(ap, bq, bqkv, nullptr, 0);

    // tensor-core attention (writes attn + fp16-2 ctx)
    attn_tc_kernel<<<dim3(8, 256), 256, ATTN_SMEM>>>(rel, attn);

    // out projection
    mma_gemm_kernel<<<dim3(8, 64), 256, GEMM_SMEM>>>(cp, bo2, bo, out, 1);
}

// round 17
// speedup vs baseline: 3.6491x; 1.1510x over previous
#include <cuda_runtime.h>
#include <cuda_bf16.h>
#include <cuda_fp16.h>
#include <math.h>
#include <stdint.h>

#define NB 16
#define NT 512
#define ND 1024
#define NH 16
#define NDK 64
#define KP2 2048   // expanded K for GEMMs (2x fp16 split terms)

#define OUT_ELEMS  ((size_t)NB*NT*ND)             // 8,388,608
#define ATTN_ELEMS ((size_t)NB*NH*NT*NT)          // 67,108,864

// ---------------------------------------------------------------------------
// Scratch (device globals: allocation-free per harness rules)
// ---------------------------------------------------------------------------
__device__ float g_attn_fallback[NB*NH*NT*NT];

__device__ __align__(16) __half g_ap[8192ull*KP2];    // x  split/interleaved (fp16 A-pat)
__device__ __align__(16) __half g_bq[3072ull*KP2];    // Wqkv^T replicated (fp16 B-pat)
__device__ __align__(16) __half g_bo2[1024ull*KP2];   // Wo^T replicated
__device__ __align__(16) __half g_cp[8192ull*KP2];    // ctx split/interleaved
__device__ __align__(16) __nv_bfloat16 g_qp[(size_t)NB*NH*NT*192];  // Q' A-side (bf16-3)
__device__ __align__(16) __nv_bfloat16 g_kp[(size_t)NB*NH*NT*192];  // K' B-side
__device__ __align__(16) __half g_vp[(size_t)NB*NH*NDK*1024];       // V'^T fp16-2 B-side

// ---------------------------------------------------------------------------
// helpers
// ---------------------------------------------------------------------------
__device__ __forceinline__ uint32_t smem_u32(const void* p) {
    uint32_t a;
    asm("{ .reg .u64 t; cvta.to.shared.u64 t, %1; cvt.u32.u64 %0, t; }"
        : "=r"(a) : "l"(p));
    return a;
}
__device__ __forceinline__ void ldsm_x4(uint32_t& r0, uint32_t& r1,
                                        uint32_t& r2, uint32_t& r3, uint32_t addr) {
    asm volatile("ldmatrix.sync.aligned.m8n8.x4.shared.b16 {%0,%1,%2,%3}, [%4];"
                 : "=r"(r0), "=r"(r1), "=r"(r2), "=r"(r3) : "r"(addr));
}
__device__ __forceinline__ void mma_bf16(float* d, const uint32_t* a, const uint32_t* b) {
    asm volatile("mma.sync.aligned.m16n8k16.row.col.f32.bf16.bf16.f32 "
                 "{%0,%1,%2,%3}, {%4,%5,%6,%7}, {%8,%9}, {%0,%1,%2,%3};"
                 : "+f"(d[0]), "+f"(d[1]), "+f"(d[2]), "+f"(d[3])
                 : "r"(a[0]), "r"(a[1]), "r"(a[2]), "r"(a[3]),
                   "r"(b[0]), "r"(b[1]));
}
__device__ __forceinline__ void mma_f16(float* d, const uint32_t* a, const uint32_t* b) {
    asm volatile("mma.sync.aligned.m16n8k16.row.col.f32.f16.f16.f32 "
                 "{%0,%1,%2,%3}, {%4,%5,%6,%7}, {%8,%9}, {%0,%1,%2,%3};"
                 : "+f"(d[0]), "+f"(d[1]), "+f"(d[2]), "+f"(d[3])
                 : "r"(a[0]), "r"(a[1]), "r"(a[2]), "r"(a[3]),
                   "r"(b[0]), "r"(b[1]));
}
#define CP_ASYNC16(dst, src) \
    asm volatile("cp.async.cg.shared.global [%0], [%1], 16;" :: "r"(dst), "l"(src))
#define CP_COMMIT()  asm volatile("cp.async.commit_group;" ::: "memory")
#define CP_WAIT0()   asm volatile("cp.async.wait_group 0;" ::: "memory")
#define CP_WAIT1()   asm volatile("cp.async.wait_group 1;" ::: "memory")
// streaming store: 268MB attn must not wash L2
#define STG_CS4(ptr, v) \
    asm volatile("st.global.cs.v4.f32 [%0], {%1,%2,%3,%4};" \
                 :: "l"(ptr), "f"((v).x), "f"((v).y), "f"((v).z), "f"((v).w) : "memory")

__device__ __forceinline__ void split_bf16(float x, unsigned short& h, unsigned short& l) {
    __nv_bfloat16 hb = __float2bfloat16_rn(x);
    float hr = __bfloat162float(hb);
    __nv_bfloat16 lb = __float2bfloat16_rn(x - hr);
    h = *(unsigned short*)&hb;
    l = *(unsigned short*)&lb;
}
__device__ __forceinline__ void split_f16(float x, unsigned short& h, unsigned short& l) {
    __half hb = __float2half_rn(x);
    float hr = __half2float(hb);
    __half lb = __float2half_rn(x - hr);
    h = *(unsigned short*)&hb;
    l = *(unsigned short*)&lb;
}
__device__ __forceinline__ unsigned short f16_hi(float x) {
    __half hb = __float2half_rn(x);
    return *(unsigned short*)&hb;
}
__device__ __forceinline__ void write_a_pat(ushort4* d4, const unsigned short* h,
                                            const unsigned short* l) {
    d4[0] = make_ushort4(h[0], h[0], l[0], h[1]);
    d4[1] = make_ushort4(h[1], l[1], h[2], h[2]);
    d4[2] = make_ushort4(l[2], h[3], h[3], l[3]);
}
__device__ __forceinline__ void write_b_pat(ushort4* d4, const unsigned short* h,
                                            const unsigned short* l) {
    d4[0] = make_ushort4(h[0], l[0], h[0], h[1]);
    d4[1] = make_ushort4(l[1], h[1], h[2], l[2]);
    d4[2] = make_ushort4(h[2], h[3], l[3], h[3]);
}

// ---------------------------------------------------------------------------
// Prep: A-side fp16 split interleave  A'[m][2k+{0,1}] = {hi, lo}
// ---------------------------------------------------------------------------
__global__ __launch_bounds__(256) void interleave_a_kernel(
    const float* __restrict__ src, __half* __restrict__ dst)
{
    int gid = blockIdx.x * 256 + threadIdx.x;
    int m  = gid >> 8;
    int k4 = (gid & 255) * 4;
    float4 v = *(const float4*)(src + (size_t)m*1024 + k4);
    unsigned short h[4], l[4];
    split_f16(v.x, h[0], l[0]);
    split_f16(v.y, h[1], l[1]);
    split_f16(v.z, h[2], l[2]);
    split_f16(v.w, h[3], l[3]);
    ushort4* d4 = (ushort4*)(dst + (size_t)m*KP2 + (size_t)k4*2);
    d4[0] = make_ushort4(h[0], l[0], h[1], l[1]);
    d4[1] = make_ushort4(h[2], l[2], h[3], l[3]);
}

// ---------------------------------------------------------------------------
// Prep: B-side transpose + fp16 replicate.  W[k][n] -> B'[n][2k+{0,1}] = {hi,hi}
// ---------------------------------------------------------------------------
__global__ __launch_bounds__(256) void transpose_w_kernel(
    const float* __restrict__ W, int Ncols, __half* __restrict__ dst)
{
    __shared__ float s[32][33];
    const int tid = threadIdx.x;
    const int tx = tid & 31, ty = tid >> 5;
    const int n0 = blockIdx.x * 32, k0 = blockIdx.y * 32;
    #pragma unroll
    for (int i = 0; i < 4; i++)
        s[tx][ty + 8*i] = W[(size_t)(k0 + ty + 8*i)*Ncols + n0 + tx];
    __syncthreads();
    const int nn = tid >> 3;
    const int kq = (tid & 7) * 4;
    unsigned short h[4];
    #pragma unroll
    for (int t = 0; t < 4; t++)
        h[t] = f16_hi(s[nn][kq + t]);
    ushort4* d4 = (ushort4*)(dst + (size_t)(n0 + nn)*KP2 + (size_t)(k0 + kq)*2);
    d4[0] = make_ushort4(h[0], h[0], h[1], h[1]);
    d4[1] = make_ushort4(h[2], h[2], h[3], h[3]);
}

// ---------------------------------------------------------------------------
// fp16 mma.sync GEMM, 2-stage cp.async pipeline. KP2=2048, 32 K-tiles.
// mode 0: epilogue emits Q'/K' (bf16-3) and V' (fp16-2); mode 1: C + bias.
// ---------------------------------------------------------------------------
#define STAGE_BYTES 36864
#define GEMM_SMEM   73728
#define NKT 32

__global__ __launch_bounds__(256) void mma_gemm_kernel(
    const __half* __restrict__ Ap, const __half* __restrict__ Bp,
    const float* __restrict__ bias, float* __restrict__ C, int mode)
{
    extern __shared__ __align__(16) char smem[];
    const int tid = threadIdx.x;
    const int lane = tid & 31, wid = tid >> 5;
    const int wm = wid >> 2, wn = wid & 3;
    const int m0 = blockIdx.y * 128, n0 = blockIdx.x * 128;
    const uint32_t sb = smem_u32(smem);
    float acc[4][4][4];
    #pragma unroll
    for (int i = 0; i < 4; i++)
        #pragma unroll
        for (int j = 0; j < 4; j++)
            #pragma unroll
            for (int r = 0; r < 4; r++) acc[i][j][r] = 0.f;

    int cr[4], cc[4];
    #pragma unroll
    for (int i = 0; i < 4; i++) {
        int e = tid + 256*i;
        cr[i] = e >> 3;
        cc[i] = (e & 7) * 8;
    }
    const uint32_t a_off = (uint32_t)((wm*64 + (lane & 15))*144 + ((lane >> 4) << 4));
    const int g = lane >> 3, rl = lane & 7;
    const uint32_t b_off = (uint32_t)(18432 + (wn*32 + (g >> 1)*8 + rl)*144 + ((g & 1) << 4));

    {
        #pragma unroll
        for (int i = 0; i < 4; i++) {
            uint32_t da = sb + (uint32_t)(cr[i]*144 + cc[i]*2);
            CP_ASYNC16(da, Ap + (size_t)(m0 + cr[i])*KP2 + cc[i]);
            CP_ASYNC16(da + 18432, Bp + (size_t)(n0 + cr[i])*KP2 + cc[i]);
        }
        CP_COMMIT();
    }

    for (int kt = 0; kt < NKT; kt++) {
        const int s = kt & 1;
        if (kt + 1 < NKT) {
            const int kb = (kt + 1) * 64;
            const uint32_t st = (uint32_t)((s ^ 1) * STAGE_BYTES);
            #pragma unroll
            for (int i = 0; i < 4; i++) {
                uint32_t da = sb + st + (uint32_t)(cr[i]*144 + cc[i]*2);
                CP_ASYNC16(da, Ap + (size_t)(m0 + cr[i])*KP2 + kb + cc[i]);
                CP_ASYNC16(da + 18432, Bp + (size_t)(n0 + cr[i])*KP2 + kb + cc[i]);
            }
            CP_COMMIT();
            CP_WAIT1();
        } else {
            CP_WAIT0();
        }
        __syncthreads();

        const uint32_t sbase = sb + (uint32_t)(s * STAGE_BYTES);
        const uint32_t a_addr = sbase + a_off;
        const uint32_t b_addr = sbase + b_off;
        #pragma unroll
        for (int ks = 0; ks < 4; ks++) {
            uint32_t af[4][4];
            #pragma unroll
            for (int mf = 0; mf < 4; mf++)
                ldsm_x4(af[mf][0], af[mf][1], af[mf][2], af[mf][3],
                        a_addr + mf*16*144 + ks*32);
            uint32_t bf[4][2];
            #pragma unroll
            for (int np = 0; np < 2; np++) {
                uint32_t r0, r1, r2, r3;
                ldsm_x4(r0, r1, r2, r3, b_addr + np*16*144 + ks*32);
                bf[np*2][0] = r0;   bf[np*2][1] = r1;
                bf[np*2+1][0] = r2; bf[np*2+1][1] = r3;
            }
            #pragma unroll
            for (int mf = 0; mf < 4; mf++)
                #pragma unroll
                for (int nf = 0; nf < 4; nf++)
                    mma_f16(acc[mf][nf], af[mf], bf[nf]);
        }
        __syncthreads();
    }

    const int qr = lane >> 2, qc = (lane & 3) * 2;

    if (mode == 1) {
        #pragma unroll
        for (int mf = 0; mf < 4; mf++) {
            #pragma unroll
            for (int nf = 0; nf < 4; nf++) {
                int row = m0 + wm*64 + mf*16 + qr;
                int col = n0 + wn*32 + nf*8 + qc;
                float2 bi = *(const float2*)(bias + col);
                *(float2*)(C + (size_t)row*1024 + col) =
                    make_float2(acc[mf][nf][0] + bi.x, acc[mf][nf][1] + bi.y);
                *(float2*)(C + (size_t)(row + 8)*1024 + col) =
                    make_float2(acc[mf][nf][2] + bi.x, acc[mf][nf][3] + bi.y);
            }
        }
        return;
    }

    // ---- mode 0: stage tile (+bias), emit Q'/K' (bf16-3) and V' (fp16-2) ----
    float* stage = (float*)smem;             // 128 x 132 fp32 = 67584 B
    #pragma unroll
    for (int mf = 0; mf < 4; mf++) {
        #pragma unroll
        for (int nf = 0; nf < 4; nf++) {
            int r = wm*64 + mf*16 + qr;
            int c = wn*32 + nf*8 + qc;
            float2 bi = *(const float2*)(bias + n0 + c);
            stage[(size_t)r*132 + c]     = acc[mf][nf][0] + bi.x;
            stage[(size_t)r*132 + c + 1] = acc[mf][nf][1] + bi.y;
            stage[(size_t)(r+8)*132 + c]     = acc[mf][nf][2] + bi.x;
            stage[(size_t)(r+8)*132 + c + 1] = acc[mf][nf][3] + bi.y;
        }
    }
    __syncthreads();

    #pragma unroll
    for (int ch = 0; ch < 2; ch++) {
        const int gcol0 = n0 + ch*64;
        const int chunk = gcol0 >> 6;        // 0..47
        const int part  = chunk >> 4;        // 0=q, 1=k, 2=v
        const int hd    = chunk & 15;
        if (part < 2) {
            __nv_bfloat16* dst = (part == 0) ? g_qp : g_kp;
            #pragma unroll
            for (int it = 0; it < 8; it++) {
                int task = tid + 256*it;     // 0..2047
                int r = task >> 4, dq = task & 15;
                const float* sp = &stage[(size_t)r*132 + ch*64 + dq*4];
                unsigned short hh[4], ll[4];
                #pragma unroll
                for (int u = 0; u < 4; u++) split_bf16(sp[u], hh[u], ll[u]);
                int m = m0 + r;
                int bb = m >> 9, t = m & 511;
                ushort4* o = (ushort4*)(dst + ((size_t)((bb*NH + hd)*NT + t))*192
                                        + (size_t)dq*12);
                if (part == 0) write_a_pat(o, hh, ll);
                else           write_b_pat(o, hh, ll);
            }
        } else {
            #pragma unroll
            for (int it = 0; it < 8; it++) {
                int task = tid + 256*it;     // 0..2047
                int d = task >> 5, jq = task & 31;
                unsigned short hh[4];
                #pragma unroll
                for (int u = 0; u < 4; u++)
                    hh[u] = f16_hi(stage[(size_t)(jq*4 + u)*132 + ch*64 + d]);
                int m = m0 + jq*4;
                int bb = m >> 9, t = m & 511;
                int bh = bb*NH + hd;
                ushort4* o = (ushort4*)(g_vp + ((size_t)(bh*NDK + d))*1024
                                        + (size_t)t*2);
                o[0] = make_ushort4(hh[0], hh[0], hh[1], hh[1]);
                o[1] = make_ushort4(hh[2], hh[2], hh[3], hh[3]);
            }
        }
    }
}

// ---------------------------------------------------------------------------
// Tensor-core attention, WINDOWED, 512 threads (16 warps, 4Mx4N).
// Scores: bf16-3 (accuracy for attn output). PV: fp16-2 (P exact, V rounded).
// ---------------------------------------------------------------------------
#define SROW 324
#define QROWB 400                   // Q'/K' row stride (bytes), 192 bf16 + pad
#define VROWB 272                   // P/V' row stride (bytes), 128 fp16 + pad
#define OFF_BIAS 82944
#define OFF_BUF1 87040              // Q' (scores) / P (PV)
#define OFF_BUF2 112640             // K' 2x25600 (scores) / V' 2x17408 (PV)
#define KV_STAGE 25600
#define PV_STAGE 17408
#define ATTN_SMEM 163840

__global__ __launch_bounds__(512) void attn_tc_kernel(
    const float* __restrict__ rel_table, float* __restrict__ attn)
{
    extern __shared__ __align__(16) char smem[];
    float* S = (float*)smem;
    float* sbias = (float*)(smem + OFF_BIAS);
    const uint32_t sb = smem_u32(smem);
    const int tid = threadIdx.x;
    const int lane = tid & 31, wid = tid >> 5;   // 16 warps
    const int wm = wid >> 2, wn = wid & 3;       // 4(M) x 4(N), warp tile 16x16
    const int bh = blockIdx.y;
    const int b = bh >> 4, h = bh & 15;
    const int q0 = blockIdx.x * 64;
    const int js = max(0, q0 - 128);
    const int je = min(NT, q0 + 64 + 128);
    const int jb_lo = js >> 6;
    const int nblk = (je - js) >> 6;

    for (int i = tid; i < 1023; i += 512)
        sbias[i] = rel_table[(size_t)i*NH + h];

    {
        const __nv_bfloat16* qsrc = g_qp + (size_t)(bh*NT + q0)*192;
        for (int i = tid; i < 1536; i += 512) {
            int r = i / 24, c = i % 24;
            *(uint4*)(smem + OFF_BUF1 + r*QROWB + c*16) =
                *(const uint4*)((const char*)(qsrc + (size_t)r*192) + c*16);
        }
    }

    const int g = lane >> 3, rl = lane & 7;
    const uint32_t a_off  = (uint32_t)((wm*16 + (lane & 15))*QROWB + ((lane >> 4) << 4));
    const uint32_t b_off  = (uint32_t)((wn*16 + (g >> 1)*8 + rl)*QROWB + ((g & 1) << 4));
    const uint32_t pva_off = (uint32_t)((wm*16 + (lane & 15))*VROWB + ((lane >> 4) << 4));
    const uint32_t pvb_off = (uint32_t)((wn*16 + (g >> 1)*8 + rl)*VROWB + ((g & 1) << 4));
    const int qr = lane >> 2, qc = (lane & 3) * 2;
    const int rl0 = wm*16 + qr;

    // ---- scores: prologue prefetch of first K block ----
    {
        const __nv_bfloat16* ksrc = g_kp + (size_t)(bh*NT + jb_lo*64)*192;
        for (int i = tid; i < 1536; i += 512) {
            int r = i / 24, c = i % 24;
            CP_ASYNC16(sb + OFF_BUF2 + (uint32_t)(r*QROWB + c*16),
                       (const char*)(ksrc + (size_t)r*192) + c*16);
        }
        CP_COMMIT();
    }

    for (int ib = 0; ib < nblk; ib++) {
        CP_WAIT0();
        __syncthreads();
        if (ib + 1 < nblk) {
            const __nv_bfloat16* ksrc = g_kp + (size_t)(bh*NT + (jb_lo + ib + 1)*64)*192;
            const uint32_t st = (uint32_t)(((ib + 1) & 1) * KV_STAGE);
            for (int i = tid; i < 1536; i += 512) {
                int r = i / 24, c = i % 24;
                CP_ASYNC16(sb + OFF_BUF2 + st + (uint32_t)(r*QROWB + c*16),
                           (const char*)(ksrc + (size_t)r*192) + c*16);
            }
            CP_COMMIT();
        }

        float acc[2][4];
        #pragma unroll
        for (int nf = 0; nf < 2; nf++)
            #pragma unroll
            for (int r = 0; r < 4; r++) acc[nf][r] = 0.f;

        const uint32_t kbase = sb + OFF_BUF2 + (uint32_t)((ib & 1) * KV_STAGE);
        #pragma unroll
        for (int ks = 0; ks < 12; ks++) {
            uint32_t af[4];
            ldsm_x4(af[0], af[1], af[2], af[3], sb + OFF_BUF1 + a_off + ks*32);
            uint32_t bf[2][2];
            {
                uint32_t r0, r1, r2, r3;
                ldsm_x4(r0, r1, r2, r3, kbase + b_off + ks*32);
                bf[0][0] = r0; bf[0][1] = r1;
                bf[1][0] = r2; bf[1][1] = r3;
            }
            mma_bf16(acc[0], af, bf[0]);
            mma_bf16(acc[1], af, bf[1]);
        }

        #pragma unroll
        for (int nf = 0; nf < 2; nf++) {
            int cl = ib*64 + wn*16 + nf*8 + qc;
            int j  = js + cl;
            int qiA = q0 + rl0, qiB = qiA + 8;
            S[rl0*SROW + cl]     = acc[nf][0]*0.125f + sbias[j - qiA + 511];
            S[rl0*SROW + cl + 1] = acc[nf][1]*0.125f + sbias[j + 1 - qiA + 511];
            S[(rl0+8)*SROW + cl]     = acc[nf][2]*0.125f + sbias[j - qiB + 511];
            S[(rl0+8)*SROW + cl + 1] = acc[nf][3]*0.125f + sbias[j + 1 - qiB + 511];
        }
    }
    __syncthreads();

    // ---- softmax + attn write: each warp owns 4 rows ----
    const int span = je - js;
    #pragma unroll
    for (int rr = 0; rr < 4; rr++) {
        int r = wid*4 + rr;
        int qi = q0 + r;
        int jlo = max(0, qi - 128), jhi = min(NT - 1, qi + 128);
        float mx = -1e30f;
        for (int j = jlo + lane; j <= jhi; j += 32)
            mx = fmaxf(mx, S[r*SROW + j - js]);
        #pragma unroll
        for (int o = 16; o > 0; o >>= 1)
            mx = fmaxf(mx, __shfl_xor_sync(0xffffffffu, mx, o));
        float sum = 0.f;
        for (int j = jlo + lane; j <= jhi; j += 32) {
            float e = __expf(S[r*SROW + j - js] - mx);
            S[r*SROW + j - js] = e;
            sum += e;
        }
        #pragma unroll
        for (int o = 16; o > 0; o >>= 1)
            sum += __shfl_xor_sync(0xffffffffu, sum, o);
        float inv = 1.f / sum;
        for (int idx = lane; idx < span; idx += 32) {
            int j = js + idx;
            float v = (j >= jlo && j <= jhi) ? S[r*SROW + idx]*inv : 0.f;
            S[r*SROW + idx] = v;
        }
        __syncwarp();
        float* arow = attn + ((size_t)bh*NT + qi)*NT;
        for (int j4 = lane; j4 < 128; j4 += 32) {
            int j = j4*4;
            float4 o;
            o.x = (j   >= js && j   < je) ? S[r*SROW + j   - js] : 0.f;
            o.y = (j+1 >= js && j+1 < je) ? S[r*SROW + j+1 - js] : 0.f;
            o.z = (j+2 >= js && j+2 < je) ? S[r*SROW + j+2 - js] : 0.f;
            o.w = (j+3 >= js && j+3 < je) ? S[r*SROW + j+3 - js] : 0.f;
            STG_CS4(arow + j, o);
        }
    }
    __syncthreads();

    // ---- PV (fp16-2): P=[Ph,Pl], V'=[Vh,Vh], 8 ks per block ----
    float cacc[2][4];
    #pragma unroll
    for (int nf = 0; nf < 2; nf++)
        #pragma unroll
        for (int r = 0; r < 4; r++) cacc[nf][r] = 0.f;

    {
        const __half* vsrc = g_vp + (size_t)(bh*NDK)*1024 + (size_t)jb_lo*128;
        for (int i = tid; i < 1024; i += 512) {
            int r = i >> 4, c = i & 15;
            CP_ASYNC16(sb + OFF_BUF2 + (uint32_t)(r*VROWB + c*16),
                       (const char*)(vsrc + (size_t)r*1024) + c*16);
        }
        CP_COMMIT();
    }

    for (int ib = 0; ib < nblk; ib++) {
        CP_WAIT0();
        if (ib + 1 < nblk) {
            const __half* vsrc = g_vp + (size_t)(bh*NDK)*1024
                                 + (size_t)(jb_lo + ib + 1)*128;
            const uint32_t st = (uint32_t)(((ib + 1) & 1) * PV_STAGE);
            for (int i = tid; i < 1024; i += 512) {
                int r = i >> 4, c = i & 15;
                CP_ASYNC16(sb + OFF_BUF2 + st + (uint32_t)(r*VROWB + c*16),
                           (const char*)(vsrc + (size_t)r*1024) + c*16);
            }
            CP_COMMIT();
        }
        // convert P chunk ib -> fp16-2 interleave in buf1
        #pragma unroll
        for (int i = 0; i < 2; i++) {
            int e = tid + 512*i;      // 0..1023
            int q = e >> 4, j4 = e & 15;
            const float* sp = &S[q*SROW + ib*64 + j4*4];
            unsigned short hh[4], ll[4];
            #pragma unroll
            for (int u = 0; u < 4; u++) split_f16(sp[u], hh[u], ll[u]);
            ushort4* o = (ushort4*)(smem + OFF_BUF1 + q*VROWB + j4*16);
            o[0] = make_ushort4(hh[0], ll[0], hh[1], ll[1]);
            o[1] = make_ushort4(hh[2], ll[2], hh[3], ll[3]);
        }
        __syncthreads();

        const uint32_t vbase = sb + OFF_BUF2 + (uint32_t)((ib & 1) * PV_STAGE);
        #pragma unroll
        for (int ks = 0; ks < 8; ks++) {
            uint32_t af[4];
            ldsm_x4(af[0], af[1], af[2], af[3], sb + OFF_BUF1 + pva_off + ks*32);
            uint32_t bf[2][2];
            {
                uint32_t r0, r1, r2, r3;
                ldsm_x4(r0, r1, r2, r3, vbase + pvb_off + ks*32);
                bf[0][0] = r0; bf[0][1] = r1;
                bf[1][0] = r2; bf[1][1] = r3;
            }
            mma_f16(cacc[0], af, bf[0]);
            mma_f16(cacc[1], af, bf[1]);
        }
        __syncthreads();
    }

    // stage ctx (64 q x 64 d) into S cols 0..63
    #pragma unroll
    for (int nf = 0; nf < 2; nf++) {
        int cl = wn*16 + nf*8 + qc;
        S[rl0*SROW + cl]     = cacc[nf][0];
        S[rl0*SROW + cl + 1] = cacc[nf][1];
        S[(rl0+8)*SROW + cl]     = cacc[nf][2];
        S[(rl0+8)*SROW + cl + 1] = cacc[nf][3];
    }
    __syncthreads();

    // write ctx as fp16-2 split A-pattern into g_cp
    #pragma unroll
    for (int i = 0; i < 2; i++) {
        int e = tid + 512*i;
        int q = e >> 4, dv = e & 15;
        const float* sp = &S[q*SROW + dv*4];
        unsigned short hh[4], ll[4];
        #pragma unroll
        for (int u = 0; u < 4; u++) split_f16(sp[u], hh[u], ll[u]);
        size_t m = (size_t)b*NT + q0 + q;
        ushort4* o = (ushort4*)(g_cp + m*KP2 + (size_t)(h*NDK + dv*4)*2);
        o[0] = make_ushort4(hh[0], ll[0], hh[1], ll[1]);
        o[1] = make_ushort4(hh[2], ll[2], hh[3], ll[3]);
    }
}

// ---------------------------------------------------------------------------
extern "C" void kernel_launch(void* const* d_in, const int* in_sizes, int n_in,
                              void* d_out, int out_size)
{
    const float* x     = (const float*)d_in[0];
    const float* Wqkv  = (const float*)d_in[1];
    const float* bqkv  = (const float*)d_in[2];
    const float* Wo    = (const float*)d_in[3];
    const float* bo    = (const float*)d_in[4];
    const float* rel   = (const float*)d_in[5];

    float* out = (float*)d_out;
    float* attn;
    if ((size_t)out_size >= OUT_ELEMS + ATTN_ELEMS) {
        attn = out + OUT_ELEMS;
    } else {
        cudaGetSymbolAddress((void**)&attn, g_attn_fallback);
    }

    __half *ap, *bq, *bo2, *cp;
    cudaGetSymbolAddress((void**)&ap,  g_ap);
    cudaGetSymbolAddress((void**)&bq,  g_bq);
    cudaGetSymbolAddress((void**)&bo2, g_bo2);
    cudaGetSymbolAddress((void**)&cp,  g_cp);

    cudaFuncSetAttribute(mma_gemm_kernel,
                         cudaFuncAttributeMaxDynamicSharedMemorySize, GEMM_SMEM);
    cudaFuncSetAttribute(attn_tc_kernel,
                         cudaFuncAttributeMaxDynamicSharedMemorySize, ATTN_SMEM);

    // prep inputs
    interleave_a_kernel<<<8192, 256>>>(x, ap);
    transpose_w_kernel<<<dim3(96, 32), 256>>>(Wqkv, 3072, bq);
    transpose_w_kernel<<<dim3(32, 32), 256>>>(Wo, 1024, bo2);

    // QKV projection (epilogue emits Q'/K' bf16-3 and V' fp16-2 directly)
    mma_gemm_kernel<<<dim3(24, 64), 256, GEMM_SMEM>>>(ap, bq, bqkv, nullptr, 0);

    // tensor-core attention (writes attn + fp16-2 ctx)
    attn_tc_kernel<<<dim3(8, 256), 512, ATTN_SMEM>>>(rel, attn);

    // out projection
    mma_gemm_kernel<<<dim3(8, 64), 256, GEMM_SMEM>>>(cp, bo2, bo, out, 1);
}